// round 3
// baseline (speedup 1.0000x reference)
#include <cuda_runtime.h>
#include <math.h>
#include <stdint.h>

#define NA 16
#define OBSF 128
#define STATE 256
#define EMBED 32
#define NHID 32
#define BTOT 8192
#define ALPHA 0.2f
#define NEGV -9.0e15f

// ---------------- scratch (device globals; no allocation in kernel_launch) --------
__device__ float g_xcat1[(size_t)BTOT * NA * 128];   // 64 MB  (g1 head concat, post-elu)
__device__ float g_xcatf[(size_t)BTOT * NA * 128];   // 64 MB  (gf head concat, post-elu)
__device__ float g_whout1[(size_t)BTOT * NA * 512];  // 256 MB (g1 out-layer Wh)
__device__ float g_ball[(size_t)BTOT * 512];         // 16 MB  (b_all pre-bias)

// =====================================================================
// Kernel 1: per-batch head stage for BOTH GATs (8 heads of 32 fused).
// =====================================================================
__global__ __launch_bounds__(256) void heads_kernel(
    const float* __restrict__ obs_g, const float* __restrict__ adj_g,
    const float* __restrict__ g1_Wh, const float* __restrict__ g1_ah,
    const float* __restrict__ gf_Wh, const float* __restrict__ gf_ah)
{
    int b = blockIdx.x;
    int tid = threadIdx.x;

    __shared__ float obs[NA][OBSF];   // 8 KB
    __shared__ float wh8[NA][256];    // 16 KB  (8 heads x 32 cols)
    __shared__ float adj[NA][NA];
    __shared__ float att[NA][NA];
    __shared__ float f1[NA], f2[NA];

    const float* ob = obs_g + (size_t)b * NA * OBSF;
    for (int idx = tid; idx < NA * OBSF; idx += 256)
        obs[idx >> 7][idx & 127] = ob[idx];
    if (tid < 256) adj[tid >> 4][tid & 15] = adj_g[(size_t)b * 256 + tid];
    __syncthreads();

    // Wh for all 8 heads: each thread owns one output column (c = tid)
    {
        int c = tid;                 // 0..255
        int h = c >> 5, col = c & 31;
        const float* W = (h < 4) ? (g1_Wh + (size_t)h * OBSF * NHID)
                                 : (gf_Wh + (size_t)(h - 4) * OBSF * NHID);
        float acc[NA];
        #pragma unroll
        for (int i = 0; i < NA; i++) acc[i] = 0.f;
        #pragma unroll 4
        for (int k = 0; k < OBSF; k++) {
            float w = W[k * NHID + col];
            #pragma unroll
            for (int i = 0; i < NA; i++) acc[i] = fmaf(obs[i][k], w, acc[i]);
        }
        #pragma unroll
        for (int i = 0; i < NA; i++) wh8[i][c] = acc[i];
    }
    __syncthreads();

    for (int h = 0; h < 8; h++) {
        const float* a = (h < 4) ? (g1_ah + (size_t)h * 2 * NHID)
                                 : (gf_ah + (size_t)(h - 4) * 2 * NHID);
        // f1[i] = Wh_i . a[:32],  f2[j] = Wh_j . a[32:]
        if (tid < 32) {
            int d = tid & 15;
            const float* av = a + ((tid >= 16) ? NHID : 0);
            float acc = 0.f;
            #pragma unroll
            for (int c = 0; c < NHID; c++) acc = fmaf(wh8[d][h * NHID + c], av[c], acc);
            if (tid >= 16) f2[d] = acc; else f1[d] = acc;
        }
        __syncthreads();
        // column-wise softmax (axis=1 of [B,N,N]) with adj mask + leaky relu
        if (tid < NA) {
            int j = tid;
            float ev[NA];
            float m = -INFINITY;
            #pragma unroll
            for (int i = 0; i < NA; i++) {
                float e = f1[i] + f2[j];
                e = e > 0.f ? e : ALPHA * e;
                e = (adj[i][j] > 0.f) ? e : NEGV;
                ev[i] = e;
                m = fmaxf(m, e);
            }
            float s = 0.f;
            #pragma unroll
            for (int i = 0; i < NA; i++) { float t = expf(ev[i] - m); ev[i] = t; s += t; }
            float inv = 1.f / s;
            #pragma unroll
            for (int i = 0; i < NA; i++) att[i][j] = ev[i] * inv;
        }
        __syncthreads();
        // out = att @ Wh, then elu, store to xcat scratch
        #pragma unroll
        for (int l = 0; l < 2; l++) {
            int idx = tid + l * 256;     // 0..511
            int i = idx >> 5, c = idx & 31;
            float acc = 0.f;
            #pragma unroll
            for (int n = 0; n < NA; n++) acc = fmaf(att[i][n], wh8[n][h * NHID + c], acc);
            acc = acc > 0.f ? acc : expm1f(acc);
            float* dst = (h < 4) ? g_xcat1 : g_xcatf;
            int hh = (h < 4) ? h : (h - 4);
            dst[(size_t)b * 2048 + i * 128 + hh * 32 + c] = acc;
        }
        __syncthreads();
    }
}

// =====================================================================
// Kernel 2: generic fp32 tiled GEMM. C[M,N] = A[M,K] @ B[K,N].
// B element (k,n) at Bp[k*bsk + n*bsn] (handles both weight layouts).
// BM=BN=64, BK=16, 256 threads, 4x4 per thread. All dims tile-divisible.
// =====================================================================
__global__ __launch_bounds__(256) void gemm_tiled(
    const float* __restrict__ A, const float* __restrict__ Bp, float* __restrict__ C,
    int K, int lda, int bsk, int bsn, int ldc)
{
    __shared__ float As[64][17];
    __shared__ float Bs[16][65];
    int bn = blockIdx.x * 64;
    int bm = blockIdx.y * 64;
    int tid = threadIdx.x;
    int tx = tid & 15, ty = tid >> 4;

    float acc[4][4];
    #pragma unroll
    for (int i = 0; i < 4; i++)
        #pragma unroll
        for (int j = 0; j < 4; j++) acc[i][j] = 0.f;

    for (int k0 = 0; k0 < K; k0 += 16) {
        #pragma unroll
        for (int l = 0; l < 4; l++) {
            int idx = tid + l * 256;
            int m = idx >> 4, k = idx & 15;
            As[m][k] = A[(size_t)(bm + m) * lda + k0 + k];
        }
        #pragma unroll
        for (int l = 0; l < 4; l++) {
            int idx = tid + l * 256;
            int k = idx >> 6, n = idx & 63;
            Bs[k][n] = Bp[(size_t)(k0 + k) * bsk + (size_t)(bn + n) * bsn];
        }
        __syncthreads();
        #pragma unroll
        for (int k = 0; k < 16; k++) {
            float ra[4], rb[4];
            #pragma unroll
            for (int i = 0; i < 4; i++) ra[i] = As[ty * 4 + i][k];
            #pragma unroll
            for (int j = 0; j < 4; j++) rb[j] = Bs[k][tx * 4 + j];
            #pragma unroll
            for (int i = 0; i < 4; i++)
                #pragma unroll
                for (int j = 0; j < 4; j++) acc[i][j] = fmaf(ra[i], rb[j], acc[i][j]);
        }
        __syncthreads();
    }
    #pragma unroll
    for (int i = 0; i < 4; i++) {
        float4 v = make_float4(acc[i][0], acc[i][1], acc[i][2], acc[i][3]);
        *reinterpret_cast<float4*>(&C[(size_t)(bm + ty * 4 + i) * ldc + bn + tx * 4]) = v;
    }
}

// =====================================================================
// Kernel 3: out-layer attention for both GATs + all final mixing.
// =====================================================================
__global__ __launch_bounds__(256) void final_kernel(
    const float* __restrict__ agent_qs, const float* __restrict__ states,
    const float* __restrict__ adj_g,
    const float* __restrict__ wn_w, const float* __restrict__ wn_b,
    const float* __restrict__ g1_aout,
    const float* __restrict__ gf_Wout, const float* __restrict__ gf_aout,
    const float* __restrict__ hb_b,
    const float* __restrict__ v1_w, const float* __restrict__ v1_b,
    const float* __restrict__ v2_w, const float* __restrict__ v2_b,
    float* __restrict__ out)
{
    int b = blockIdx.x;
    int tid = threadIdx.x;
    int lane = tid & 31, warp = tid >> 5;

    __shared__ float Wsm[NA][512];    // 32 KB: g1 Whout, later reused for |log_softmax| (= w1)
    __shared__ float adj[NA][NA];
    __shared__ float att[NA][NA];
    __shared__ float f1[NA], f2[NA];
    __shared__ float whf[NA][EMBED];
    __shared__ float whf2[NA][EMBED];
    __shared__ float st[STATE];
    __shared__ float qs[NA];
    __shared__ float ypart[NA][16];
    __shared__ float yv[NA], disv[NA], vpart[32];

    for (int idx = tid; idx < NA * 512; idx += 256)
        Wsm[idx >> 9][idx & 511] = g_whout1[(size_t)b * 8192 + idx];
    if (tid < 256) {
        adj[tid >> 4][tid & 15] = adj_g[(size_t)b * 256 + tid];
        st[tid] = states[(size_t)b * 256 + tid];
    }
    if (tid < NA) qs[tid] = agent_qs[(size_t)b * NA + tid];
    __syncthreads();

    // ---- g1 out-layer attention scores: 32 dots of 512 (warp-per-dot) ----
    #pragma unroll
    for (int r = 0; r < 4; r++) {
        int d = warp * 4 + r;        // 0..31
        int row = d & 15;
        const float* av = g1_aout + ((d < 16) ? 0 : 512);
        float acc = 0.f;
        #pragma unroll
        for (int k = lane; k < 512; k += 32) acc = fmaf(Wsm[row][k], av[k], acc);
        #pragma unroll
        for (int o = 16; o; o >>= 1) acc += __shfl_down_sync(0xffffffffu, acc, o);
        if (lane == 0) { if (d < 16) f1[row] = acc; else f2[row] = acc; }
    }
    __syncthreads();

    if (tid < NA) {  // column softmax
        int j = tid;
        float ev[NA]; float m = -INFINITY;
        #pragma unroll
        for (int i = 0; i < NA; i++) {
            float e = f1[i] + f2[j];
            e = e > 0.f ? e : ALPHA * e;
            e = (adj[i][j] > 0.f) ? e : NEGV;
            ev[i] = e; m = fmaxf(m, e);
        }
        float s = 0.f;
        #pragma unroll
        for (int i = 0; i < NA; i++) { float t = expf(ev[i] - m); ev[i] = t; s += t; }
        float inv = 1.f / s;
        #pragma unroll
        for (int i = 0; i < NA; i++) att[i][j] = ev[i] * inv;
    }
    __syncthreads();

    // ---- out2 = elu(att @ Wsm) staged in registers, then overwrite Wsm ----
    float o2[32];
    #pragma unroll
    for (int l = 0; l < 32; l++) {
        int idx = tid + l * 256;
        int i = idx >> 9, fcol = idx & 511;
        float acc = 0.f;
        #pragma unroll
        for (int n = 0; n < NA; n++) acc = fmaf(att[i][n], Wsm[n][fcol], acc);
        o2[l] = acc > 0.f ? acc : expm1f(acc);
    }
    __syncthreads();
    #pragma unroll
    for (int l = 0; l < 32; l++) {
        int idx = tid + l * 256;
        Wsm[idx >> 9][idx & 511] = o2[l];
    }
    __syncthreads();

    // ---- log_softmax over agents (axis=1) per column, then abs  -> w1 ----
    #pragma unroll
    for (int l = 0; l < 2; l++) {
        int fcol = tid + l * 256;
        float m = -INFINITY;
        #pragma unroll
        for (int i = 0; i < NA; i++) m = fmaxf(m, Wsm[i][fcol]);
        float s = 0.f;
        #pragma unroll
        for (int i = 0; i < NA; i++) s += expf(Wsm[i][fcol] - m);
        float lse = m + logf(s);
        #pragma unroll
        for (int i = 0; i < NA; i++) Wsm[i][fcol] = fabsf(Wsm[i][fcol] - lse);
    }
    __syncthreads();

    // ---- gf output layer: Whf = xcatf @ gf_Wout (16x128 @ 128x32) ----
    #pragma unroll
    for (int l = 0; l < 2; l++) {
        int idx = tid + l * 256;
        int i = idx >> 5, c = idx & 31;
        const float* xr = g_xcatf + (size_t)b * 2048 + i * 128;
        float acc = 0.f;
        #pragma unroll 4
        for (int k = 0; k < 128; k++) acc = fmaf(xr[k], gf_Wout[k * 32 + c], acc);
        whf[i][c] = acc;
    }
    __syncthreads();

    if (tid < 32) {
        int d = tid & 15;
        const float* av = gf_aout + ((tid < 16) ? 0 : 32);
        float acc = 0.f;
        #pragma unroll
        for (int c = 0; c < 32; c++) acc = fmaf(whf[d][c], av[c], acc);
        if (tid < 16) f1[d] = acc; else f2[d] = acc;
    }
    __syncthreads();

    if (tid < NA) {
        int j = tid;
        float ev[NA]; float m = -INFINITY;
        #pragma unroll
        for (int i = 0; i < NA; i++) {
            float e = f1[i] + f2[j];
            e = e > 0.f ? e : ALPHA * e;
            e = (adj[i][j] > 0.f) ? e : NEGV;
            ev[i] = e; m = fmaxf(m, e);
        }
        float s = 0.f;
        #pragma unroll
        for (int i = 0; i < NA; i++) { float t = expf(ev[i] - m); ev[i] = t; s += t; }
        float inv = 1.f / s;
        #pragma unroll
        for (int i = 0; i < NA; i++) att[i][j] = ev[i] * inv;
    }
    __syncthreads();

    #pragma unroll
    for (int l = 0; l < 2; l++) {
        int idx = tid + l * 256;
        int i = idx >> 5, c = idx & 31;
        float acc = 0.f;
        #pragma unroll
        for (int n = 0; n < NA; n++) acc = fmaf(att[i][n], whf[n][c], acc);
        whf2[i][c] = acc > 0.f ? acc : expm1f(acc);
    }
    __syncthreads();

    if (tid < 32) {  // log_softmax over agents per column, then abs -> hyper_wf
        int c = tid;
        float m = -INFINITY;
        #pragma unroll
        for (int i = 0; i < NA; i++) m = fmaxf(m, whf2[i][c]);
        float s = 0.f;
        #pragma unroll
        for (int i = 0; i < NA; i++) s += expf(whf2[i][c] - m);
        float lse = m + logf(s);
        #pragma unroll
        for (int i = 0; i < NA; i++) whf2[i][c] = fabsf(whf2[i][c] - lse);
    }
    __syncthreads();

    // ---- hidden[i,e] = elu(sum_n qs[n]*w1[i,n,e] + b_all[i,e]); y[i] = hidden.wf ----
    {
        int i = tid >> 4, g = tid & 15;
        float part = 0.f;
        #pragma unroll
        for (int u = 0; u < 2; u++) {
            int e = g * 2 + u;
            float hacc = g_ball[(size_t)b * 512 + i * 32 + e] + hb_b[i * 32 + e];
            #pragma unroll
            for (int n = 0; n < NA; n++) hacc = fmaf(qs[n], Wsm[i][n * 32 + e], hacc);
            hacc = hacc > 0.f ? hacc : expm1f(hacc);
            part = fmaf(hacc, whf2[i][e], part);
        }
        ypart[i][g] = part;
    }
    __syncthreads();
    if (tid < NA) {
        float s = 0.f;
        #pragma unroll
        for (int g = 0; g < 16; g++) s += ypart[tid][g];
        yv[tid] = s;
    }

    // ---- dis (16 dots of 256) and V-net (32 dots of 256), warp-per-dot ----
    #pragma unroll
    for (int r = 0; r < 2; r++) {
        int n = warp * 2 + r;
        float acc = 0.f;
        #pragma unroll
        for (int s_ = lane; s_ < 256; s_ += 32) acc = fmaf(st[s_], wn_w[n * 256 + s_], acc);
        #pragma unroll
        for (int o = 16; o; o >>= 1) acc += __shfl_down_sync(0xffffffffu, acc, o);
        if (lane == 0) disv[n] = fabsf(acc + wn_b[n]);
    }
    #pragma unroll
    for (int r = 0; r < 4; r++) {
        int n = warp * 4 + r;
        float acc = 0.f;
        #pragma unroll
        for (int s_ = lane; s_ < 256; s_ += 32) acc = fmaf(st[s_], v1_w[n * 256 + s_], acc);
        #pragma unroll
        for (int o = 16; o; o >>= 1) acc += __shfl_down_sync(0xffffffffu, acc, o);
        if (lane == 0) vpart[n] = fmaxf(acc + v1_b[n], 0.f);
    }
    __syncthreads();

    if (tid == 0) {
        float v = v2_b[0];
        #pragma unroll
        for (int h = 0; h < 32; h++) v = fmaf(vpart[h], v2_w[h], v);
        float q = v;
        #pragma unroll
        for (int n = 0; n < NA; n++) q = fmaf(yv[n], disv[n], q);
        out[b] = q;
    }
}

// =====================================================================
extern "C" void kernel_launch(void* const* d_in, const int* in_sizes, int n_in,
                              void* d_out, int out_size)
{
    const float* agent_qs = (const float*)d_in[0];
    const float* states   = (const float*)d_in[1];
    const float* obs_ls   = (const float*)d_in[2];
    const float* adj_ls   = (const float*)d_in[3];
    const float* wn_w     = (const float*)d_in[4];
    const float* wn_b     = (const float*)d_in[5];
    const float* g1_Wh    = (const float*)d_in[6];
    const float* g1_ah    = (const float*)d_in[7];
    const float* g1_Wout  = (const float*)d_in[8];
    const float* g1_aout  = (const float*)d_in[9];
    const float* gf_Wh    = (const float*)d_in[10];
    const float* gf_ah    = (const float*)d_in[11];
    const float* gf_Wout  = (const float*)d_in[12];
    const float* gf_aout  = (const float*)d_in[13];
    const float* hb_W     = (const float*)d_in[14];
    const float* hb_b     = (const float*)d_in[15];
    const float* v1_w     = (const float*)d_in[16];
    const float* v1_b     = (const float*)d_in[17];
    const float* v2_w     = (const float*)d_in[18];
    const float* v2_b     = (const float*)d_in[19];
    float* out = (float*)d_out;

    // resolve device-global scratch addresses (not an allocation)
    float *p_xcat1, *p_whout1, *p_ball;
    cudaGetSymbolAddress((void**)&p_xcat1,  g_xcat1);
    cudaGetSymbolAddress((void**)&p_whout1, g_whout1);
    cudaGetSymbolAddress((void**)&p_ball,   g_ball);

    heads_kernel<<<BTOT, 256>>>(obs_ls, adj_ls, g1_Wh, g1_ah, gf_Wh, gf_ah);

    // GEMM1: [B*16,128] @ [128,512] -> g_whout1   (g1_Wout row-major K x N)
    gemm_tiled<<<dim3(512 / 64, (BTOT * NA) / 64), 256>>>(
        p_xcat1, g1_Wout, p_whout1, 128, 128, 512, 1, 512);

    // GEMM2: b_all = states[8192,256] @ hb_W^T[256,512]
    // hb_W is [n,e,s] row-major: element (k=s, col=n*32+e) at hb_W[col*256 + s]
    gemm_tiled<<<dim3(512 / 64, BTOT / 64), 256>>>(
        states, hb_W, p_ball, 256, 256, 1, 256, 512);

    final_kernel<<<BTOT, 256>>>(agent_qs, states, adj_ls, wn_w, wn_b,
                                g1_aout, gf_Wout, gf_aout, hb_b,
                                v1_w, v1_b, v2_w, v2_b, out);
}

// round 4
// speedup vs baseline: 1.9377x; 1.9377x over previous
#include <cuda_runtime.h>
#include <math.h>
#include <stdint.h>

#define NA 16
#define OBSF 128
#define STATE 256
#define EMBED 32
#define NHID 32
#define BTOT 8192
#define ALPHA 0.2f
#define NEGV -9.0e15f

// ---------------- scratch (device globals) ----------------
__device__ float g_whall[(size_t)BTOT * NA * 256];   // 128 MB  obs@Wh8 (all heads)
__device__ float g_z[(size_t)BTOT * NA * 128];       // 64 MB   att2@xcat1
__device__ float g_w1raw[(size_t)BTOT * NA * 512];   // 256 MB  z@Wout
__device__ float g_ball[(size_t)BTOT * 512];         // 16 MB   b_all pre-bias
__device__ float g_wf[(size_t)BTOT * 512];           // 16 MB   |logsoftmax(gf out)|
__device__ float g_Bheads[128 * 256];                // packed head weights
__device__ float g_BhbT[256 * 512];                  // hb_W transposed
__device__ float g_wa[256];                          // wa1 (128) | wa2 (128)

// =====================================================================
// K0: pack weights + wa vectors
// =====================================================================
__global__ void pack_kernel(const float* __restrict__ g1_Wh, const float* __restrict__ gf_Wh,
                            const float* __restrict__ g1_Wout, const float* __restrict__ g1_aout,
                            const float* __restrict__ hb_W)
{
    int t = threadIdx.x, bid = blockIdx.x;
    int gid = bid * 256 + t;
    for (int idx = gid; idx < 128 * 256; idx += 64 * 256) {
        int k = idx >> 8, c = idx & 255;
        float v = (c < 128) ? g1_Wh[(c >> 5) * 4096 + k * 32 + (c & 31)]
                            : gf_Wh[((c - 128) >> 5) * 4096 + k * 32 + (c & 31)];
        g_Bheads[idx] = v;
    }
    for (int idx = gid; idx < 256 * 512; idx += 64 * 256) {
        int k = idx >> 9, n = idx & 511;
        g_BhbT[idx] = hb_W[n * 256 + k];
    }
    if (bid == 0) {
        int k = t & 127, half = t >> 7;
        const float* ap = g1_aout + half * 512;
        float acc = 0.f;
        for (int c = 0; c < 512; c++) acc = fmaf(g1_Wout[k * 512 + c], ap[c], acc);
        g_wa[half * 128 + k] = acc;
    }
}

// =====================================================================
// TF32 GEMM: C[M,N] = A[M,K] @ B[K,N], all row-major, M%128==N%128==K%32==0
// 128x128 tile, 256 threads (8 warps 4x2), warp tile 32x64, mma m16n8k8
// =====================================================================
__device__ __forceinline__ uint32_t f2tf32(float f) {
    uint32_t u; asm("cvt.rna.tf32.f32 %0, %1;" : "=r"(u) : "f"(f)); return u;
}

#define LDA 36
#define LDB 136

__global__ __launch_bounds__(256) void gemm_tf32(
    const float* __restrict__ A, const float* __restrict__ B, float* __restrict__ C,
    int M, int K, int N)
{
    __shared__ uint32_t As[128 * LDA];
    __shared__ uint32_t Bs[32 * LDB];
    int t = threadIdx.x;
    int lane = t & 31, w = t >> 5;
    int wm = w & 3, wn = w >> 2;
    int bm = blockIdx.y * 128, bn = blockIdx.x * 128;
    int r = lane >> 2, cq = lane & 3;   // groupID, threadID-in-group

    float acc[2][8][4];
    #pragma unroll
    for (int mi = 0; mi < 2; mi++)
        #pragma unroll
        for (int ni = 0; ni < 8; ni++)
            #pragma unroll
            for (int j = 0; j < 4; j++) acc[mi][ni][j] = 0.f;

    for (int k0 = 0; k0 < K; k0 += 32) {
        #pragma unroll
        for (int l = 0; l < 4; l++) {                 // A tile 128x32
            int idx = t + l * 256;
            int row = idx >> 3, q = idx & 7;
            float4 v = *reinterpret_cast<const float4*>(A + (size_t)(bm + row) * K + k0 + q * 4);
            uint32_t* p = &As[row * LDA + q * 4];
            p[0] = f2tf32(v.x); p[1] = f2tf32(v.y); p[2] = f2tf32(v.z); p[3] = f2tf32(v.w);
        }
        #pragma unroll
        for (int l = 0; l < 4; l++) {                 // B tile 32x128
            int idx = t + l * 256;
            int row = idx >> 5, q = idx & 31;
            float4 v = *reinterpret_cast<const float4*>(B + (size_t)(k0 + row) * N + bn + q * 4);
            uint32_t* p = &Bs[row * LDB + q * 4];
            p[0] = f2tf32(v.x); p[1] = f2tf32(v.y); p[2] = f2tf32(v.z); p[3] = f2tf32(v.w);
        }
        __syncthreads();
        #pragma unroll
        for (int kk = 0; kk < 32; kk += 8) {
            uint32_t a[2][4];
            #pragma unroll
            for (int mi = 0; mi < 2; mi++) {
                int rb = wm * 32 + mi * 16;
                a[mi][0] = As[(rb + r) * LDA + kk + cq];
                a[mi][1] = As[(rb + r + 8) * LDA + kk + cq];
                a[mi][2] = As[(rb + r) * LDA + kk + cq + 4];
                a[mi][3] = As[(rb + r + 8) * LDA + kk + cq + 4];
            }
            #pragma unroll
            for (int ni = 0; ni < 8; ni++) {
                int cb = wn * 64 + ni * 8;
                uint32_t b0 = Bs[(kk + cq) * LDB + cb + r];
                uint32_t b1 = Bs[(kk + 4 + cq) * LDB + cb + r];
                #pragma unroll
                for (int mi = 0; mi < 2; mi++) {
                    asm volatile(
                        "mma.sync.aligned.m16n8k8.row.col.f32.tf32.tf32.f32 "
                        "{%0,%1,%2,%3}, {%4,%5,%6,%7}, {%8,%9}, {%0,%1,%2,%3};"
                        : "+f"(acc[mi][ni][0]), "+f"(acc[mi][ni][1]),
                          "+f"(acc[mi][ni][2]), "+f"(acc[mi][ni][3])
                        : "r"(a[mi][0]), "r"(a[mi][1]), "r"(a[mi][2]), "r"(a[mi][3]),
                          "r"(b0), "r"(b1));
                }
            }
        }
        __syncthreads();
    }
    #pragma unroll
    for (int mi = 0; mi < 2; mi++) {
        int rb = bm + wm * 32 + mi * 16 + r;
        #pragma unroll
        for (int ni = 0; ni < 8; ni++) {
            int cb = bn + wn * 64 + ni * 8 + 2 * cq;
            *reinterpret_cast<float2*>(C + (size_t)rb * N + cb) =
                make_float2(acc[mi][ni][0], acc[mi][ni][1]);
            *reinterpret_cast<float2*>(C + (size_t)(rb + 8) * N + cb) =
                make_float2(acc[mi][ni][2], acc[mi][ni][3]);
        }
    }
}

// =====================================================================
// K1: per-b attention for all 8 heads + g1-out attention (via wa) -> z,
//     plus the full gf output path -> g_wf
// =====================================================================
__global__ __launch_bounds__(256) void attn_kernel(
    const float* __restrict__ adj_g,
    const float* __restrict__ g1_ah, const float* __restrict__ gf_ah,
    const float* __restrict__ gf_Wout, const float* __restrict__ gf_aout)
{
    int b = blockIdx.x;
    int t = threadIdx.x;
    int lane = t & 31, w = t >> 5;

    __shared__ float wh8[NA][256];
    __shared__ float xc1[NA][128];
    __shared__ float xcf[NA][128];
    __shared__ float adj[NA][NA];
    __shared__ float att[NA][NA];
    __shared__ float f1[NA], f2[NA];
    __shared__ float whf[NA][32];
    __shared__ float whf2[NA][32];

    for (int idx = t; idx < NA * 256; idx += 256)
        wh8[idx >> 8][idx & 255] = g_whall[(size_t)b * 4096 + idx];
    adj[t >> 4][t & 15] = adj_g[(size_t)b * 256 + t];
    __syncthreads();

    // ---- 8 heads ----
    for (int h = 0; h < 8; h++) {
        const float* a = (h < 4) ? (g1_ah + (size_t)h * 2 * NHID)
                                 : (gf_ah + (size_t)(h - 4) * 2 * NHID);
        if (t < 32) {
            int d = t & 15;
            const float* av = a + ((t >= 16) ? NHID : 0);
            float acc = 0.f;
            #pragma unroll
            for (int c = 0; c < NHID; c++) acc = fmaf(wh8[d][h * 32 + c], av[c], acc);
            if (t >= 16) f2[d] = acc; else f1[d] = acc;
        }
        __syncthreads();
        if (t < NA) {
            int j = t;
            float ev[NA]; float m = -INFINITY;
            #pragma unroll
            for (int i = 0; i < NA; i++) {
                float e = f1[i] + f2[j];
                e = e > 0.f ? e : ALPHA * e;
                e = (adj[i][j] > 0.f) ? e : NEGV;
                ev[i] = e; m = fmaxf(m, e);
            }
            float s = 0.f;
            #pragma unroll
            for (int i = 0; i < NA; i++) { float x = expf(ev[i] - m); ev[i] = x; s += x; }
            float inv = 1.f / s;
            #pragma unroll
            for (int i = 0; i < NA; i++) att[i][j] = ev[i] * inv;
        }
        __syncthreads();
        #pragma unroll
        for (int l = 0; l < 2; l++) {
            int idx = t + l * 256;
            int i = idx >> 5, c = idx & 31;
            float acc = 0.f;
            #pragma unroll
            for (int n = 0; n < NA; n++) acc = fmaf(att[i][n], wh8[n][h * 32 + c], acc);
            acc = acc > 0.f ? acc : expm1f(acc);
            if (h < 4) xc1[i][h * 32 + c] = acc;
            else       xcf[i][(h - 4) * 32 + c] = acc;
        }
        __syncthreads();
    }

    // ---- g1-out scores: f = xcat1 @ wa ----
    #pragma unroll
    for (int rr = 0; rr < 4; rr++) {
        int d = w * 4 + rr;            // 0..31
        int i = d & 15, half = d >> 4;
        const float* wav = g_wa + half * 128;
        float acc = 0.f;
        #pragma unroll
        for (int k = lane; k < 128; k += 32) acc = fmaf(xc1[i][k], wav[k], acc);
        #pragma unroll
        for (int o = 16; o; o >>= 1) acc += __shfl_down_sync(0xffffffffu, acc, o);
        if (lane == 0) { if (half) f2[i] = acc; else f1[i] = acc; }
    }
    __syncthreads();
    if (t < NA) {
        int j = t;
        float ev[NA]; float m = -INFINITY;
        #pragma unroll
        for (int i = 0; i < NA; i++) {
            float e = f1[i] + f2[j];
            e = e > 0.f ? e : ALPHA * e;
            e = (adj[i][j] > 0.f) ? e : NEGV;
            ev[i] = e; m = fmaxf(m, e);
        }
        float s = 0.f;
        #pragma unroll
        for (int i = 0; i < NA; i++) { float x = expf(ev[i] - m); ev[i] = x; s += x; }
        float inv = 1.f / s;
        #pragma unroll
        for (int i = 0; i < NA; i++) att[i][j] = ev[i] * inv;
    }
    __syncthreads();

    // ---- z = att2 @ xcat1 -> global ----
    #pragma unroll
    for (int l = 0; l < 8; l++) {
        int idx = t + l * 256;
        int i = idx >> 7, k = idx & 127;
        float acc = 0.f;
        #pragma unroll
        for (int n = 0; n < NA; n++) acc = fmaf(att[i][n], xc1[n][k], acc);
        g_z[(size_t)b * 2048 + idx] = acc;
    }

    // ---- gf output layer: whf = xcatf @ gf_Wout (16x32, K=128) ----
    #pragma unroll
    for (int l = 0; l < 2; l++) {
        int idx = t + l * 256;
        int i = idx >> 5, c = idx & 31;
        float acc = 0.f;
        #pragma unroll 4
        for (int k = 0; k < 128; k++) acc = fmaf(xcf[i][k], gf_Wout[k * 32 + c], acc);
        whf[i][c] = acc;
    }
    __syncthreads();

    if (t < 32) {
        int d = t & 15;
        const float* av = gf_aout + ((t < 16) ? 0 : 32);
        float acc = 0.f;
        #pragma unroll
        for (int c = 0; c < 32; c++) acc = fmaf(whf[d][c], av[c], acc);
        if (t < 16) f1[d] = acc; else f2[d] = acc;
    }
    __syncthreads();
    if (t < NA) {
        int j = t;
        float ev[NA]; float m = -INFINITY;
        #pragma unroll
        for (int i = 0; i < NA; i++) {
            float e = f1[i] + f2[j];
            e = e > 0.f ? e : ALPHA * e;
            e = (adj[i][j] > 0.f) ? e : NEGV;
            ev[i] = e; m = fmaxf(m, e);
        }
        float s = 0.f;
        #pragma unroll
        for (int i = 0; i < NA; i++) { float x = expf(ev[i] - m); ev[i] = x; s += x; }
        float inv = 1.f / s;
        #pragma unroll
        for (int i = 0; i < NA; i++) att[i][j] = ev[i] * inv;
    }
    __syncthreads();
    #pragma unroll
    for (int l = 0; l < 2; l++) {
        int idx = t + l * 256;
        int i = idx >> 5, c = idx & 31;
        float acc = 0.f;
        #pragma unroll
        for (int n = 0; n < NA; n++) acc = fmaf(att[i][n], whf[n][c], acc);
        whf2[i][c] = acc > 0.f ? acc : expm1f(acc);
    }
    __syncthreads();
    if (t < 32) {        // log_softmax over agents per col, abs, store
        int c = t;
        float m = -INFINITY;
        #pragma unroll
        for (int i = 0; i < NA; i++) m = fmaxf(m, whf2[i][c]);
        float s = 0.f;
        #pragma unroll
        for (int i = 0; i < NA; i++) s += expf(whf2[i][c] - m);
        float lse = m + logf(s);
        #pragma unroll
        for (int i = 0; i < NA; i++)
            g_wf[(size_t)b * 512 + i * 32 + c] = fabsf(whf2[i][c] - lse);
    }
}

// =====================================================================
// K3: elu -> log_softmax -> abs on D, hidden, y, dis, V, q
// =====================================================================
__global__ __launch_bounds__(512) void mix_kernel(
    const float* __restrict__ agent_qs, const float* __restrict__ states,
    const float* __restrict__ wn_w, const float* __restrict__ wn_b,
    const float* __restrict__ hb_b,
    const float* __restrict__ v1_w, const float* __restrict__ v1_b,
    const float* __restrict__ v2_w, const float* __restrict__ v2_b,
    float* __restrict__ out)
{
    int b = blockIdx.x;
    int t = threadIdx.x;
    int lane = t & 31, w = t >> 5;     // 16 warps

    __shared__ float w1[NA * 512];     // 32 KB
    __shared__ float st[STATE];
    __shared__ float qs[NA];
    __shared__ float yv[NA], disv[NA], vpart[32];

    for (int idx = t; idx < NA * 512; idx += 512)
        w1[idx] = g_w1raw[(size_t)b * 8192 + idx];
    if (t < 256) st[t] = states[(size_t)b * 256 + t];
    if (t < NA) qs[t] = agent_qs[(size_t)b * NA + t];
    __syncthreads();

    {   // per-column: elu -> logsoftmax over agents -> abs
        int col = t;                   // 0..511
        float e[NA]; float m = -INFINITY;
        #pragma unroll
        for (int i = 0; i < NA; i++) {
            float x = w1[i * 512 + col];
            x = x > 0.f ? x : expm1f(x);
            e[i] = x; m = fmaxf(m, x);
        }
        float s = 0.f;
        #pragma unroll
        for (int i = 0; i < NA; i++) s += expf(e[i] - m);
        float lse = m + logf(s);
        #pragma unroll
        for (int i = 0; i < NA; i++) w1[i * 512 + col] = fabsf(e[i] - lse);
    }
    __syncthreads();

    {   // hidden + y: warp w owns agent i=w, lanes own e
        int i = w, e = lane;
        float hacc = g_ball[(size_t)b * 512 + i * 32 + e] + hb_b[i * 32 + e];
        #pragma unroll
        for (int n = 0; n < NA; n++)
            hacc = fmaf(qs[n], w1[i * 512 + n * 32 + e], hacc);
        hacc = hacc > 0.f ? hacc : expm1f(hacc);
        float prod = hacc * g_wf[(size_t)b * 512 + i * 32 + e];
        #pragma unroll
        for (int o = 16; o; o >>= 1) prod += __shfl_down_sync(0xffffffffu, prod, o);
        if (lane == 0) yv[i] = prod;
    }

    {   // dis (warp w -> agent w) and V (warp w -> rows 2w, 2w+1)
        float acc = 0.f;
        #pragma unroll
        for (int s_ = lane; s_ < 256; s_ += 32) acc = fmaf(st[s_], wn_w[w * 256 + s_], acc);
        #pragma unroll
        for (int o = 16; o; o >>= 1) acc += __shfl_down_sync(0xffffffffu, acc, o);
        if (lane == 0) disv[w] = fabsf(acc + wn_b[w]);
        #pragma unroll
        for (int rr = 0; rr < 2; rr++) {
            int n = w * 2 + rr;
            float a2 = 0.f;
            #pragma unroll
            for (int s_ = lane; s_ < 256; s_ += 32) a2 = fmaf(st[s_], v1_w[n * 256 + s_], a2);
            #pragma unroll
            for (int o = 16; o; o >>= 1) a2 += __shfl_down_sync(0xffffffffu, a2, o);
            if (lane == 0) vpart[n] = fmaxf(a2 + v1_b[n], 0.f);
        }
    }
    __syncthreads();

    if (t == 0) {
        float v = v2_b[0];
        #pragma unroll
        for (int h = 0; h < 32; h++) v = fmaf(vpart[h], v2_w[h], v);
        float q = v;
        #pragma unroll
        for (int n = 0; n < NA; n++) q = fmaf(yv[n], disv[n], q);
        out[b] = q;
    }
}

// =====================================================================
extern "C" void kernel_launch(void* const* d_in, const int* in_sizes, int n_in,
                              void* d_out, int out_size)
{
    const float* agent_qs = (const float*)d_in[0];
    const float* states   = (const float*)d_in[1];
    const float* obs_ls   = (const float*)d_in[2];
    const float* adj_ls   = (const float*)d_in[3];
    const float* wn_w     = (const float*)d_in[4];
    const float* wn_b     = (const float*)d_in[5];
    const float* g1_Wh    = (const float*)d_in[6];
    const float* g1_ah    = (const float*)d_in[7];
    const float* g1_Wout  = (const float*)d_in[8];
    const float* g1_aout  = (const float*)d_in[9];
    const float* gf_Wh    = (const float*)d_in[10];
    const float* gf_ah    = (const float*)d_in[11];
    const float* gf_Wout  = (const float*)d_in[12];
    const float* gf_aout  = (const float*)d_in[13];
    const float* hb_W     = (const float*)d_in[14];
    const float* hb_b     = (const float*)d_in[15];
    const float* v1_w     = (const float*)d_in[16];
    const float* v1_b     = (const float*)d_in[17];
    const float* v2_w     = (const float*)d_in[18];
    const float* v2_b     = (const float*)d_in[19];
    float* out = (float*)d_out;

    float *p_whall, *p_z, *p_w1raw, *p_ball, *p_Bheads, *p_BhbT;
    cudaGetSymbolAddress((void**)&p_whall,  g_whall);
    cudaGetSymbolAddress((void**)&p_z,      g_z);
    cudaGetSymbolAddress((void**)&p_w1raw,  g_w1raw);
    cudaGetSymbolAddress((void**)&p_ball,   g_ball);
    cudaGetSymbolAddress((void**)&p_Bheads, g_Bheads);
    cudaGetSymbolAddress((void**)&p_BhbT,   g_BhbT);

    pack_kernel<<<64, 256>>>(g1_Wh, gf_Wh, g1_Wout, g1_aout, hb_W);

    // Whall = obs(131072x128) @ Bheads(128x256)
    gemm_tf32<<<dim3(2, 1024), 256>>>(obs_ls, p_Bheads, p_whall, BTOT * NA, 128, 256);

    // b_all = states(8192x256) @ hb_W^T(256x512)
    gemm_tf32<<<dim3(4, 64), 256>>>(states, p_BhbT, p_ball, BTOT, 256, 512);

    attn_kernel<<<BTOT, 256>>>(adj_ls, g1_ah, gf_ah, gf_Wout, gf_aout);

    // D = Z(131072x128) @ Wout(128x512)
    gemm_tf32<<<dim3(4, 1024), 256>>>(p_z, g1_Wout, p_w1raw, BTOT * NA, 128, 512);

    mix_kernel<<<BTOT, 512>>>(agent_qs, states, wn_w, wn_b, hb_b,
                              v1_w, v1_b, v2_w, v2_b, out);
}

// round 6
// speedup vs baseline: 2.1794x; 1.1247x over previous
#include <cuda_runtime.h>
#include <math.h>
#include <stdint.h>

#define NA 16
#define OBSF 128
#define STATE 256
#define EMBED 32
#define NHID 32
#define BTOT 8192
#define ALPHA 0.2f
#define NEGV -9.0e15f
#define FULLM 0xffffffffu

// ---------------- scratch (device globals) ----------------
__device__ float g_whall[(size_t)BTOT * NA * 256];   // 128 MB  obs@Wh8 (all heads)
__device__ float g_z[(size_t)BTOT * NA * 128];       // 64 MB   att2@xcat1
__device__ float g_w1raw[(size_t)BTOT * NA * 512];   // 256 MB  z@Wout
__device__ float g_ball[(size_t)BTOT * 512];         // 16 MB   b_all pre-bias
__device__ float g_wf[(size_t)BTOT * 512];           // 16 MB   |logsoftmax(gf out)|
__device__ float g_Bheads[128 * 256];                // packed head weights
__device__ float g_BhbT[256 * 512];                  // hb_W transposed
__device__ float g_wa[256];                          // wa1 (128) | wa2 (128)

// =====================================================================
// K0: pack weights + wa vectors
// =====================================================================
__global__ void pack_kernel(const float* __restrict__ g1_Wh, const float* __restrict__ gf_Wh,
                            const float* __restrict__ g1_Wout, const float* __restrict__ g1_aout,
                            const float* __restrict__ hb_W)
{
    int t = threadIdx.x, bid = blockIdx.x;
    int gid = bid * 256 + t;
    for (int idx = gid; idx < 128 * 256; idx += 64 * 256) {
        int k = idx >> 8, c = idx & 255;
        float v = (c < 128) ? g1_Wh[(c >> 5) * 4096 + k * 32 + (c & 31)]
                            : gf_Wh[((c - 128) >> 5) * 4096 + k * 32 + (c & 31)];
        g_Bheads[idx] = v;
    }
    for (int idx = gid; idx < 256 * 512; idx += 64 * 256) {
        int k = idx >> 9, n = idx & 511;
        g_BhbT[idx] = hb_W[n * 256 + k];
    }
    if (bid == 0) {
        int k = t & 127, half = t >> 7;
        const float* ap = g1_aout + half * 512;
        float acc = 0.f;
        for (int c = 0; c < 512; c++) acc = fmaf(g1_Wout[k * 512 + c], ap[c], acc);
        g_wa[half * 128 + k] = acc;
    }
}

// =====================================================================
// TF32 GEMM: C[M,N] = A[M,K] @ B[K,N], row-major, M%128==N%128==K%32==0
// =====================================================================
__device__ __forceinline__ uint32_t f2tf32(float f) {
    uint32_t u; asm("cvt.rna.tf32.f32 %0, %1;" : "=r"(u) : "f"(f)); return u;
}

#define LDA 36
#define LDB 136

__global__ __launch_bounds__(256) void gemm_tf32(
    const float* __restrict__ A, const float* __restrict__ B, float* __restrict__ C,
    int M, int K, int N)
{
    __shared__ uint32_t As[128 * LDA];
    __shared__ uint32_t Bs[32 * LDB];
    int t = threadIdx.x;
    int lane = t & 31, w = t >> 5;
    int wm = w & 3, wn = w >> 2;
    int bm = blockIdx.y * 128, bn = blockIdx.x * 128;
    int r = lane >> 2, cq = lane & 3;

    float acc[2][8][4];
    #pragma unroll
    for (int mi = 0; mi < 2; mi++)
        #pragma unroll
        for (int ni = 0; ni < 8; ni++)
            #pragma unroll
            for (int j = 0; j < 4; j++) acc[mi][ni][j] = 0.f;

    for (int k0 = 0; k0 < K; k0 += 32) {
        #pragma unroll
        for (int l = 0; l < 4; l++) {
            int idx = t + l * 256;
            int row = idx >> 3, q = idx & 7;
            float4 v = *reinterpret_cast<const float4*>(A + (size_t)(bm + row) * K + k0 + q * 4);
            uint32_t* p = &As[row * LDA + q * 4];
            p[0] = f2tf32(v.x); p[1] = f2tf32(v.y); p[2] = f2tf32(v.z); p[3] = f2tf32(v.w);
        }
        #pragma unroll
        for (int l = 0; l < 4; l++) {
            int idx = t + l * 256;
            int row = idx >> 5, q = idx & 31;
            float4 v = *reinterpret_cast<const float4*>(B + (size_t)(k0 + row) * N + bn + q * 4);
            uint32_t* p = &Bs[row * LDB + q * 4];
            p[0] = f2tf32(v.x); p[1] = f2tf32(v.y); p[2] = f2tf32(v.z); p[3] = f2tf32(v.w);
        }
        __syncthreads();
        #pragma unroll
        for (int kk = 0; kk < 32; kk += 8) {
            uint32_t a[2][4];
            #pragma unroll
            for (int mi = 0; mi < 2; mi++) {
                int rb = wm * 32 + mi * 16;
                a[mi][0] = As[(rb + r) * LDA + kk + cq];
                a[mi][1] = As[(rb + r + 8) * LDA + kk + cq];
                a[mi][2] = As[(rb + r) * LDA + kk + cq + 4];
                a[mi][3] = As[(rb + r + 8) * LDA + kk + cq + 4];
            }
            #pragma unroll
            for (int ni = 0; ni < 8; ni++) {
                int cb = wn * 64 + ni * 8;
                uint32_t b0 = Bs[(kk + cq) * LDB + cb + r];
                uint32_t b1 = Bs[(kk + 4 + cq) * LDB + cb + r];
                #pragma unroll
                for (int mi = 0; mi < 2; mi++) {
                    asm volatile(
                        "mma.sync.aligned.m16n8k8.row.col.f32.tf32.tf32.f32 "
                        "{%0,%1,%2,%3}, {%4,%5,%6,%7}, {%8,%9}, {%0,%1,%2,%3};"
                        : "+f"(acc[mi][ni][0]), "+f"(acc[mi][ni][1]),
                          "+f"(acc[mi][ni][2]), "+f"(acc[mi][ni][3])
                        : "r"(a[mi][0]), "r"(a[mi][1]), "r"(a[mi][2]), "r"(a[mi][3]),
                          "r"(b0), "r"(b1));
                }
            }
        }
        __syncthreads();
    }
    #pragma unroll
    for (int mi = 0; mi < 2; mi++) {
        int rb = bm + wm * 32 + mi * 16 + r;
        #pragma unroll
        for (int ni = 0; ni < 8; ni++) {
            int cb = bn + wn * 64 + ni * 8 + 2 * cq;
            *reinterpret_cast<float2*>(C + (size_t)rb * N + cb) =
                make_float2(acc[mi][ni][0], acc[mi][ni][1]);
            *reinterpret_cast<float2*>(C + (size_t)(rb + 8) * N + cb) =
                make_float2(acc[mi][ni][2], acc[mi][ni][3]);
        }
    }
}

// =====================================================================
// K1: warp-per-head attention; att lives in registers, spread by shfl.
// Static smem = 40,960 B (< 48 KB).
// =====================================================================
#define WH8P 260
#define XCP 132

__global__ __launch_bounds__(256) void attn_kernel(
    const float* __restrict__ adj_g,
    const float* __restrict__ g1_ah, const float* __restrict__ gf_ah,
    const float* __restrict__ gf_Wout, const float* __restrict__ gf_aout)
{
    int b = blockIdx.x;
    int t = threadIdx.x;
    int lane = t & 31, w = t >> 5;

    __shared__ float wh8[NA][WH8P];      // 16640 B, bank-stride-4 padding
    __shared__ float xc1[NA][XCP];       //  8448 B
    __shared__ float xcf[NA][XCP];       //  8448 B
    __shared__ float adj[NA][NA];        //  1024 B
    __shared__ float sa[8][64];          //  2048 B  all head a-vectors
    __shared__ float swa[256];           //  1024 B  wa1|wa2
    __shared__ float f1s[NA], f2s[NA];   //   128 B
    __shared__ float att2s[NA][17];      //  1088 B
    __shared__ float whf[NA][33];        //  2112 B

    // ---- loads (float4 for whall) ----
    {
        const float4* src = reinterpret_cast<const float4*>(g_whall + (size_t)b * 4096);
        #pragma unroll
        for (int l = 0; l < 4; l++) {
            int idx4 = t + l * 256;              // 0..1023
            int row = idx4 >> 6, c4 = (idx4 & 63) * 4;
            float4 v = src[idx4];
            wh8[row][c4] = v.x; wh8[row][c4 + 1] = v.y;
            wh8[row][c4 + 2] = v.z; wh8[row][c4 + 3] = v.w;
        }
    }
    adj[t >> 4][t & 15] = adj_g[(size_t)b * 256 + t];
    #pragma unroll
    for (int idx = t; idx < 512; idx += 256) {
        int h = idx >> 6, c = idx & 63;
        sa[h][c] = (h < 4) ? g1_ah[h * 64 + c] : gf_ah[(h - 4) * 64 + c];
    }
    swa[t] = g_wa[t];
    __syncthreads();

    // ---- warp w owns head w entirely; att kept in registers ----
    {
        int h = w;
        int d = lane & 15, half = lane >> 4;
        const float* av = &sa[h][half * 32];
        float facc = 0.f;
        #pragma unroll
        for (int c = 0; c < 32; c++) facc = fmaf(wh8[d][h * 32 + c], av[c], facc);
        // lanes 0..15 hold f1[d]; lanes 16..31 hold f2[d]
        int j = lane & 15;
        float f2j = __shfl_sync(FULLM, facc, 16 + j);
        float attc[NA];                    // lane j holds att[i][j] (i = reg idx)
        float m = -INFINITY;
        #pragma unroll
        for (int i = 0; i < NA; i++) {
            float f1i = __shfl_sync(FULLM, facc, i);
            float e = f1i + f2j;
            e = e > 0.f ? e : ALPHA * e;
            e = (adj[i][j] > 0.f) ? e : NEGV;
            attc[i] = e; m = fmaxf(m, e);
        }
        float s = 0.f;
        #pragma unroll
        for (int i = 0; i < NA; i++) { float x = expf(attc[i] - m); attc[i] = x; s += x; }
        float inv = 1.f / s;
        #pragma unroll
        for (int i = 0; i < NA; i++) attc[i] *= inv;
        // out[i][c], c = lane; att[i][n] pulled from lane n by shfl
        int c = lane;
        float* dst0 = (h < 4) ? &xc1[0][h * 32 + c] : &xcf[0][(h - 4) * 32 + c];
        #pragma unroll
        for (int i = 0; i < NA; i++) {
            float acc = 0.f;
            #pragma unroll
            for (int n = 0; n < NA; n++) {
                float a_in = __shfl_sync(FULLM, attc[i], n);
                acc = fmaf(a_in, wh8[n][h * 32 + c], acc);
            }
            acc = acc > 0.f ? acc : expm1f(acc);
            dst0[i * XCP] = acc;
        }
    }
    __syncthreads();

    // ---- g1-out scores via wa:  f = xc1 @ wa ----
    #pragma unroll
    for (int rr = 0; rr < 4; rr++) {
        int d = w * 4 + rr;                 // 0..31
        int i = d & 15, half = d >> 4;
        const float* wav = &swa[half * 128];
        float acc = 0.f;
        #pragma unroll
        for (int k = lane; k < 128; k += 32) acc = fmaf(xc1[i][k], wav[k], acc);
        #pragma unroll
        for (int o = 16; o; o >>= 1) acc += __shfl_down_sync(FULLM, acc, o);
        if (lane == 0) { if (half) f2s[i] = acc; else f1s[i] = acc; }
    }
    __syncthreads();
    if (t < NA) {
        int j = t;
        float ev[NA]; float m = -INFINITY;
        #pragma unroll
        for (int i = 0; i < NA; i++) {
            float e = f1s[i] + f2s[j];
            e = e > 0.f ? e : ALPHA * e;
            e = (adj[i][j] > 0.f) ? e : NEGV;
            ev[i] = e; m = fmaxf(m, e);
        }
        float s = 0.f;
        #pragma unroll
        for (int i = 0; i < NA; i++) { float x = expf(ev[i] - m); ev[i] = x; s += x; }
        float inv = 1.f / s;
        #pragma unroll
        for (int i = 0; i < NA; i++) att2s[i][j] = ev[i] * inv;
    }
    __syncthreads();

    // z = att2 @ xc1 -> global
    #pragma unroll
    for (int l = 0; l < 8; l++) {
        int idx = t + l * 256;
        int i = idx >> 7, k = idx & 127;
        float acc = 0.f;
        #pragma unroll
        for (int n = 0; n < NA; n++) acc = fmaf(att2s[i][n], xc1[n][k], acc);
        g_z[(size_t)b * 2048 + idx] = acc;
    }

    // whf = xcf @ gf_Wout (16x32, K=128)
    #pragma unroll
    for (int l = 0; l < 2; l++) {
        int idx = t + l * 256;
        int i = idx >> 5, c = idx & 31;
        float acc = 0.f;
        #pragma unroll 4
        for (int k = 0; k < 128; k++) acc = fmaf(xcf[i][k], gf_Wout[k * 32 + c], acc);
        whf[i][c] = acc;
    }
    __syncthreads();

    // gf attention (single warp; att + out + logsoftmax all in registers)
    if (w == 0) {
        int d = lane & 15, half = lane >> 4;
        const float* av = gf_aout + half * 32;
        float facc = 0.f;
        #pragma unroll
        for (int c = 0; c < 32; c++) facc = fmaf(whf[d][c], av[c], facc);
        int j = lane & 15;
        float f2j = __shfl_sync(FULLM, facc, 16 + j);
        float attc[NA];
        float m = -INFINITY;
        #pragma unroll
        for (int i = 0; i < NA; i++) {
            float f1i = __shfl_sync(FULLM, facc, i);
            float e = f1i + f2j;
            e = e > 0.f ? e : ALPHA * e;
            e = (adj[i][j] > 0.f) ? e : NEGV;
            attc[i] = e; m = fmaxf(m, e);
        }
        float s = 0.f;
        #pragma unroll
        for (int i = 0; i < NA; i++) { float x = expf(attc[i] - m); attc[i] = x; s += x; }
        float inv = 1.f / s;
        #pragma unroll
        for (int i = 0; i < NA; i++) attc[i] *= inv;
        // out2[i] for column c = lane, in registers
        int c = lane;
        float o2[NA];
        float mm = -INFINITY;
        #pragma unroll
        for (int i = 0; i < NA; i++) {
            float acc = 0.f;
            #pragma unroll
            for (int n = 0; n < NA; n++) {
                float a_in = __shfl_sync(FULLM, attc[i], n);
                acc = fmaf(a_in, whf[n][c], acc);
            }
            acc = acc > 0.f ? acc : expm1f(acc);
            o2[i] = acc; mm = fmaxf(mm, acc);
        }
        float ss = 0.f;
        #pragma unroll
        for (int i = 0; i < NA; i++) ss += expf(o2[i] - mm);
        float lse = mm + logf(ss);
        #pragma unroll
        for (int i = 0; i < NA; i++)
            g_wf[(size_t)b * 512 + i * 32 + c] = fabsf(o2[i] - lse);
    }
}

// =====================================================================
// K3: elu -> log_softmax -> abs on D, hidden, y, dis, V, q
// =====================================================================
__global__ __launch_bounds__(512) void mix_kernel(
    const float* __restrict__ agent_qs, const float* __restrict__ states,
    const float* __restrict__ wn_w, const float* __restrict__ wn_b,
    const float* __restrict__ hb_b,
    const float* __restrict__ v1_w, const float* __restrict__ v1_b,
    const float* __restrict__ v2_w, const float* __restrict__ v2_b,
    float* __restrict__ out)
{
    int b = blockIdx.x;
    int t = threadIdx.x;
    int lane = t & 31, w = t >> 5;

    __shared__ float w1[NA * 512];
    __shared__ float st[STATE];
    __shared__ float qs[NA];
    __shared__ float yv[NA], disv[NA], vpart[32];

    for (int idx = t; idx < NA * 512; idx += 512)
        w1[idx] = g_w1raw[(size_t)b * 8192 + idx];
    if (t < 256) st[t] = states[(size_t)b * 256 + t];
    if (t < NA) qs[t] = agent_qs[(size_t)b * NA + t];
    __syncthreads();

    {
        int col = t;
        float e[NA]; float m = -INFINITY;
        #pragma unroll
        for (int i = 0; i < NA; i++) {
            float x = w1[i * 512 + col];
            x = x > 0.f ? x : expm1f(x);
            e[i] = x; m = fmaxf(m, x);
        }
        float s = 0.f;
        #pragma unroll
        for (int i = 0; i < NA; i++) s += expf(e[i] - m);
        float lse = m + logf(s);
        #pragma unroll
        for (int i = 0; i < NA; i++) w1[i * 512 + col] = fabsf(e[i] - lse);
    }
    __syncthreads();

    {
        int i = w, e = lane;
        float hacc = g_ball[(size_t)b * 512 + i * 32 + e] + hb_b[i * 32 + e];
        #pragma unroll
        for (int n = 0; n < NA; n++)
            hacc = fmaf(qs[n], w1[i * 512 + n * 32 + e], hacc);
        hacc = hacc > 0.f ? hacc : expm1f(hacc);
        float prod = hacc * g_wf[(size_t)b * 512 + i * 32 + e];
        #pragma unroll
        for (int o = 16; o; o >>= 1) prod += __shfl_down_sync(FULLM, prod, o);
        if (lane == 0) yv[i] = prod;
    }

    {
        float acc = 0.f;
        #pragma unroll
        for (int s_ = lane; s_ < 256; s_ += 32) acc = fmaf(st[s_], wn_w[w * 256 + s_], acc);
        #pragma unroll
        for (int o = 16; o; o >>= 1) acc += __shfl_down_sync(FULLM, acc, o);
        if (lane == 0) disv[w] = fabsf(acc + wn_b[w]);
        #pragma unroll
        for (int rr = 0; rr < 2; rr++) {
            int n = w * 2 + rr;
            float a2 = 0.f;
            #pragma unroll
            for (int s_ = lane; s_ < 256; s_ += 32) a2 = fmaf(st[s_], v1_w[n * 256 + s_], a2);
            #pragma unroll
            for (int o = 16; o; o >>= 1) a2 += __shfl_down_sync(FULLM, a2, o);
            if (lane == 0) vpart[n] = fmaxf(a2 + v1_b[n], 0.f);
        }
    }
    __syncthreads();

    if (t == 0) {
        float v = v2_b[0];
        #pragma unroll
        for (int h = 0; h < 32; h++) v = fmaf(vpart[h], v2_w[h], v);
        float q = v;
        #pragma unroll
        for (int n = 0; n < NA; n++) q = fmaf(yv[n], disv[n], q);
        out[b] = q;
    }
}

// =====================================================================
extern "C" void kernel_launch(void* const* d_in, const int* in_sizes, int n_in,
                              void* d_out, int out_size)
{
    const float* agent_qs = (const float*)d_in[0];
    const float* states   = (const float*)d_in[1];
    const float* obs_ls   = (const float*)d_in[2];
    const float* adj_ls   = (const float*)d_in[3];
    const float* wn_w     = (const float*)d_in[4];
    const float* wn_b     = (const float*)d_in[5];
    const float* g1_Wh    = (const float*)d_in[6];
    const float* g1_ah    = (const float*)d_in[7];
    const float* g1_Wout  = (const float*)d_in[8];
    const float* g1_aout  = (const float*)d_in[9];
    const float* gf_Wh    = (const float*)d_in[10];
    const float* gf_ah    = (const float*)d_in[11];
    const float* gf_Wout  = (const float*)d_in[12];
    const float* gf_aout  = (const float*)d_in[13];
    const float* hb_W     = (const float*)d_in[14];
    const float* hb_b     = (const float*)d_in[15];
    const float* v1_w     = (const float*)d_in[16];
    const float* v1_b     = (const float*)d_in[17];
    const float* v2_w     = (const float*)d_in[18];
    const float* v2_b     = (const float*)d_in[19];
    float* out = (float*)d_out;

    float *p_whall, *p_z, *p_w1raw, *p_ball, *p_Bheads, *p_BhbT;
    cudaGetSymbolAddress((void**)&p_whall,  g_whall);
    cudaGetSymbolAddress((void**)&p_z,      g_z);
    cudaGetSymbolAddress((void**)&p_w1raw,  g_w1raw);
    cudaGetSymbolAddress((void**)&p_ball,   g_ball);
    cudaGetSymbolAddress((void**)&p_Bheads, g_Bheads);
    cudaGetSymbolAddress((void**)&p_BhbT,   g_BhbT);

    pack_kernel<<<64, 256>>>(g1_Wh, gf_Wh, g1_Wout, g1_aout, hb_W);

    // Whall = obs(131072x128) @ Bheads(128x256)
    gemm_tf32<<<dim3(2, 1024), 256>>>(obs_ls, p_Bheads, p_whall, BTOT * NA, 128, 256);

    // b_all = states(8192x256) @ hb_W^T(256x512)
    gemm_tf32<<<dim3(4, 64), 256>>>(states, p_BhbT, p_ball, BTOT, 256, 512);

    attn_kernel<<<BTOT, 256>>>(adj_ls, g1_ah, gf_ah, gf_Wout, gf_aout);

    // D = Z(131072x128) @ Wout(128x512)
    gemm_tf32<<<dim3(4, 1024), 256>>>(p_z, g1_Wout, p_w1raw, BTOT * NA, 128, 512);

    mix_kernel<<<BTOT, 512>>>(agent_qs, states, wn_w, wn_b, hb_b,
                              v1_w, v1_b, v2_w, v2_b, out);
}

// round 7
// speedup vs baseline: 2.5583x; 1.1739x over previous
#include <cuda_runtime.h>
#include <math.h>
#include <stdint.h>

#define NA 16
#define OBSF 128
#define STATE 256
#define EMBED 32
#define NHID 32
#define BTOT 8192
#define ALPHA 0.2f
#define NEGV -9.0e15f
#define FULLM 0xffffffffu

// ---------------- scratch (device globals) ----------------
__device__ float g_whall[(size_t)BTOT * NA * 256];   // 128 MB  obs@Wh8 (all heads)
__device__ float g_z[(size_t)BTOT * NA * 128];       // 64 MB   att2@xcat1
__device__ float g_ball[(size_t)BTOT * 512];         // 16 MB   b_all pre-bias
__device__ float g_wf[(size_t)BTOT * 512];           // 16 MB   |logsoftmax(gf out)|
__device__ float g_Bheads[128 * 256];                // packed head weights
__device__ float g_BhbT[256 * 512];                  // hb_W transposed
__device__ float g_wa[256];                          // wa1 (128) | wa2 (128)

// =====================================================================
// K0: pack weights + wa vectors
// =====================================================================
__global__ void pack_kernel(const float* __restrict__ g1_Wh, const float* __restrict__ gf_Wh,
                            const float* __restrict__ g1_Wout, const float* __restrict__ g1_aout,
                            const float* __restrict__ hb_W)
{
    int t = threadIdx.x, bid = blockIdx.x;
    int gid = bid * 256 + t;
    for (int idx = gid; idx < 128 * 256; idx += 64 * 256) {
        int k = idx >> 8, c = idx & 255;
        float v = (c < 128) ? g1_Wh[(c >> 5) * 4096 + k * 32 + (c & 31)]
                            : gf_Wh[((c - 128) >> 5) * 4096 + k * 32 + (c & 31)];
        g_Bheads[idx] = v;
    }
    for (int idx = gid; idx < 256 * 512; idx += 64 * 256) {
        int k = idx >> 9, n = idx & 511;
        g_BhbT[idx] = hb_W[n * 256 + k];
    }
    if (bid == 0) {
        int k = t & 127, half = t >> 7;
        const float* ap = g1_aout + half * 512;
        float acc = 0.f;
        for (int c = 0; c < 512; c++) acc = fmaf(g1_Wout[k * 512 + c], ap[c], acc);
        g_wa[half * 128 + k] = acc;
    }
}

// =====================================================================
// TF32 GEMM (generic): C[M,N] = A[M,K] @ B[K,N]
// =====================================================================
__device__ __forceinline__ uint32_t f2tf32(float f) {
    uint32_t u; asm("cvt.rna.tf32.f32 %0, %1;" : "=r"(u) : "f"(f)); return u;
}

#define LDA 36
#define LDB 136

__global__ __launch_bounds__(256) void gemm_tf32(
    const float* __restrict__ A, const float* __restrict__ B, float* __restrict__ C,
    int M, int K, int N)
{
    __shared__ uint32_t As[128 * LDA];
    __shared__ uint32_t Bs[32 * LDB];
    int t = threadIdx.x;
    int lane = t & 31, w = t >> 5;
    int wm = w & 3, wn = w >> 2;
    int bm = blockIdx.y * 128, bn = blockIdx.x * 128;
    int r = lane >> 2, cq = lane & 3;

    float acc[2][8][4];
    #pragma unroll
    for (int mi = 0; mi < 2; mi++)
        #pragma unroll
        for (int ni = 0; ni < 8; ni++)
            #pragma unroll
            for (int j = 0; j < 4; j++) acc[mi][ni][j] = 0.f;

    for (int k0 = 0; k0 < K; k0 += 32) {
        #pragma unroll
        for (int l = 0; l < 4; l++) {
            int idx = t + l * 256;
            int row = idx >> 3, q = idx & 7;
            float4 v = *reinterpret_cast<const float4*>(A + (size_t)(bm + row) * K + k0 + q * 4);
            uint32_t* p = &As[row * LDA + q * 4];
            p[0] = f2tf32(v.x); p[1] = f2tf32(v.y); p[2] = f2tf32(v.z); p[3] = f2tf32(v.w);
        }
        #pragma unroll
        for (int l = 0; l < 4; l++) {
            int idx = t + l * 256;
            int row = idx >> 5, q = idx & 31;
            float4 v = *reinterpret_cast<const float4*>(B + (size_t)(k0 + row) * N + bn + q * 4);
            uint32_t* p = &Bs[row * LDB + q * 4];
            p[0] = f2tf32(v.x); p[1] = f2tf32(v.y); p[2] = f2tf32(v.z); p[3] = f2tf32(v.w);
        }
        __syncthreads();
        #pragma unroll
        for (int kk = 0; kk < 32; kk += 8) {
            uint32_t a[2][4];
            #pragma unroll
            for (int mi = 0; mi < 2; mi++) {
                int rb = wm * 32 + mi * 16;
                a[mi][0] = As[(rb + r) * LDA + kk + cq];
                a[mi][1] = As[(rb + r + 8) * LDA + kk + cq];
                a[mi][2] = As[(rb + r) * LDA + kk + cq + 4];
                a[mi][3] = As[(rb + r + 8) * LDA + kk + cq + 4];
            }
            #pragma unroll
            for (int ni = 0; ni < 8; ni++) {
                int cb = wn * 64 + ni * 8;
                uint32_t b0 = Bs[(kk + cq) * LDB + cb + r];
                uint32_t b1 = Bs[(kk + 4 + cq) * LDB + cb + r];
                #pragma unroll
                for (int mi = 0; mi < 2; mi++) {
                    asm volatile(
                        "mma.sync.aligned.m16n8k8.row.col.f32.tf32.tf32.f32 "
                        "{%0,%1,%2,%3}, {%4,%5,%6,%7}, {%8,%9}, {%0,%1,%2,%3};"
                        : "+f"(acc[mi][ni][0]), "+f"(acc[mi][ni][1]),
                          "+f"(acc[mi][ni][2]), "+f"(acc[mi][ni][3])
                        : "r"(a[mi][0]), "r"(a[mi][1]), "r"(a[mi][2]), "r"(a[mi][3]),
                          "r"(b0), "r"(b1));
                }
            }
        }
        __syncthreads();
    }
    #pragma unroll
    for (int mi = 0; mi < 2; mi++) {
        int rb = bm + wm * 32 + mi * 16 + r;
        #pragma unroll
        for (int ni = 0; ni < 8; ni++) {
            int cb = bn + wn * 64 + ni * 8 + 2 * cq;
            *reinterpret_cast<float2*>(C + (size_t)rb * N + cb) =
                make_float2(acc[mi][ni][0], acc[mi][ni][1]);
            *reinterpret_cast<float2*>(C + (size_t)(rb + 8) * N + cb) =
                make_float2(acc[mi][ni][2], acc[mi][ni][3]);
        }
    }
}

// =====================================================================
// K1: warp-per-head attention (register att, shfl spread) + z + gf path
// =====================================================================
#define WH8P 260
#define XCP 132

__global__ __launch_bounds__(256) void attn_kernel(
    const float* __restrict__ adj_g,
    const float* __restrict__ g1_ah, const float* __restrict__ gf_ah,
    const float* __restrict__ gf_Wout, const float* __restrict__ gf_aout)
{
    int b = blockIdx.x;
    int t = threadIdx.x;
    int lane = t & 31, w = t >> 5;

    __shared__ float wh8[NA][WH8P];
    __shared__ float xc1[NA][XCP];
    __shared__ float xcf[NA][XCP];
    __shared__ float adj[NA][NA];
    __shared__ float sa[8][64];
    __shared__ float swa[256];
    __shared__ float f1s[NA], f2s[NA];
    __shared__ float att2s[NA][17];
    __shared__ float whf[NA][33];

    {
        const float4* src = reinterpret_cast<const float4*>(g_whall + (size_t)b * 4096);
        #pragma unroll
        for (int l = 0; l < 4; l++) {
            int idx4 = t + l * 256;
            int row = idx4 >> 6, c4 = (idx4 & 63) * 4;
            float4 v = src[idx4];
            wh8[row][c4] = v.x; wh8[row][c4 + 1] = v.y;
            wh8[row][c4 + 2] = v.z; wh8[row][c4 + 3] = v.w;
        }
    }
    adj[t >> 4][t & 15] = adj_g[(size_t)b * 256 + t];
    #pragma unroll
    for (int idx = t; idx < 512; idx += 256) {
        int h = idx >> 6, c = idx & 63;
        sa[h][c] = (h < 4) ? g1_ah[h * 64 + c] : gf_ah[(h - 4) * 64 + c];
    }
    swa[t] = g_wa[t];
    __syncthreads();

    // ---- warp w owns head w ----
    {
        int h = w;
        int d = lane & 15, half = lane >> 4;
        const float* av = &sa[h][half * 32];
        float facc = 0.f;
        #pragma unroll
        for (int c = 0; c < 32; c++) facc = fmaf(wh8[d][h * 32 + c], av[c], facc);
        int j = lane & 15;
        float f2j = __shfl_sync(FULLM, facc, 16 + j);
        float attc[NA];
        float m = -INFINITY;
        #pragma unroll
        for (int i = 0; i < NA; i++) {
            float f1i = __shfl_sync(FULLM, facc, i);
            float e = f1i + f2j;
            e = e > 0.f ? e : ALPHA * e;
            e = (adj[i][j] > 0.f) ? e : NEGV;
            attc[i] = e; m = fmaxf(m, e);
        }
        float s = 0.f;
        #pragma unroll
        for (int i = 0; i < NA; i++) { float x = expf(attc[i] - m); attc[i] = x; s += x; }
        float inv = 1.f / s;
        #pragma unroll
        for (int i = 0; i < NA; i++) attc[i] *= inv;
        int c = lane;
        float whv[NA];
        #pragma unroll
        for (int n = 0; n < NA; n++) whv[n] = wh8[n][h * 32 + c];
        float* dst0 = (h < 4) ? &xc1[0][h * 32 + c] : &xcf[0][(h - 4) * 32 + c];
        #pragma unroll
        for (int i = 0; i < NA; i++) {
            float acc = 0.f;
            #pragma unroll
            for (int n = 0; n < NA; n++) {
                float a_in = __shfl_sync(FULLM, attc[i], n);
                acc = fmaf(a_in, whv[n], acc);
            }
            acc = acc > 0.f ? acc : expm1f(acc);
            dst0[i * XCP] = acc;
        }
    }
    __syncthreads();

    // ---- g1-out scores via wa ----
    #pragma unroll
    for (int rr = 0; rr < 4; rr++) {
        int d = w * 4 + rr;
        int i = d & 15, half = d >> 4;
        const float* wav = &swa[half * 128];
        float acc = 0.f;
        #pragma unroll
        for (int k = lane; k < 128; k += 32) acc = fmaf(xc1[i][k], wav[k], acc);
        #pragma unroll
        for (int o = 16; o; o >>= 1) acc += __shfl_down_sync(FULLM, acc, o);
        if (lane == 0) { if (half) f2s[i] = acc; else f1s[i] = acc; }
    }
    __syncthreads();
    if (t < NA) {
        int j = t;
        float ev[NA]; float m = -INFINITY;
        #pragma unroll
        for (int i = 0; i < NA; i++) {
            float e = f1s[i] + f2s[j];
            e = e > 0.f ? e : ALPHA * e;
            e = (adj[i][j] > 0.f) ? e : NEGV;
            ev[i] = e; m = fmaxf(m, e);
        }
        float s = 0.f;
        #pragma unroll
        for (int i = 0; i < NA; i++) { float x = expf(ev[i] - m); ev[i] = x; s += x; }
        float inv = 1.f / s;
        #pragma unroll
        for (int i = 0; i < NA; i++) att2s[i][j] = ev[i] * inv;
    }
    __syncthreads();

    // ---- z = att2 @ xc1: thread owns fixed column k, xc1 column in regs ----
    {
        int k = t & 127, half = t >> 7;
        float xv[NA];
        #pragma unroll
        for (int n = 0; n < NA; n++) xv[n] = xc1[n][k];
        float* zdst = g_z + (size_t)b * 2048 + k;
        #pragma unroll
        for (int i0 = 0; i0 < 8; i0++) {
            int i = half * 8 + i0;
            float acc = 0.f;
            #pragma unroll
            for (int n = 0; n < NA; n++) acc = fmaf(att2s[i][n], xv[n], acc);
            zdst[i * 128] = acc;
        }
    }

    // ---- whf = xcf @ gf_Wout, 2-row register blocking ----
    {
        int c = t & 31, ig = t >> 5;         // ig 0..7
        float a0 = 0.f, a1 = 0.f;
        #pragma unroll 4
        for (int kk = 0; kk < 128; kk++) {
            float wv = gf_Wout[kk * 32 + c];
            a0 = fmaf(xcf[ig][kk], wv, a0);
            a1 = fmaf(xcf[ig + 8][kk], wv, a1);
        }
        whf[ig][c] = a0; whf[ig + 8][c] = a1;
    }
    __syncthreads();

    // ---- gf attention (single warp, fully register) ----
    if (w == 0) {
        int d = lane & 15, half = lane >> 4;
        const float* av = gf_aout + half * 32;
        float facc = 0.f;
        #pragma unroll
        for (int c = 0; c < 32; c++) facc = fmaf(whf[d][c], av[c], facc);
        int j = lane & 15;
        float f2j = __shfl_sync(FULLM, facc, 16 + j);
        float attc[NA];
        float m = -INFINITY;
        #pragma unroll
        for (int i = 0; i < NA; i++) {
            float f1i = __shfl_sync(FULLM, facc, i);
            float e = f1i + f2j;
            e = e > 0.f ? e : ALPHA * e;
            e = (adj[i][j] > 0.f) ? e : NEGV;
            attc[i] = e; m = fmaxf(m, e);
        }
        float s = 0.f;
        #pragma unroll
        for (int i = 0; i < NA; i++) { float x = expf(attc[i] - m); attc[i] = x; s += x; }
        float inv = 1.f / s;
        #pragma unroll
        for (int i = 0; i < NA; i++) attc[i] *= inv;
        int c = lane;
        float o2[NA];
        float mm = -INFINITY;
        #pragma unroll
        for (int i = 0; i < NA; i++) {
            float acc = 0.f;
            #pragma unroll
            for (int n = 0; n < NA; n++) {
                float a_in = __shfl_sync(FULLM, attc[i], n);
                acc = fmaf(a_in, whf[n][c], acc);
            }
            acc = acc > 0.f ? acc : expm1f(acc);
            o2[i] = acc; mm = fmaxf(mm, acc);
        }
        float ss = 0.f;
        #pragma unroll
        for (int i = 0; i < NA; i++) ss += expf(o2[i] - mm);
        float lse = mm + logf(ss);
        #pragma unroll
        for (int i = 0; i < NA; i++)
            g_wf[(size_t)b * 512 + i * 32 + c] = fabsf(o2[i] - lse);
    }
}

// =====================================================================
// K2: fused GEMM3 + mix. Block = 64 rows (4 batches) x ALL 512 cols.
// 512 threads, warp grid 2x8 (warp tile 32x64). Dynamic smem 128KB.
// Epilogue: elu -> per-column logsoftmax over 16 agents -> abs ->
// qs contraction -> hidden elu -> y, dis, V, q.  No D in global memory.
// =====================================================================
#define LDB3 520

extern __shared__ char g3smem[];

__global__ __launch_bounds__(512, 1) void gemm3_mix_kernel(
    const float* __restrict__ A,              // g_z [131072 x 128]
    const float* __restrict__ Wout,           // [128 x 512]
    const float* __restrict__ agent_qs, const float* __restrict__ states,
    const float* __restrict__ wn_w, const float* __restrict__ wn_b,
    const float* __restrict__ hb_b,
    const float* __restrict__ v1_w, const float* __restrict__ v1_b,
    const float* __restrict__ v2_w, const float* __restrict__ v2_b,
    float* __restrict__ out)
{
    uint32_t* As = reinterpret_cast<uint32_t*>(g3smem);     // 64 x 36
    uint32_t* Bs = As + 64 * LDA;                           // 32 x 520
    float*    Ds = reinterpret_cast<float*>(g3smem);        // 64 x 512 (reuses As/Bs)

    __shared__ float qs_s[4][NA];
    __shared__ float st_s[4][STATE];
    __shared__ float yv_s[4][NA];
    __shared__ float disv[4][NA];
    __shared__ float vpart[4][32];

    int t = threadIdx.x;
    int lane = t & 31, w = t >> 5;          // 16 warps
    int wm = w & 1, wn = w >> 1;            // 2 x 8 warp grid
    int r = lane >> 2, cq = lane & 3;
    int bm = blockIdx.y * 64;               // row block
    int b0 = blockIdx.y * 4;                // first batch of this block

    // small per-batch loads
    if (t < 64) qs_s[t >> 4][t & 15] = agent_qs[(size_t)(b0 + (t >> 4)) * NA + (t & 15)];
    #pragma unroll
    for (int l = 0; l < 2; l++) {
        int idx = t + l * 512;              // 0..1023
        st_s[idx >> 8][idx & 255] = states[(size_t)b0 * 256 + idx];
    }

    float acc[2][8][4];
    #pragma unroll
    for (int mi = 0; mi < 2; mi++)
        #pragma unroll
        for (int ni = 0; ni < 8; ni++)
            #pragma unroll
            for (int j = 0; j < 4; j++) acc[mi][ni][j] = 0.f;

    for (int k0 = 0; k0 < 128; k0 += 32) {
        {   // A tile 64x32 : one float4 per thread
            int row = t >> 3, q = t & 7;
            float4 v = *reinterpret_cast<const float4*>(A + (size_t)(bm + row) * 128 + k0 + q * 4);
            uint32_t* p = &As[row * LDA + q * 4];
            p[0] = f2tf32(v.x); p[1] = f2tf32(v.y); p[2] = f2tf32(v.z); p[3] = f2tf32(v.w);
        }
        #pragma unroll
        for (int l = 0; l < 8; l++) {       // B tile 32x512
            int idx = t + l * 512;
            int row = idx >> 7, q = idx & 127;
            float4 v = *reinterpret_cast<const float4*>(Wout + (size_t)(k0 + row) * 512 + q * 4);
            uint32_t* p = &Bs[row * LDB3 + q * 4];
            p[0] = f2tf32(v.x); p[1] = f2tf32(v.y); p[2] = f2tf32(v.z); p[3] = f2tf32(v.w);
        }
        __syncthreads();
        #pragma unroll
        for (int kk = 0; kk < 32; kk += 8) {
            uint32_t a[2][4];
            #pragma unroll
            for (int mi = 0; mi < 2; mi++) {
                int rb = wm * 32 + mi * 16;
                a[mi][0] = As[(rb + r) * LDA + kk + cq];
                a[mi][1] = As[(rb + r + 8) * LDA + kk + cq];
                a[mi][2] = As[(rb + r) * LDA + kk + cq + 4];
                a[mi][3] = As[(rb + r + 8) * LDA + kk + cq + 4];
            }
            #pragma unroll
            for (int ni = 0; ni < 8; ni++) {
                int cb = wn * 64 + ni * 8;
                uint32_t b0r = Bs[(kk + cq) * LDB3 + cb + r];
                uint32_t b1r = Bs[(kk + 4 + cq) * LDB3 + cb + r];
                #pragma unroll
                for (int mi = 0; mi < 2; mi++) {
                    asm volatile(
                        "mma.sync.aligned.m16n8k8.row.col.f32.tf32.tf32.f32 "
                        "{%0,%1,%2,%3}, {%4,%5,%6,%7}, {%8,%9}, {%0,%1,%2,%3};"
                        : "+f"(acc[mi][ni][0]), "+f"(acc[mi][ni][1]),
                          "+f"(acc[mi][ni][2]), "+f"(acc[mi][ni][3])
                        : "r"(a[mi][0]), "r"(a[mi][1]), "r"(a[mi][2]), "r"(a[mi][3]),
                          "r"(b0r), "r"(b1r));
                }
            }
        }
        __syncthreads();
    }

    // ---- stage elu(D) into Ds (stride 512) ----
    #pragma unroll
    for (int mi = 0; mi < 2; mi++) {
        int row0 = wm * 32 + mi * 16 + r;
        #pragma unroll
        for (int ni = 0; ni < 8; ni++) {
            int col = wn * 64 + ni * 8 + 2 * cq;
            float v0 = acc[mi][ni][0], v1 = acc[mi][ni][1];
            float v2 = acc[mi][ni][2], v3 = acc[mi][ni][3];
            v0 = v0 > 0.f ? v0 : expm1f(v0);
            v1 = v1 > 0.f ? v1 : expm1f(v1);
            v2 = v2 > 0.f ? v2 : expm1f(v2);
            v3 = v3 > 0.f ? v3 : expm1f(v3);
            *reinterpret_cast<float2*>(&Ds[row0 * 512 + col]) = make_float2(v0, v1);
            *reinterpret_cast<float2*>(&Ds[(row0 + 8) * 512 + col]) = make_float2(v2, v3);
        }
    }
    __syncthreads();

    // ---- per-column logsoftmax over 16 agents + abs, in place ----
    #pragma unroll
    for (int p = 0; p < 4; p++) {
        int tt = t + p * 512;               // 0..2047
        int bl = tt >> 9, c = tt & 511;
        float* col = Ds + (bl * 16) * 512 + c;
        float v[NA]; float m = -INFINITY;
        #pragma unroll
        for (int i = 0; i < NA; i++) { v[i] = col[i * 512]; m = fmaxf(m, v[i]); }
        float s = 0.f;
        #pragma unroll
        for (int i = 0; i < NA; i++) s += expf(v[i] - m);
        float lse = m + logf(s);
        #pragma unroll
        for (int i = 0; i < NA; i++) col[i * 512] = fabsf(v[i] - lse);
    }
    __syncthreads();

    // ---- hidden + y : warp w handles agent i=w&15 across 4 batches ----
    {
        int e = lane & 31, i = w;           // 16 warps = 16 agents, lane = e
        #pragma unroll
        for (int bl = 0; bl < 4; bl++) {
            int b = b0 + bl;
            float p = g_ball[(size_t)b * 512 + i * 32 + e] + hb_b[i * 32 + e];
            const float* row = Ds + (bl * 16 + i) * 512;
            #pragma unroll
            for (int n = 0; n < NA; n++)
                p = fmaf(qs_s[bl][n], row[n * 32 + e], p);
            p = p > 0.f ? p : expm1f(p);
            float prod = p * g_wf[(size_t)b * 512 + i * 32 + e];
            #pragma unroll
            for (int o = 16; o; o >>= 1) prod += __shfl_down_sync(FULLM, prod, o);
            if (lane == 0) yv_s[bl][i] = prod;
        }
    }

    // ---- dis + V : warp w -> (batch w>>2, quarter w&3) ----
    {
        int bl = w >> 2, qt = w & 3;
        #pragma unroll
        for (int rr = 0; rr < 4; rr++) {
            int n = qt * 4 + rr;
            float acc2 = 0.f;
            #pragma unroll
            for (int s_ = lane; s_ < 256; s_ += 32)
                acc2 = fmaf(st_s[bl][s_], wn_w[n * 256 + s_], acc2);
            #pragma unroll
            for (int o = 16; o; o >>= 1) acc2 += __shfl_down_sync(FULLM, acc2, o);
            if (lane == 0) disv[bl][n] = fabsf(acc2 + wn_b[n]);
        }
        #pragma unroll
        for (int rr = 0; rr < 8; rr++) {
            int n = qt * 8 + rr;
            float acc2 = 0.f;
            #pragma unroll
            for (int s_ = lane; s_ < 256; s_ += 32)
                acc2 = fmaf(st_s[bl][s_], v1_w[n * 256 + s_], acc2);
            #pragma unroll
            for (int o = 16; o; o >>= 1) acc2 += __shfl_down_sync(FULLM, acc2, o);
            if (lane == 0) vpart[bl][n] = fmaxf(acc2 + v1_b[n], 0.f);
        }
    }
    __syncthreads();

    if (t < 4) {
        int bl = t;
        float v = v2_b[0];
        #pragma unroll
        for (int h = 0; h < 32; h++) v = fmaf(vpart[bl][h], v2_w[h], v);
        float q = v;
        #pragma unroll
        for (int n = 0; n < NA; n++) q = fmaf(yv_s[bl][n], disv[bl][n], q);
        out[b0 + bl] = q;
    }
}

// =====================================================================
extern "C" void kernel_launch(void* const* d_in, const int* in_sizes, int n_in,
                              void* d_out, int out_size)
{
    const float* agent_qs = (const float*)d_in[0];
    const float* states   = (const float*)d_in[1];
    const float* obs_ls   = (const float*)d_in[2];
    const float* adj_ls   = (const float*)d_in[3];
    const float* wn_w     = (const float*)d_in[4];
    const float* wn_b     = (const float*)d_in[5];
    const float* g1_Wh    = (const float*)d_in[6];
    const float* g1_ah    = (const float*)d_in[7];
    const float* g1_Wout  = (const float*)d_in[8];
    const float* g1_aout  = (const float*)d_in[9];
    const float* gf_Wh    = (const float*)d_in[10];
    const float* gf_ah    = (const float*)d_in[11];
    const float* gf_Wout  = (const float*)d_in[12];
    const float* gf_aout  = (const float*)d_in[13];
    const float* hb_W     = (const float*)d_in[14];
    const float* hb_b     = (const float*)d_in[15];
    const float* v1_w     = (const float*)d_in[16];
    const float* v1_b     = (const float*)d_in[17];
    const float* v2_w     = (const float*)d_in[18];
    const float* v2_b     = (const float*)d_in[19];
    float* out = (float*)d_out;

    float *p_whall, *p_z, *p_ball, *p_Bheads, *p_BhbT;
    cudaGetSymbolAddress((void**)&p_whall,  g_whall);
    cudaGetSymbolAddress((void**)&p_z,      g_z);
    cudaGetSymbolAddress((void**)&p_ball,   g_ball);
    cudaGetSymbolAddress((void**)&p_Bheads, g_Bheads);
    cudaGetSymbolAddress((void**)&p_BhbT,   g_BhbT);

    const int G3_SMEM = 64 * 512 * 4;     // 128 KB dynamic
    cudaFuncSetAttribute(gemm3_mix_kernel,
                         cudaFuncAttributeMaxDynamicSharedMemorySize, G3_SMEM);

    pack_kernel<<<64, 256>>>(g1_Wh, gf_Wh, g1_Wout, g1_aout, hb_W);

    // Whall = obs(131072x128) @ Bheads(128x256)
    gemm_tf32<<<dim3(2, 1024), 256>>>(obs_ls, p_Bheads, p_whall, BTOT * NA, 128, 256);

    // b_all = states(8192x256) @ hb_W^T(256x512)
    gemm_tf32<<<dim3(4, 64), 256>>>(states, p_BhbT, p_ball, BTOT, 256, 512);

    attn_kernel<<<BTOT, 256>>>(adj_ls, g1_ah, gf_ah, gf_Wout, gf_aout);

    // fused: D = Z @ Wout -> elu -> logsoftmax -> abs -> mix -> q
    gemm3_mix_kernel<<<dim3(1, 2048), 512, G3_SMEM>>>(
        p_z, g1_Wout, agent_qs, states, wn_w, wn_b, hb_b,
        v1_w, v1_b, v2_w, v2_b, out);
}

// round 8
// speedup vs baseline: 2.7973x; 1.0934x over previous
#include <cuda_runtime.h>
#include <math.h>
#include <stdint.h>

#define NA 16
#define OBSF 128
#define STATE 256
#define EMBED 32
#define NHID 32
#define BTOT 8192
#define ALPHA 0.2f
#define NEGV -9.0e15f
#define FULLM 0xffffffffu

// ---------------- scratch (device globals) ----------------
__device__ float g_whall[(size_t)BTOT * NA * 256];   // 128 MB  obs@Wh8 (all heads)
__device__ float g_z[(size_t)BTOT * NA * 128];       // 64 MB   att2@xcat1
__device__ float g_ball[(size_t)BTOT * 512];         // 16 MB   b_all pre-bias
__device__ float g_wf[(size_t)BTOT * 512];           // 16 MB   |logsoftmax(gf out)|
__device__ float g_Bheads[128 * 256];                // packed head weights
__device__ float g_BhbT[256 * 512];                  // hb_W transposed
__device__ float g_wa[256];                          // wa1 (128) | wa2 (128)

__device__ __forceinline__ uint32_t f2tf32(float f) {
    uint32_t u; asm("cvt.rna.tf32.f32 %0, %1;" : "=r"(u) : "f"(f)); return u;
}

__device__ __forceinline__ void mma_16n8k8(float* c,
    uint32_t a0, uint32_t a1, uint32_t a2, uint32_t a3,
    uint32_t b0, uint32_t b1)
{
    asm volatile(
        "mma.sync.aligned.m16n8k8.row.col.f32.tf32.tf32.f32 "
        "{%0,%1,%2,%3}, {%4,%5,%6,%7}, {%8,%9}, {%0,%1,%2,%3};"
        : "+f"(c[0]), "+f"(c[1]), "+f"(c[2]), "+f"(c[3])
        : "r"(a0), "r"(a1), "r"(a2), "r"(a3), "r"(b0), "r"(b1));
}

__device__ __forceinline__ float elu1(float v) {
    return v > 0.f ? v : expm1f(v);
}

// =====================================================================
// K0: pack weights + wa vectors
// =====================================================================
__global__ void pack_kernel(const float* __restrict__ g1_Wh, const float* __restrict__ gf_Wh,
                            const float* __restrict__ g1_Wout, const float* __restrict__ g1_aout,
                            const float* __restrict__ hb_W)
{
    int t = threadIdx.x, bid = blockIdx.x;
    int gid = bid * 256 + t;
    for (int idx = gid; idx < 128 * 256; idx += 64 * 256) {
        int k = idx >> 8, c = idx & 255;
        float v = (c < 128) ? g1_Wh[(c >> 5) * 4096 + k * 32 + (c & 31)]
                            : gf_Wh[((c - 128) >> 5) * 4096 + k * 32 + (c & 31)];
        g_Bheads[idx] = v;
    }
    for (int idx = gid; idx < 256 * 512; idx += 64 * 256) {
        int k = idx >> 9, n = idx & 511;
        g_BhbT[idx] = hb_W[n * 256 + k];
    }
    if (bid == 0) {
        int k = t & 127, half = t >> 7;
        const float* ap = g1_aout + half * 512;
        float acc = 0.f;
        for (int c = 0; c < 512; c++) acc = fmaf(g1_Wout[k * 512 + c], ap[c], acc);
        g_wa[half * 128 + k] = acc;
    }
}

// =====================================================================
// TF32 GEMM (generic): C[M,N] = A[M,K] @ B[K,N]
// =====================================================================
#define LDA 36
#define LDB 136

__global__ __launch_bounds__(256) void gemm_tf32(
    const float* __restrict__ A, const float* __restrict__ B, float* __restrict__ C,
    int M, int K, int N)
{
    __shared__ uint32_t As[128 * LDA];
    __shared__ uint32_t Bs[32 * LDB];
    int t = threadIdx.x;
    int lane = t & 31, w = t >> 5;
    int wm = w & 3, wn = w >> 2;
    int bm = blockIdx.y * 128, bn = blockIdx.x * 128;
    int r = lane >> 2, cq = lane & 3;

    float acc[2][8][4];
    #pragma unroll
    for (int mi = 0; mi < 2; mi++)
        #pragma unroll
        for (int ni = 0; ni < 8; ni++)
            #pragma unroll
            for (int j = 0; j < 4; j++) acc[mi][ni][j] = 0.f;

    for (int k0 = 0; k0 < K; k0 += 32) {
        #pragma unroll
        for (int l = 0; l < 4; l++) {
            int idx = t + l * 256;
            int row = idx >> 3, q = idx & 7;
            float4 v = *reinterpret_cast<const float4*>(A + (size_t)(bm + row) * K + k0 + q * 4);
            uint32_t* p = &As[row * LDA + q * 4];
            p[0] = f2tf32(v.x); p[1] = f2tf32(v.y); p[2] = f2tf32(v.z); p[3] = f2tf32(v.w);
        }
        #pragma unroll
        for (int l = 0; l < 4; l++) {
            int idx = t + l * 256;
            int row = idx >> 5, q = idx & 31;
            float4 v = *reinterpret_cast<const float4*>(B + (size_t)(k0 + row) * N + bn + q * 4);
            uint32_t* p = &Bs[row * LDB + q * 4];
            p[0] = f2tf32(v.x); p[1] = f2tf32(v.y); p[2] = f2tf32(v.z); p[3] = f2tf32(v.w);
        }
        __syncthreads();
        #pragma unroll
        for (int kk = 0; kk < 32; kk += 8) {
            uint32_t a[2][4];
            #pragma unroll
            for (int mi = 0; mi < 2; mi++) {
                int rb = wm * 32 + mi * 16;
                a[mi][0] = As[(rb + r) * LDA + kk + cq];
                a[mi][1] = As[(rb + r + 8) * LDA + kk + cq];
                a[mi][2] = As[(rb + r) * LDA + kk + cq + 4];
                a[mi][3] = As[(rb + r + 8) * LDA + kk + cq + 4];
            }
            #pragma unroll
            for (int ni = 0; ni < 8; ni++) {
                int cb = wn * 64 + ni * 8;
                uint32_t b0 = Bs[(kk + cq) * LDB + cb + r];
                uint32_t b1 = Bs[(kk + 4 + cq) * LDB + cb + r];
                #pragma unroll
                for (int mi = 0; mi < 2; mi++)
                    mma_16n8k8(acc[mi][ni], a[mi][0], a[mi][1], a[mi][2], a[mi][3], b0, b1);
            }
        }
        __syncthreads();
    }
    #pragma unroll
    for (int mi = 0; mi < 2; mi++) {
        int rb = bm + wm * 32 + mi * 16 + r;
        #pragma unroll
        for (int ni = 0; ni < 8; ni++) {
            int cb = bn + wn * 64 + ni * 8 + 2 * cq;
            *reinterpret_cast<float2*>(C + (size_t)rb * N + cb) =
                make_float2(acc[mi][ni][0], acc[mi][ni][1]);
            *reinterpret_cast<float2*>(C + (size_t)(rb + 8) * N + cb) =
                make_float2(acc[mi][ni][2], acc[mi][ni][3]);
        }
    }
}

// =====================================================================
// K1: attention — tensor-core products for head-out, z, whf.
// smem = 48,704 B.
// =====================================================================
#define WH8P 260
#define XCP 132
#define WHFP 34

__global__ __launch_bounds__(256) void attn_kernel(
    const float* __restrict__ adj_g,
    const float* __restrict__ g1_ah, const float* __restrict__ gf_ah,
    const float* __restrict__ gf_Wout, const float* __restrict__ gf_aout)
{
    int b = blockIdx.x;
    int t = threadIdx.x;
    int lane = t & 31, w = t >> 5;
    int r = lane >> 2, cq = lane & 3;

    __shared__ float wh8[NA][WH8P];      // 16640
    __shared__ float xc1[NA][XCP];       //  8448
    __shared__ float xcf[NA][XCP];       //  8448
    __shared__ float att_w[8][NA][17];   //  8704
    __shared__ float adj[NA][NA];        //  1024
    __shared__ float sa[8][64];          //  2048
    __shared__ float f1s[NA], f2s[NA];   //   128
    __shared__ float att2s[NA][17];      //  1088
    __shared__ float whf[NA][WHFP];      //  2176

    // ---- loads ----
    {
        const float4* src = reinterpret_cast<const float4*>(g_whall + (size_t)b * 4096);
        #pragma unroll
        for (int l = 0; l < 4; l++) {
            int idx4 = t + l * 256;
            int row = idx4 >> 6, c4 = (idx4 & 63) * 4;
            float4 v = src[idx4];
            wh8[row][c4] = v.x; wh8[row][c4 + 1] = v.y;
            wh8[row][c4 + 2] = v.z; wh8[row][c4 + 3] = v.w;
        }
    }
    adj[t >> 4][t & 15] = adj_g[(size_t)b * 256 + t];
    #pragma unroll
    for (int idx = t; idx < 512; idx += 256) {
        int h = idx >> 6, c = idx & 63;
        sa[h][c] = (h < 4) ? g1_ah[h * 64 + c] : gf_ah[(h - 4) * 64 + c];
    }
    __syncthreads();

    // ---- warp w = head w: scores + softmax (scalar), out via MMA ----
    {
        int h = w;
        int d = lane & 15, half = lane >> 4;
        const float* av = &sa[h][half * 32];
        float facc = 0.f;
        #pragma unroll
        for (int c = 0; c < 32; c++) facc = fmaf(wh8[d][h * 32 + c], av[c], facc);
        int j = lane & 15;
        float f2j = __shfl_sync(FULLM, facc, 16 + j);
        float attc[NA];
        float m = -INFINITY;
        #pragma unroll
        for (int i = 0; i < NA; i++) {
            float f1i = __shfl_sync(FULLM, facc, i);
            float e = f1i + f2j;
            e = e > 0.f ? e : ALPHA * e;
            e = (adj[i][j] > 0.f) ? e : NEGV;
            attc[i] = e; m = fmaxf(m, e);
        }
        float s = 0.f;
        #pragma unroll
        for (int i = 0; i < NA; i++) { float x = expf(attc[i] - m); attc[i] = x; s += x; }
        float inv = 1.f / s;
        if (lane < 16) {
            #pragma unroll
            for (int i = 0; i < NA; i++) att_w[h][i][j] = attc[i] * inv;
        }
        __syncwarp();

        // out(16x32) = att(16x16) @ wh8[:, h*32:h*32+32]
        float acc[4][4];
        #pragma unroll
        for (int nt = 0; nt < 4; nt++)
            #pragma unroll
            for (int q = 0; q < 4; q++) acc[nt][q] = 0.f;
        #pragma unroll
        for (int ks = 0; ks < 2; ks++) {
            int kk = ks * 8;
            uint32_t a0 = f2tf32(att_w[h][r][kk + cq]);
            uint32_t a1 = f2tf32(att_w[h][r + 8][kk + cq]);
            uint32_t a2 = f2tf32(att_w[h][r][kk + cq + 4]);
            uint32_t a3 = f2tf32(att_w[h][r + 8][kk + cq + 4]);
            #pragma unroll
            for (int nt = 0; nt < 4; nt++) {
                int cb = nt * 8;
                uint32_t b0 = f2tf32(wh8[kk + cq][h * 32 + cb + r]);
                uint32_t b1 = f2tf32(wh8[kk + 4 + cq][h * 32 + cb + r]);
                mma_16n8k8(acc[nt], a0, a1, a2, a3, b0, b1);
            }
        }
        // epilogue: elu, store to xc1/xcf
        float* base = (h < 4) ? &xc1[0][h * 32] : &xcf[0][(h - 4) * 32];
        #pragma unroll
        for (int nt = 0; nt < 4; nt++) {
            int col = nt * 8 + 2 * cq;
            *reinterpret_cast<float2*>(base + r * XCP + col) =
                make_float2(elu1(acc[nt][0]), elu1(acc[nt][1]));
            *reinterpret_cast<float2*>(base + (r + 8) * XCP + col) =
                make_float2(elu1(acc[nt][2]), elu1(acc[nt][3]));
        }
    }
    __syncthreads();

    // ---- g1-out scores: f = xc1 @ wa  (wa via LDG) ----
    #pragma unroll
    for (int rr = 0; rr < 4; rr++) {
        int d = w * 4 + rr;
        int i = d & 15, half = d >> 4;
        const float* wav = g_wa + half * 128;
        float acc = 0.f;
        #pragma unroll
        for (int k = lane; k < 128; k += 32) acc = fmaf(xc1[i][k], wav[k], acc);
        #pragma unroll
        for (int o = 16; o; o >>= 1) acc += __shfl_down_sync(FULLM, acc, o);
        if (lane == 0) { if (half) f2s[i] = acc; else f1s[i] = acc; }
    }
    __syncthreads();
    if (t < NA) {
        int j = t;
        float ev[NA]; float m = -INFINITY;
        #pragma unroll
        for (int i = 0; i < NA; i++) {
            float e = f1s[i] + f2s[j];
            e = e > 0.f ? e : ALPHA * e;
            e = (adj[i][j] > 0.f) ? e : NEGV;
            ev[i] = e; m = fmaxf(m, e);
        }
        float s = 0.f;
        #pragma unroll
        for (int i = 0; i < NA; i++) { float x = expf(ev[i] - m); ev[i] = x; s += x; }
        float inv = 1.f / s;
        #pragma unroll
        for (int i = 0; i < NA; i++) att2s[i][j] = ev[i] * inv;
    }
    __syncthreads();

    // ---- z(16x128) = att2(16x16) @ xc1(16x128): warp w -> cols [16w,16w+16) ----
    {
        float acc[2][4];
        #pragma unroll
        for (int nt = 0; nt < 2; nt++)
            #pragma unroll
            for (int q = 0; q < 4; q++) acc[nt][q] = 0.f;
        #pragma unroll
        for (int ks = 0; ks < 2; ks++) {
            int kk = ks * 8;
            uint32_t a0 = f2tf32(att2s[r][kk + cq]);
            uint32_t a1 = f2tf32(att2s[r + 8][kk + cq]);
            uint32_t a2 = f2tf32(att2s[r][kk + cq + 4]);
            uint32_t a3 = f2tf32(att2s[r + 8][kk + cq + 4]);
            #pragma unroll
            for (int nt = 0; nt < 2; nt++) {
                int cb = w * 16 + nt * 8;
                uint32_t b0 = f2tf32(xc1[kk + cq][cb + r]);
                uint32_t b1 = f2tf32(xc1[kk + 4 + cq][cb + r]);
                mma_16n8k8(acc[nt], a0, a1, a2, a3, b0, b1);
            }
        }
        float* zdst = g_z + (size_t)b * 2048;
        #pragma unroll
        for (int nt = 0; nt < 2; nt++) {
            int col = w * 16 + nt * 8 + 2 * cq;
            *reinterpret_cast<float2*>(zdst + r * 128 + col) =
                make_float2(acc[nt][0], acc[nt][1]);
            *reinterpret_cast<float2*>(zdst + (r + 8) * 128 + col) =
                make_float2(acc[nt][2], acc[nt][3]);
        }
    }

    // ---- whf(16x32) = xcf(16x128) @ gf_Wout(128x32): warps 0-3, nt = w ----
    if (w < 4) {
        int cb = w * 8;
        float acc[4] = {0.f, 0.f, 0.f, 0.f};
        #pragma unroll
        for (int ks = 0; ks < 16; ks++) {
            int kk = ks * 8;
            uint32_t a0 = f2tf32(xcf[r][kk + cq]);
            uint32_t a1 = f2tf32(xcf[r + 8][kk + cq]);
            uint32_t a2 = f2tf32(xcf[r][kk + cq + 4]);
            uint32_t a3 = f2tf32(xcf[r + 8][kk + cq + 4]);
            uint32_t b0 = f2tf32(gf_Wout[(kk + cq) * 32 + cb + r]);
            uint32_t b1 = f2tf32(gf_Wout[(kk + 4 + cq) * 32 + cb + r]);
            mma_16n8k8(acc, a0, a1, a2, a3, b0, b1);
        }
        int col = cb + 2 * cq;
        *reinterpret_cast<float2*>(&whf[r][col]) = make_float2(acc[0], acc[1]);
        *reinterpret_cast<float2*>(&whf[r + 8][col]) = make_float2(acc[2], acc[3]);
    }
    __syncthreads();

    // ---- gf attention finish (single warp, registers) ----
    if (w == 0) {
        int d = lane & 15, half = lane >> 4;
        const float* av = gf_aout + half * 32;
        float facc = 0.f;
        #pragma unroll
        for (int c = 0; c < 32; c++) facc = fmaf(whf[d][c], av[c], facc);
        int j = lane & 15;
        float f2j = __shfl_sync(FULLM, facc, 16 + j);
        float attc[NA];
        float m = -INFINITY;
        #pragma unroll
        for (int i = 0; i < NA; i++) {
            float f1i = __shfl_sync(FULLM, facc, i);
            float e = f1i + f2j;
            e = e > 0.f ? e : ALPHA * e;
            e = (adj[i][j] > 0.f) ? e : NEGV;
            attc[i] = e; m = fmaxf(m, e);
        }
        float s = 0.f;
        #pragma unroll
        for (int i = 0; i < NA; i++) { float x = expf(attc[i] - m); attc[i] = x; s += x; }
        float inv = 1.f / s;
        #pragma unroll
        for (int i = 0; i < NA; i++) attc[i] *= inv;
        int c = lane;
        float o2[NA];
        float mm = -INFINITY;
        #pragma unroll
        for (int i = 0; i < NA; i++) {
            float acc = 0.f;
            #pragma unroll
            for (int n = 0; n < NA; n++) {
                float a_in = __shfl_sync(FULLM, attc[i], n);
                acc = fmaf(a_in, whf[n][c], acc);
            }
            acc = elu1(acc);
            o2[i] = acc; mm = fmaxf(mm, acc);
        }
        float ss = 0.f;
        #pragma unroll
        for (int i = 0; i < NA; i++) ss += expf(o2[i] - mm);
        float lse = mm + logf(ss);
        #pragma unroll
        for (int i = 0; i < NA; i++)
            g_wf[(size_t)b * 512 + i * 32 + c] = fabsf(o2[i] - lse);
    }
}

// =====================================================================
// K2: fused GEMM3 + mix (unchanged from R7)
// =====================================================================
#define LDB3 520

extern __shared__ char g3smem[];

__global__ __launch_bounds__(512, 1) void gemm3_mix_kernel(
    const float* __restrict__ A,              // g_z [131072 x 128]
    const float* __restrict__ Wout,           // [128 x 512]
    const float* __restrict__ agent_qs, const float* __restrict__ states,
    const float* __restrict__ wn_w, const float* __restrict__ wn_b,
    const float* __restrict__ hb_b,
    const float* __restrict__ v1_w, const float* __restrict__ v1_b,
    const float* __restrict__ v2_w, const float* __restrict__ v2_b,
    float* __restrict__ out)
{
    uint32_t* As = reinterpret_cast<uint32_t*>(g3smem);
    uint32_t* Bs = As + 64 * LDA;
    float*    Ds = reinterpret_cast<float*>(g3smem);

    __shared__ float qs_s[4][NA];
    __shared__ float st_s[4][STATE];
    __shared__ float yv_s[4][NA];
    __shared__ float disv[4][NA];
    __shared__ float vpart[4][32];

    int t = threadIdx.x;
    int lane = t & 31, w = t >> 5;
    int wm = w & 1, wn = w >> 1;
    int r = lane >> 2, cq = lane & 3;
    int bm = blockIdx.y * 64;
    int b0 = blockIdx.y * 4;

    if (t < 64) qs_s[t >> 4][t & 15] = agent_qs[(size_t)(b0 + (t >> 4)) * NA + (t & 15)];
    #pragma unroll
    for (int l = 0; l < 2; l++) {
        int idx = t + l * 512;
        st_s[idx >> 8][idx & 255] = states[(size_t)b0 * 256 + idx];
    }

    float acc[2][8][4];
    #pragma unroll
    for (int mi = 0; mi < 2; mi++)
        #pragma unroll
        for (int ni = 0; ni < 8; ni++)
            #pragma unroll
            for (int j = 0; j < 4; j++) acc[mi][ni][j] = 0.f;

    for (int k0 = 0; k0 < 128; k0 += 32) {
        {
            int row = t >> 3, q = t & 7;
            float4 v = *reinterpret_cast<const float4*>(A + (size_t)(bm + row) * 128 + k0 + q * 4);
            uint32_t* p = &As[row * LDA + q * 4];
            p[0] = f2tf32(v.x); p[1] = f2tf32(v.y); p[2] = f2tf32(v.z); p[3] = f2tf32(v.w);
        }
        #pragma unroll
        for (int l = 0; l < 8; l++) {
            int idx = t + l * 512;
            int row = idx >> 7, q = idx & 127;
            float4 v = *reinterpret_cast<const float4*>(Wout + (size_t)(k0 + row) * 512 + q * 4);
            uint32_t* p = &Bs[row * LDB3 + q * 4];
            p[0] = f2tf32(v.x); p[1] = f2tf32(v.y); p[2] = f2tf32(v.z); p[3] = f2tf32(v.w);
        }
        __syncthreads();
        #pragma unroll
        for (int kk = 0; kk < 32; kk += 8) {
            uint32_t a[2][4];
            #pragma unroll
            for (int mi = 0; mi < 2; mi++) {
                int rb = wm * 32 + mi * 16;
                a[mi][0] = As[(rb + r) * LDA + kk + cq];
                a[mi][1] = As[(rb + r + 8) * LDA + kk + cq];
                a[mi][2] = As[(rb + r) * LDA + kk + cq + 4];
                a[mi][3] = As[(rb + r + 8) * LDA + kk + cq + 4];
            }
            #pragma unroll
            for (int ni = 0; ni < 8; ni++) {
                int cb = wn * 64 + ni * 8;
                uint32_t b0r = Bs[(kk + cq) * LDB3 + cb + r];
                uint32_t b1r = Bs[(kk + 4 + cq) * LDB3 + cb + r];
                #pragma unroll
                for (int mi = 0; mi < 2; mi++)
                    mma_16n8k8(acc[mi][ni], a[mi][0], a[mi][1], a[mi][2], a[mi][3], b0r, b1r);
            }
        }
        __syncthreads();
    }

    #pragma unroll
    for (int mi = 0; mi < 2; mi++) {
        int row0 = wm * 32 + mi * 16 + r;
        #pragma unroll
        for (int ni = 0; ni < 8; ni++) {
            int col = wn * 64 + ni * 8 + 2 * cq;
            *reinterpret_cast<float2*>(&Ds[row0 * 512 + col]) =
                make_float2(elu1(acc[mi][ni][0]), elu1(acc[mi][ni][1]));
            *reinterpret_cast<float2*>(&Ds[(row0 + 8) * 512 + col]) =
                make_float2(elu1(acc[mi][ni][2]), elu1(acc[mi][ni][3]));
        }
    }
    __syncthreads();

    #pragma unroll
    for (int p = 0; p < 4; p++) {
        int tt = t + p * 512;
        int bl = tt >> 9, c = tt & 511;
        float* col = Ds + (bl * 16) * 512 + c;
        float v[NA]; float m = -INFINITY;
        #pragma unroll
        for (int i = 0; i < NA; i++) { v[i] = col[i * 512]; m = fmaxf(m, v[i]); }
        float s = 0.f;
        #pragma unroll
        for (int i = 0; i < NA; i++) s += expf(v[i] - m);
        float lse = m + logf(s);
        #pragma unroll
        for (int i = 0; i < NA; i++) col[i * 512] = fabsf(v[i] - lse);
    }
    __syncthreads();

    {
        int e = lane & 31, i = w;
        #pragma unroll
        for (int bl = 0; bl < 4; bl++) {
            int b = b0 + bl;
            float p = g_ball[(size_t)b * 512 + i * 32 + e] + hb_b[i * 32 + e];
            const float* row = Ds + (bl * 16 + i) * 512;
            #pragma unroll
            for (int n = 0; n < NA; n++)
                p = fmaf(qs_s[bl][n], row[n * 32 + e], p);
            p = elu1(p);
            float prod = p * g_wf[(size_t)b * 512 + i * 32 + e];
            #pragma unroll
            for (int o = 16; o; o >>= 1) prod += __shfl_down_sync(FULLM, prod, o);
            if (lane == 0) yv_s[bl][i] = prod;
        }
    }

    {
        int bl = w >> 2, qt = w & 3;
        #pragma unroll
        for (int rr = 0; rr < 4; rr++) {
            int n = qt * 4 + rr;
            float acc2 = 0.f;
            #pragma unroll
            for (int s_ = lane; s_ < 256; s_ += 32)
                acc2 = fmaf(st_s[bl][s_], wn_w[n * 256 + s_], acc2);
            #pragma unroll
            for (int o = 16; o; o >>= 1) acc2 += __shfl_down_sync(FULLM, acc2, o);
            if (lane == 0) disv[bl][n] = fabsf(acc2 + wn_b[n]);
        }
        #pragma unroll
        for (int rr = 0; rr < 8; rr++) {
            int n = qt * 8 + rr;
            float acc2 = 0.f;
            #pragma unroll
            for (int s_ = lane; s_ < 256; s_ += 32)
                acc2 = fmaf(st_s[bl][s_], v1_w[n * 256 + s_], acc2);
            #pragma unroll
            for (int o = 16; o; o >>= 1) acc2 += __shfl_down_sync(FULLM, acc2, o);
            if (lane == 0) vpart[bl][n] = fmaxf(acc2 + v1_b[n], 0.f);
        }
    }
    __syncthreads();

    if (t < 4) {
        int bl = t;
        float v = v2_b[0];
        #pragma unroll
        for (int h = 0; h < 32; h++) v = fmaf(vpart[bl][h], v2_w[h], v);
        float q = v;
        #pragma unroll
        for (int n = 0; n < NA; n++) q = fmaf(yv_s[bl][n], disv[bl][n], q);
        out[b0 + bl] = q;
    }
}

// =====================================================================
extern "C" void kernel_launch(void* const* d_in, const int* in_sizes, int n_in,
                              void* d_out, int out_size)
{
    const float* agent_qs = (const float*)d_in[0];
    const float* states   = (const float*)d_in[1];
    const float* obs_ls   = (const float*)d_in[2];
    const float* adj_ls   = (const float*)d_in[3];
    const float* wn_w     = (const float*)d_in[4];
    const float* wn_b     = (const float*)d_in[5];
    const float* g1_Wh    = (const float*)d_in[6];
    const float* g1_ah    = (const float*)d_in[7];
    const float* g1_Wout  = (const float*)d_in[8];
    const float* g1_aout  = (const float*)d_in[9];
    const float* gf_Wh    = (const float*)d_in[10];
    const float* gf_ah    = (const float*)d_in[11];
    const float* gf_Wout  = (const float*)d_in[12];
    const float* gf_aout  = (const float*)d_in[13];
    const float* hb_W     = (const float*)d_in[14];
    const float* hb_b     = (const float*)d_in[15];
    const float* v1_w     = (const float*)d_in[16];
    const float* v1_b     = (const float*)d_in[17];
    const float* v2_w     = (const float*)d_in[18];
    const float* v2_b     = (const float*)d_in[19];
    float* out = (float*)d_out;

    float *p_whall, *p_z, *p_ball, *p_Bheads, *p_BhbT;
    cudaGetSymbolAddress((void**)&p_whall,  g_whall);
    cudaGetSymbolAddress((void**)&p_z,      g_z);
    cudaGetSymbolAddress((void**)&p_ball,   g_ball);
    cudaGetSymbolAddress((void**)&p_Bheads, g_Bheads);
    cudaGetSymbolAddress((void**)&p_BhbT,   g_BhbT);

    const int G3_SMEM = 64 * 512 * 4;     // 128 KB dynamic
    cudaFuncSetAttribute(gemm3_mix_kernel,
                         cudaFuncAttributeMaxDynamicSharedMemorySize, G3_SMEM);

    pack_kernel<<<64, 256>>>(g1_Wh, gf_Wh, g1_Wout, g1_aout, hb_W);

    // Whall = obs(131072x128) @ Bheads(128x256)
    gemm_tf32<<<dim3(2, 1024), 256>>>(obs_ls, p_Bheads, p_whall, BTOT * NA, 128, 256);

    // b_all = states(8192x256) @ hb_W^T(256x512)
    gemm_tf32<<<dim3(4, 64), 256>>>(states, p_BhbT, p_ball, BTOT, 256, 512);

    attn_kernel<<<BTOT, 256>>>(adj_ls, g1_ah, gf_ah, gf_Wout, gf_aout);

    // fused: D = Z @ Wout -> elu -> logsoftmax -> abs -> mix -> q
    gemm3_mix_kernel<<<dim3(1, 2048), 512, G3_SMEM>>>(
        p_z, g1_Wout, agent_qs, states, wn_w, wn_b, hb_b,
        v1_w, v1_b, v2_w, v2_b, out);
}

// round 9
// speedup vs baseline: 2.8042x; 1.0025x over previous
#include <cuda_runtime.h>
#include <math.h>
#include <stdint.h>

#define NA 16
#define OBSF 128
#define STATE 256
#define EMBED 32
#define NHID 32
#define BTOT 8192
#define ALPHA 0.2f
#define NEGV -9.0e15f
#define FULLM 0xffffffffu

// ---------------- scratch (device globals) ----------------
__device__ float g_whall[(size_t)BTOT * NA * 256];   // 128 MB  obs@Wh8 (tf32 bits)
__device__ float g_z[(size_t)BTOT * NA * 128];       // 64 MB   att2@xcat1 (tf32 bits)
__device__ float g_ball[(size_t)BTOT * 512];         // 16 MB   b_all pre-bias
__device__ float g_wf[(size_t)BTOT * 512];           // 16 MB   |logsoftmax(gf out)|
__device__ float g_Bheads[128 * 256];                // packed head weights (tf32 bits)
__device__ float g_BhbT[256 * 512];                  // hb_W transposed (tf32 bits)
__device__ float g_Wout32[128 * 512];                // g1_Wout (tf32 bits)
__device__ float g_gfW32[128 * 32];                  // gf_Wout (tf32 bits)
__device__ float g_wa[256];                          // wa1 (128) | wa2 (128), fp32

__device__ __forceinline__ uint32_t f2tf32(float f) {
    uint32_t u; asm("cvt.rna.tf32.f32 %0, %1;" : "=r"(u) : "f"(f)); return u;
}
__device__ __forceinline__ float tf32f(float f) { return __uint_as_float(f2tf32(f)); }

__device__ __forceinline__ void mma_16n8k8(float* c,
    uint32_t a0, uint32_t a1, uint32_t a2, uint32_t a3,
    uint32_t b0, uint32_t b1)
{
    asm volatile(
        "mma.sync.aligned.m16n8k8.row.col.f32.tf32.tf32.f32 "
        "{%0,%1,%2,%3}, {%4,%5,%6,%7}, {%8,%9}, {%0,%1,%2,%3};"
        : "+f"(c[0]), "+f"(c[1]), "+f"(c[2]), "+f"(c[3])
        : "r"(a0), "r"(a1), "r"(a2), "r"(a3), "r"(b0), "r"(b1));
}

__device__ __forceinline__ float elu1(float v) {
    return v > 0.f ? v : expm1f(v);
}

// =====================================================================
// K0: pack weights (tf32-converted) + wa vectors
// =====================================================================
__global__ void pack_kernel(const float* __restrict__ g1_Wh, const float* __restrict__ gf_Wh,
                            const float* __restrict__ g1_Wout, const float* __restrict__ g1_aout,
                            const float* __restrict__ gf_Wout, const float* __restrict__ hb_W)
{
    int t = threadIdx.x, bid = blockIdx.x;
    int gid = bid * 256 + t;
    for (int idx = gid; idx < 128 * 256; idx += 64 * 256) {
        int k = idx >> 8, c = idx & 255;
        float v = (c < 128) ? g1_Wh[(c >> 5) * 4096 + k * 32 + (c & 31)]
                            : gf_Wh[((c - 128) >> 5) * 4096 + k * 32 + (c & 31)];
        g_Bheads[idx] = tf32f(v);
    }
    for (int idx = gid; idx < 256 * 512; idx += 64 * 256) {
        int k = idx >> 9, n = idx & 511;
        g_BhbT[idx] = tf32f(hb_W[n * 256 + k]);
    }
    for (int idx = gid; idx < 128 * 512; idx += 64 * 256)
        g_Wout32[idx] = tf32f(g1_Wout[idx]);
    for (int idx = gid; idx < 128 * 32; idx += 64 * 256)
        g_gfW32[idx] = tf32f(gf_Wout[idx]);
    if (bid == 0) {
        int k = t & 127, half = t >> 7;
        const float* ap = g1_aout + half * 512;
        float acc = 0.f;
        for (int c = 0; c < 512; c++) acc = fmaf(g1_Wout[k * 512 + c], ap[c], acc);
        g_wa[half * 128 + k] = acc;
    }
}

// =====================================================================
// TF32 GEMM: C = A @ B. A raw fp32 (converted on stage); B PRE-CONVERTED.
// =====================================================================
#define LDA 36
#define LDB 136

__global__ __launch_bounds__(256) void gemm_tf32(
    const float* __restrict__ A, const float* __restrict__ B, float* __restrict__ C,
    int M, int K, int N, int conv_out)
{
    __shared__ uint32_t As[128 * LDA];
    __shared__ uint32_t Bs[32 * LDB];
    int t = threadIdx.x;
    int lane = t & 31, w = t >> 5;
    int wm = w & 3, wn = w >> 2;
    int bm = blockIdx.y * 128, bn = blockIdx.x * 128;
    int r = lane >> 2, cq = lane & 3;

    float acc[2][8][4];
    #pragma unroll
    for (int mi = 0; mi < 2; mi++)
        #pragma unroll
        for (int ni = 0; ni < 8; ni++)
            #pragma unroll
            for (int j = 0; j < 4; j++) acc[mi][ni][j] = 0.f;

    for (int k0 = 0; k0 < K; k0 += 32) {
        #pragma unroll
        for (int l = 0; l < 4; l++) {
            int idx = t + l * 256;
            int row = idx >> 3, q = idx & 7;
            float4 v = *reinterpret_cast<const float4*>(A + (size_t)(bm + row) * K + k0 + q * 4);
            uint32_t* p = &As[row * LDA + q * 4];
            p[0] = f2tf32(v.x); p[1] = f2tf32(v.y); p[2] = f2tf32(v.z); p[3] = f2tf32(v.w);
        }
        #pragma unroll
        for (int l = 0; l < 4; l++) {
            int idx = t + l * 256;
            int row = idx >> 5, q = idx & 31;
            uint4 v = *reinterpret_cast<const uint4*>(B + (size_t)(k0 + row) * N + bn + q * 4);
            uint32_t* p = &Bs[row * LDB + q * 4];
            p[0] = v.x; p[1] = v.y; p[2] = v.z; p[3] = v.w;
        }
        __syncthreads();
        #pragma unroll
        for (int kk = 0; kk < 32; kk += 8) {
            uint32_t a[2][4];
            #pragma unroll
            for (int mi = 0; mi < 2; mi++) {
                int rb = wm * 32 + mi * 16;
                a[mi][0] = As[(rb + r) * LDA + kk + cq];
                a[mi][1] = As[(rb + r + 8) * LDA + kk + cq];
                a[mi][2] = As[(rb + r) * LDA + kk + cq + 4];
                a[mi][3] = As[(rb + r + 8) * LDA + kk + cq + 4];
            }
            #pragma unroll
            for (int ni = 0; ni < 8; ni++) {
                int cb = wn * 64 + ni * 8;
                uint32_t b0 = Bs[(kk + cq) * LDB + cb + r];
                uint32_t b1 = Bs[(kk + 4 + cq) * LDB + cb + r];
                #pragma unroll
                for (int mi = 0; mi < 2; mi++)
                    mma_16n8k8(acc[mi][ni], a[mi][0], a[mi][1], a[mi][2], a[mi][3], b0, b1);
            }
        }
        __syncthreads();
    }
    #pragma unroll
    for (int mi = 0; mi < 2; mi++) {
        int rb = bm + wm * 32 + mi * 16 + r;
        #pragma unroll
        for (int ni = 0; ni < 8; ni++) {
            int cb = bn + wn * 64 + ni * 8 + 2 * cq;
            if (conv_out) {   // write tf32-rounded (for whall consumed as MMA operands later)
                *reinterpret_cast<float2*>(C + (size_t)rb * N + cb) =
                    make_float2(tf32f(acc[mi][ni][0]), tf32f(acc[mi][ni][1]));
                *reinterpret_cast<float2*>(C + (size_t)(rb + 8) * N + cb) =
                    make_float2(tf32f(acc[mi][ni][2]), tf32f(acc[mi][ni][3]));
            } else {
                *reinterpret_cast<float2*>(C + (size_t)rb * N + cb) =
                    make_float2(acc[mi][ni][0], acc[mi][ni][1]);
                *reinterpret_cast<float2*>(C + (size_t)(rb + 8) * N + cb) =
                    make_float2(acc[mi][ni][2], acc[mi][ni][3]);
            }
        }
    }
}

// =====================================================================
// K1: attention — all staged operands already tf32; no CVT in MMA loops.
// =====================================================================
#define WH8P 260
#define XCP 132
#define WHFP 34

__global__ __launch_bounds__(256) void attn_kernel(
    const float* __restrict__ adj_g,
    const float* __restrict__ g1_ah, const float* __restrict__ gf_ah,
    const float* __restrict__ gf_aout)
{
    int b = blockIdx.x;
    int t = threadIdx.x;
    int lane = t & 31, w = t >> 5;
    int r = lane >> 2, cq = lane & 3;

    __shared__ float wh8[NA][WH8P];      // tf32 bits (valid floats)
    __shared__ float xc1[NA][XCP];       // tf32 bits
    __shared__ float xcf[NA][XCP];       // tf32 bits
    __shared__ float att_w[8][NA][17];   // tf32 bits
    __shared__ float adj[NA][NA];
    __shared__ float sa[8][64];
    __shared__ float f1s[NA], f2s[NA];
    __shared__ float att2s[NA][17];      // tf32 bits
    __shared__ float whf[NA][WHFP];      // fp32

    {
        const float4* src = reinterpret_cast<const float4*>(g_whall + (size_t)b * 4096);
        #pragma unroll
        for (int l = 0; l < 4; l++) {
            int idx4 = t + l * 256;
            int row = idx4 >> 6, c4 = (idx4 & 63) * 4;
            float4 v = src[idx4];   // already tf32 bits (conv_out=1 in gemm1)
            wh8[row][c4] = v.x; wh8[row][c4 + 1] = v.y;
            wh8[row][c4 + 2] = v.z; wh8[row][c4 + 3] = v.w;
        }
    }
    adj[t >> 4][t & 15] = adj_g[(size_t)b * 256 + t];
    #pragma unroll
    for (int idx = t; idx < 512; idx += 256) {
        int h = idx >> 6, c = idx & 63;
        sa[h][c] = (h < 4) ? g1_ah[h * 64 + c] : gf_ah[(h - 4) * 64 + c];
    }
    __syncthreads();

    // ---- warp w = head w ----
    {
        int h = w;
        int d = lane & 15, half = lane >> 4;
        const float* av = &sa[h][half * 32];
        float facc = 0.f;
        #pragma unroll
        for (int c = 0; c < 32; c++) facc = fmaf(wh8[d][h * 32 + c], av[c], facc);
        int j = lane & 15;
        float f2j = __shfl_sync(FULLM, facc, 16 + j);
        float attc[NA];
        float m = -INFINITY;
        #pragma unroll
        for (int i = 0; i < NA; i++) {
            float f1i = __shfl_sync(FULLM, facc, i);
            float e = f1i + f2j;
            e = e > 0.f ? e : ALPHA * e;
            e = (adj[i][j] > 0.f) ? e : NEGV;
            attc[i] = e; m = fmaxf(m, e);
        }
        float s = 0.f;
        #pragma unroll
        for (int i = 0; i < NA; i++) { float x = expf(attc[i] - m); attc[i] = x; s += x; }
        float inv = 1.f / s;
        if (lane < 16) {
            #pragma unroll
            for (int i = 0; i < NA; i++) att_w[h][i][j] = tf32f(attc[i] * inv);
        }
        __syncwarp();

        float acc[4][4];
        #pragma unroll
        for (int nt = 0; nt < 4; nt++)
            #pragma unroll
            for (int q = 0; q < 4; q++) acc[nt][q] = 0.f;
        #pragma unroll
        for (int ks = 0; ks < 2; ks++) {
            int kk = ks * 8;
            uint32_t a0 = __float_as_uint(att_w[h][r][kk + cq]);
            uint32_t a1 = __float_as_uint(att_w[h][r + 8][kk + cq]);
            uint32_t a2 = __float_as_uint(att_w[h][r][kk + cq + 4]);
            uint32_t a3 = __float_as_uint(att_w[h][r + 8][kk + cq + 4]);
            #pragma unroll
            for (int nt = 0; nt < 4; nt++) {
                int cb = nt * 8;
                uint32_t b0 = __float_as_uint(wh8[kk + cq][h * 32 + cb + r]);
                uint32_t b1 = __float_as_uint(wh8[kk + 4 + cq][h * 32 + cb + r]);
                mma_16n8k8(acc[nt], a0, a1, a2, a3, b0, b1);
            }
        }
        float* base = (h < 4) ? &xc1[0][h * 32] : &xcf[0][(h - 4) * 32];
        #pragma unroll
        for (int nt = 0; nt < 4; nt++) {
            int col = nt * 8 + 2 * cq;
            *reinterpret_cast<float2*>(base + r * XCP + col) =
                make_float2(tf32f(elu1(acc[nt][0])), tf32f(elu1(acc[nt][1])));
            *reinterpret_cast<float2*>(base + (r + 8) * XCP + col) =
                make_float2(tf32f(elu1(acc[nt][2])), tf32f(elu1(acc[nt][3])));
        }
    }
    __syncthreads();

    // ---- g1-out scores: f = xc1 @ wa ----
    #pragma unroll
    for (int rr = 0; rr < 4; rr++) {
        int d = w * 4 + rr;
        int i = d & 15, half = d >> 4;
        const float* wav = g_wa + half * 128;
        float acc = 0.f;
        #pragma unroll
        for (int k = lane; k < 128; k += 32) acc = fmaf(xc1[i][k], wav[k], acc);
        #pragma unroll
        for (int o = 16; o; o >>= 1) acc += __shfl_down_sync(FULLM, acc, o);
        if (lane == 0) { if (half) f2s[i] = acc; else f1s[i] = acc; }
    }
    __syncthreads();
    if (t < NA) {
        int j = t;
        float ev[NA]; float m = -INFINITY;
        #pragma unroll
        for (int i = 0; i < NA; i++) {
            float e = f1s[i] + f2s[j];
            e = e > 0.f ? e : ALPHA * e;
            e = (adj[i][j] > 0.f) ? e : NEGV;
            ev[i] = e; m = fmaxf(m, e);
        }
        float s = 0.f;
        #pragma unroll
        for (int i = 0; i < NA; i++) { float x = expf(ev[i] - m); ev[i] = x; s += x; }
        float inv = 1.f / s;
        #pragma unroll
        for (int i = 0; i < NA; i++) att2s[i][j] = tf32f(ev[i] * inv);
    }
    __syncthreads();

    // ---- z = att2 @ xc1, write tf32 bits ----
    {
        float acc[2][4];
        #pragma unroll
        for (int nt = 0; nt < 2; nt++)
            #pragma unroll
            for (int q = 0; q < 4; q++) acc[nt][q] = 0.f;
        #pragma unroll
        for (int ks = 0; ks < 2; ks++) {
            int kk = ks * 8;
            uint32_t a0 = __float_as_uint(att2s[r][kk + cq]);
            uint32_t a1 = __float_as_uint(att2s[r + 8][kk + cq]);
            uint32_t a2 = __float_as_uint(att2s[r][kk + cq + 4]);
            uint32_t a3 = __float_as_uint(att2s[r + 8][kk + cq + 4]);
            #pragma unroll
            for (int nt = 0; nt < 2; nt++) {
                int cb = w * 16 + nt * 8;
                uint32_t b0 = __float_as_uint(xc1[kk + cq][cb + r]);
                uint32_t b1 = __float_as_uint(xc1[kk + 4 + cq][cb + r]);
                mma_16n8k8(acc[nt], a0, a1, a2, a3, b0, b1);
            }
        }
        float* zdst = g_z + (size_t)b * 2048;
        #pragma unroll
        for (int nt = 0; nt < 2; nt++) {
            int col = w * 16 + nt * 8 + 2 * cq;
            *reinterpret_cast<float2*>(zdst + r * 128 + col) =
                make_float2(tf32f(acc[nt][0]), tf32f(acc[nt][1]));
            *reinterpret_cast<float2*>(zdst + (r + 8) * 128 + col) =
                make_float2(tf32f(acc[nt][2]), tf32f(acc[nt][3]));
        }
    }

    // ---- whf = xcf @ gf_Wout (pre-converted) ----
    if (w < 4) {
        int cb = w * 8;
        float acc[4] = {0.f, 0.f, 0.f, 0.f};
        #pragma unroll
        for (int ks = 0; ks < 16; ks++) {
            int kk = ks * 8;
            uint32_t a0 = __float_as_uint(xcf[r][kk + cq]);
            uint32_t a1 = __float_as_uint(xcf[r + 8][kk + cq]);
            uint32_t a2 = __float_as_uint(xcf[r][kk + cq + 4]);
            uint32_t a3 = __float_as_uint(xcf[r + 8][kk + cq + 4]);
            uint32_t b0 = __float_as_uint(g_gfW32[(kk + cq) * 32 + cb + r]);
            uint32_t b1 = __float_as_uint(g_gfW32[(kk + 4 + cq) * 32 + cb + r]);
            mma_16n8k8(acc, a0, a1, a2, a3, b0, b1);
        }
        int col = cb + 2 * cq;
        *reinterpret_cast<float2*>(&whf[r][col]) = make_float2(acc[0], acc[1]);
        *reinterpret_cast<float2*>(&whf[r + 8][col]) = make_float2(acc[2], acc[3]);
    }
    __syncthreads();

    // ---- gf attention finish (single warp) ----
    if (w == 0) {
        int d = lane & 15, half = lane >> 4;
        const float* av = gf_aout + half * 32;
        float facc = 0.f;
        #pragma unroll
        for (int c = 0; c < 32; c++) facc = fmaf(whf[d][c], av[c], facc);
        int j = lane & 15;
        float f2j = __shfl_sync(FULLM, facc, 16 + j);
        float attc[NA];
        float m = -INFINITY;
        #pragma unroll
        for (int i = 0; i < NA; i++) {
            float f1i = __shfl_sync(FULLM, facc, i);
            float e = f1i + f2j;
            e = e > 0.f ? e : ALPHA * e;
            e = (adj[i][j] > 0.f) ? e : NEGV;
            attc[i] = e; m = fmaxf(m, e);
        }
        float s = 0.f;
        #pragma unroll
        for (int i = 0; i < NA; i++) { float x = expf(attc[i] - m); attc[i] = x; s += x; }
        float inv = 1.f / s;
        #pragma unroll
        for (int i = 0; i < NA; i++) attc[i] *= inv;
        int c = lane;
        float o2[NA];
        float mm = -INFINITY;
        #pragma unroll
        for (int i = 0; i < NA; i++) {
            float acc = 0.f;
            #pragma unroll
            for (int n = 0; n < NA; n++) {
                float a_in = __shfl_sync(FULLM, attc[i], n);
                acc = fmaf(a_in, whf[n][c], acc);
            }
            acc = elu1(acc);
            o2[i] = acc; mm = fmaxf(mm, acc);
        }
        float ss = 0.f;
        #pragma unroll
        for (int i = 0; i < NA; i++) ss += expf(o2[i] - mm);
        float lse = mm + logf(ss);
        #pragma unroll
        for (int i = 0; i < NA; i++)
            g_wf[(size_t)b * 512 + i * 32 + c] = fabsf(o2[i] - lse);
    }
}

// =====================================================================
// K2: fused GEMM3 + mix. Block = 32 rows (2 batches) x 512 cols.
// 256 threads, 8 warps (warp tile 32x64). Dynamic smem ~71KB -> 2 CTA/SM.
// =====================================================================
#define LDB3 520

extern __shared__ char g3smem[];

__global__ __launch_bounds__(256, 2) void gemm3_mix_kernel(
    const float* __restrict__ A,              // g_z tf32 bits [131072 x 128]
    const float* __restrict__ Wout,           // g_Wout32 tf32 bits [128 x 512]
    const float* __restrict__ agent_qs, const float* __restrict__ states,
    const float* __restrict__ wn_w, const float* __restrict__ wn_b,
    const float* __restrict__ hb_b,
    const float* __restrict__ v1_w, const float* __restrict__ v1_b,
    const float* __restrict__ v2_w, const float* __restrict__ v2_b,
    float* __restrict__ out)
{
    uint32_t* As = reinterpret_cast<uint32_t*>(g3smem);     // 32 x 36
    uint32_t* Bs = As + 32 * LDA;                           // 32 x 520
    float*    Ds = reinterpret_cast<float*>(g3smem);        // 32 x 512 (reuse)

    __shared__ float qs_s[2][NA];
    __shared__ float st_s[2][STATE];
    __shared__ float yv_s[2][NA];
    __shared__ float disv[2][NA];
    __shared__ float vpart[2][32];

    int t = threadIdx.x;
    int lane = t & 31, w = t >> 5;          // 8 warps
    int r = lane >> 2, cq = lane & 3;
    int bm = blockIdx.y * 32;
    int b0 = blockIdx.y * 2;

    if (t < 32) qs_s[t >> 4][t & 15] = agent_qs[(size_t)b0 * NA + t];
    #pragma unroll
    for (int l = 0; l < 2; l++) {
        int idx = t + l * 256;              // 0..511
        st_s[idx >> 8][idx & 255] = states[(size_t)b0 * 256 + idx];
    }

    float acc[2][8][4];
    #pragma unroll
    for (int mi = 0; mi < 2; mi++)
        #pragma unroll
        for (int ni = 0; ni < 8; ni++)
            #pragma unroll
            for (int j = 0; j < 4; j++) acc[mi][ni][j] = 0.f;

    for (int k0 = 0; k0 < 128; k0 += 32) {
        {   // A tile 32x32: one uint4 per thread (pre-converted)
            int row = t >> 3, q = t & 7;
            uint4 v = *reinterpret_cast<const uint4*>(A + (size_t)(bm + row) * 128 + k0 + q * 4);
            uint32_t* p = &As[row * LDA + q * 4];
            p[0] = v.x; p[1] = v.y; p[2] = v.z; p[3] = v.w;
        }
        #pragma unroll
        for (int l = 0; l < 16; l++) {      // B tile 32x512 (pre-converted)
            int idx = t + l * 256;
            int row = idx >> 7, q = idx & 127;
            uint4 v = *reinterpret_cast<const uint4*>(Wout + (size_t)(k0 + row) * 512 + q * 4);
            uint32_t* p = &Bs[row * LDB3 + q * 4];
            p[0] = v.x; p[1] = v.y; p[2] = v.z; p[3] = v.w;
        }
        __syncthreads();
        #pragma unroll
        for (int kk = 0; kk < 32; kk += 8) {
            uint32_t a[2][4];
            #pragma unroll
            for (int mi = 0; mi < 2; mi++) {
                int rb = mi * 16;
                a[mi][0] = As[(rb + r) * LDA + kk + cq];
                a[mi][1] = As[(rb + r + 8) * LDA + kk + cq];
                a[mi][2] = As[(rb + r) * LDA + kk + cq + 4];
                a[mi][3] = As[(rb + r + 8) * LDA + kk + cq + 4];
            }
            #pragma unroll
            for (int ni = 0; ni < 8; ni++) {
                int cb = w * 64 + ni * 8;
                uint32_t b0r = Bs[(kk + cq) * LDB3 + cb + r];
                uint32_t b1r = Bs[(kk + 4 + cq) * LDB3 + cb + r];
                #pragma unroll
                for (int mi = 0; mi < 2; mi++)
                    mma_16n8k8(acc[mi][ni], a[mi][0], a[mi][1], a[mi][2], a[mi][3], b0r, b1r);
            }
        }
        __syncthreads();
    }

    // ---- stage elu(D) into Ds ----
    #pragma unroll
    for (int mi = 0; mi < 2; mi++) {
        int row0 = mi * 16 + r;
        #pragma unroll
        for (int ni = 0; ni < 8; ni++) {
            int col = w * 64 + ni * 8 + 2 * cq;
            *reinterpret_cast<float2*>(&Ds[row0 * 512 + col]) =
                make_float2(elu1(acc[mi][ni][0]), elu1(acc[mi][ni][1]));
            *reinterpret_cast<float2*>(&Ds[(row0 + 8) * 512 + col]) =
                make_float2(elu1(acc[mi][ni][2]), elu1(acc[mi][ni][3]));
        }
    }
    __syncthreads();

    // ---- per-column logsoftmax over 16 agents + abs, in place ----
    #pragma unroll
    for (int p = 0; p < 4; p++) {
        int tt = t + p * 256;               // 0..1023 = 2 batches x 512 cols
        int bl = tt >> 9, c = tt & 511;
        float* col = Ds + (bl * 16) * 512 + c;
        float v[NA]; float m = -INFINITY;
        #pragma unroll
        for (int i = 0; i < NA; i++) { v[i] = col[i * 512]; m = fmaxf(m, v[i]); }
        float s = 0.f;
        #pragma unroll
        for (int i = 0; i < NA; i++) s += expf(v[i] - m);
        float lse = m + logf(s);
        #pragma unroll
        for (int i = 0; i < NA; i++) col[i * 512] = fabsf(v[i] - lse);
    }
    __syncthreads();

    // ---- hidden + y: warp w -> agents {w, w+8}, both batches ----
    {
        int e = lane;
        #pragma unroll
        for (int ai = 0; ai < 2; ai++) {
            int i = w + ai * 8;
            #pragma unroll
            for (int bl = 0; bl < 2; bl++) {
                int b = b0 + bl;
                float p = g_ball[(size_t)b * 512 + i * 32 + e] + hb_b[i * 32 + e];
                const float* row = Ds + (bl * 16 + i) * 512;
                #pragma unroll
                for (int n = 0; n < NA; n++)
                    p = fmaf(qs_s[bl][n], row[n * 32 + e], p);
                p = elu1(p);
                float prod = p * g_wf[(size_t)b * 512 + i * 32 + e];
                #pragma unroll
                for (int o = 16; o; o >>= 1) prod += __shfl_down_sync(FULLM, prod, o);
                if (lane == 0) yv_s[bl][i] = prod;
            }
        }
    }

    // ---- dis + V: warp w -> (batch w>>2, quarter w&3) ----
    {
        int bl = w >> 2, qt = w & 3;
        #pragma unroll
        for (int rr = 0; rr < 4; rr++) {
            int n = qt * 4 + rr;
            float acc2 = 0.f;
            #pragma unroll
            for (int s_ = lane; s_ < 256; s_ += 32)
                acc2 = fmaf(st_s[bl][s_], wn_w[n * 256 + s_], acc2);
            #pragma unroll
            for (int o = 16; o; o >>= 1) acc2 += __shfl_down_sync(FULLM, acc2, o);
            if (lane == 0) disv[bl][n] = fabsf(acc2 + wn_b[n]);
        }
        #pragma unroll
        for (int rr = 0; rr < 8; rr++) {
            int n = qt * 8 + rr;
            float acc2 = 0.f;
            #pragma unroll
            for (int s_ = lane; s_ < 256; s_ += 32)
                acc2 = fmaf(st_s[bl][s_], v1_w[n * 256 + s_], acc2);
            #pragma unroll
            for (int o = 16; o; o >>= 1) acc2 += __shfl_down_sync(FULLM, acc2, o);
            if (lane == 0) vpart[bl][n] = fmaxf(acc2 + v1_b[n], 0.f);
        }
    }
    __syncthreads();

    if (t < 2) {
        int bl = t;
        float v = v2_b[0];
        #pragma unroll
        for (int h = 0; h < 32; h++) v = fmaf(vpart[bl][h], v2_w[h], v);
        float q = v;
        #pragma unroll
        for (int n = 0; n < NA; n++) q = fmaf(yv_s[bl][n], disv[bl][n], q);
        out[b0 + bl] = q;
    }
}

// =====================================================================
extern "C" void kernel_launch(void* const* d_in, const int* in_sizes, int n_in,
                              void* d_out, int out_size)
{
    const float* agent_qs = (const float*)d_in[0];
    const float* states   = (const float*)d_in[1];
    const float* obs_ls   = (const float*)d_in[2];
    const float* adj_ls   = (const float*)d_in[3];
    const float* wn_w     = (const float*)d_in[4];
    const float* wn_b     = (const float*)d_in[5];
    const float* g1_Wh    = (const float*)d_in[6];
    const float* g1_ah    = (const float*)d_in[7];
    const float* g1_Wout  = (const float*)d_in[8];
    const float* g1_aout  = (const float*)d_in[9];
    const float* gf_Wh    = (const float*)d_in[10];
    const float* gf_ah    = (const float*)d_in[11];
    const float* gf_Wout  = (const float*)d_in[12];
    const float* gf_aout  = (const float*)d_in[13];
    const float* hb_W     = (const float*)d_in[14];
    const float* hb_b     = (const float*)d_in[15];
    const float* v1_w     = (const float*)d_in[16];
    const float* v1_b     = (const float*)d_in[17];
    const float* v2_w     = (const float*)d_in[18];
    const float* v2_b     = (const float*)d_in[19];
    float* out = (float*)d_out;

    float *p_whall, *p_z, *p_ball, *p_Bheads, *p_BhbT, *p_Wout32;
    cudaGetSymbolAddress((void**)&p_whall,  g_whall);
    cudaGetSymbolAddress((void**)&p_z,      g_z);
    cudaGetSymbolAddress((void**)&p_ball,   g_ball);
    cudaGetSymbolAddress((void**)&p_Bheads, g_Bheads);
    cudaGetSymbolAddress((void**)&p_BhbT,   g_BhbT);
    cudaGetSymbolAddress((void**)&p_Wout32, g_Wout32);

    const int G3_SMEM = 32 * LDA * 4 + 32 * LDB3 * 4;   // 71,168 B
    cudaFuncSetAttribute(gemm3_mix_kernel,
                         cudaFuncAttributeMaxDynamicSharedMemorySize, G3_SMEM);

    pack_kernel<<<64, 256>>>(g1_Wh, gf_Wh, g1_Wout, g1_aout, gf_Wout, hb_W);

    // Whall = obs(131072x128) @ Bheads(128x256) -> tf32-rounded out
    gemm_tf32<<<dim3(2, 1024), 256>>>(obs_ls, p_Bheads, p_whall, BTOT * NA, 128, 256, 1);

    // b_all = states(8192x256) @ hb_W^T(256x512) -> fp32 out
    gemm_tf32<<<dim3(4, 64), 256>>>(states, p_BhbT, p_ball, BTOT, 256, 512, 0);

    attn_kernel<<<BTOT, 256>>>(adj_ls, g1_ah, gf_ah, gf_aout);

    // fused: D = Z @ Wout -> elu -> logsoftmax -> abs -> mix -> q
    gemm3_mix_kernel<<<dim3(1, 4096), 256, G3_SMEM>>>(
        p_z, p_Wout32, agent_qs, states, wn_w, wn_b, hb_b,
        v1_w, v1_b, v2_w, v2_b, out);
}

// round 10
// speedup vs baseline: 2.9440x; 1.0499x over previous
#include <cuda_runtime.h>
#include <math.h>
#include <stdint.h>

#define NA 16
#define OBSF 128
#define STATE 256
#define EMBED 32
#define NHID 32
#define BTOT 8192
#define ALPHA 0.2f
#define NEGV -9.0e15f
#define FULLM 0xffffffffu

// ---------------- scratch (device globals) ----------------
__device__ float g_z[(size_t)BTOT * NA * 128];       // 64 MB   att2@xcat1 (tf32 bits)
__device__ float g_ball[(size_t)BTOT * 512];         // 16 MB   b_all pre-bias
__device__ float g_wf[(size_t)BTOT * 512];           // 16 MB   |logsoftmax(gf out)|
__device__ float g_Bheads[128 * 256];                // packed head weights (tf32 bits)
__device__ float g_BhbT[256 * 512];                  // hb_W transposed (tf32 bits)
__device__ float g_Wout32[128 * 512];                // g1_Wout (tf32 bits)
__device__ float g_gfW32[128 * 32];                  // gf_Wout (tf32 bits)
__device__ float g_wa[256];                          // wa1 (128) | wa2 (128), fp32

__device__ __forceinline__ uint32_t f2tf32(float f) {
    uint32_t u; asm("cvt.rna.tf32.f32 %0, %1;" : "=r"(u) : "f"(f)); return u;
}
__device__ __forceinline__ float tf32f(float f) { return __uint_as_float(f2tf32(f)); }

__device__ __forceinline__ void mma_16n8k8(float* c,
    uint32_t a0, uint32_t a1, uint32_t a2, uint32_t a3,
    uint32_t b0, uint32_t b1)
{
    asm volatile(
        "mma.sync.aligned.m16n8k8.row.col.f32.tf32.tf32.f32 "
        "{%0,%1,%2,%3}, {%4,%5,%6,%7}, {%8,%9}, {%0,%1,%2,%3};"
        : "+f"(c[0]), "+f"(c[1]), "+f"(c[2]), "+f"(c[3])
        : "r"(a0), "r"(a1), "r"(a2), "r"(a3), "r"(b0), "r"(b1));
}

__device__ __forceinline__ float elu1(float v) {
    return v > 0.f ? v : expm1f(v);
}

// =====================================================================
// K0: pack weights (tf32-converted) + wa vectors
// =====================================================================
__global__ void pack_kernel(const float* __restrict__ g1_Wh, const float* __restrict__ gf_Wh,
                            const float* __restrict__ g1_Wout, const float* __restrict__ g1_aout,
                            const float* __restrict__ gf_Wout, const float* __restrict__ hb_W)
{
    int t = threadIdx.x, bid = blockIdx.x;
    int gid = bid * 256 + t;
    for (int idx = gid; idx < 128 * 256; idx += 64 * 256) {
        int k = idx >> 8, c = idx & 255;
        float v = (c < 128) ? g1_Wh[(c >> 5) * 4096 + k * 32 + (c & 31)]
                            : gf_Wh[((c - 128) >> 5) * 4096 + k * 32 + (c & 31)];
        g_Bheads[idx] = tf32f(v);
    }
    for (int idx = gid; idx < 256 * 512; idx += 64 * 256) {
        int k = idx >> 9, n = idx & 511;
        g_BhbT[idx] = tf32f(hb_W[n * 256 + k]);
    }
    for (int idx = gid; idx < 128 * 512; idx += 64 * 256)
        g_Wout32[idx] = tf32f(g1_Wout[idx]);
    for (int idx = gid; idx < 128 * 32; idx += 64 * 256)
        g_gfW32[idx] = tf32f(gf_Wout[idx]);
    if (bid == 0) {
        // wa = Wout @ aout halves: warp-per-row, coalesced
        int wp = t >> 5, ln = t & 31;
        for (int d = wp; d < 256; d += 8) {
            int k = d & 127, half = d >> 7;
            const float* ap = g1_aout + half * 512;
            const float* wr = g1_Wout + (size_t)k * 512;
            float acc = 0.f;
            for (int c = ln; c < 512; c += 32) acc = fmaf(wr[c], ap[c], acc);
            #pragma unroll
            for (int o = 16; o; o >>= 1) acc += __shfl_down_sync(FULLM, acc, o);
            if (ln == 0) g_wa[half * 128 + k] = acc;
        }
    }
}

// =====================================================================
// TF32 GEMM (used for b_all only): C = A @ B, B PRE-CONVERTED.
// =====================================================================
#define LDA 36
#define LDB 136

__global__ __launch_bounds__(256) void gemm_tf32(
    const float* __restrict__ A, const float* __restrict__ B, float* __restrict__ C,
    int M, int K, int N)
{
    __shared__ uint32_t As[128 * LDA];
    __shared__ uint32_t Bs[32 * LDB];
    int t = threadIdx.x;
    int lane = t & 31, w = t >> 5;
    int wm = w & 3, wn = w >> 2;
    int bm = blockIdx.y * 128, bn = blockIdx.x * 128;
    int r = lane >> 2, cq = lane & 3;

    float acc[2][8][4];
    #pragma unroll
    for (int mi = 0; mi < 2; mi++)
        #pragma unroll
        for (int ni = 0; ni < 8; ni++)
            #pragma unroll
            for (int j = 0; j < 4; j++) acc[mi][ni][j] = 0.f;

    for (int k0 = 0; k0 < K; k0 += 32) {
        #pragma unroll
        for (int l = 0; l < 4; l++) {
            int idx = t + l * 256;
            int row = idx >> 3, q = idx & 7;
            float4 v = *reinterpret_cast<const float4*>(A + (size_t)(bm + row) * K + k0 + q * 4);
            uint32_t* p = &As[row * LDA + q * 4];
            p[0] = f2tf32(v.x); p[1] = f2tf32(v.y); p[2] = f2tf32(v.z); p[3] = f2tf32(v.w);
        }
        #pragma unroll
        for (int l = 0; l < 4; l++) {
            int idx = t + l * 256;
            int row = idx >> 5, q = idx & 31;
            uint4 v = *reinterpret_cast<const uint4*>(B + (size_t)(k0 + row) * N + bn + q * 4);
            uint32_t* p = &Bs[row * LDB + q * 4];
            p[0] = v.x; p[1] = v.y; p[2] = v.z; p[3] = v.w;
        }
        __syncthreads();
        #pragma unroll
        for (int kk = 0; kk < 32; kk += 8) {
            uint32_t a[2][4];
            #pragma unroll
            for (int mi = 0; mi < 2; mi++) {
                int rb = wm * 32 + mi * 16;
                a[mi][0] = As[(rb + r) * LDA + kk + cq];
                a[mi][1] = As[(rb + r + 8) * LDA + kk + cq];
                a[mi][2] = As[(rb + r) * LDA + kk + cq + 4];
                a[mi][3] = As[(rb + r + 8) * LDA + kk + cq + 4];
            }
            #pragma unroll
            for (int ni = 0; ni < 8; ni++) {
                int cb = wn * 64 + ni * 8;
                uint32_t b0 = Bs[(kk + cq) * LDB + cb + r];
                uint32_t b1 = Bs[(kk + 4 + cq) * LDB + cb + r];
                #pragma unroll
                for (int mi = 0; mi < 2; mi++)
                    mma_16n8k8(acc[mi][ni], a[mi][0], a[mi][1], a[mi][2], a[mi][3], b0, b1);
            }
        }
        __syncthreads();
    }
    #pragma unroll
    for (int mi = 0; mi < 2; mi++) {
        int rb = bm + wm * 32 + mi * 16 + r;
        #pragma unroll
        for (int ni = 0; ni < 8; ni++) {
            int cb = bn + wn * 64 + ni * 8 + 2 * cq;
            *reinterpret_cast<float2*>(C + (size_t)rb * N + cb) =
                make_float2(acc[mi][ni][0], acc[mi][ni][1]);
            *reinterpret_cast<float2*>(C + (size_t)(rb + 8) * N + cb) =
                make_float2(acc[mi][ni][2], acc[mi][ni][3]);
        }
    }
}

// =====================================================================
// K1: FUSED head-projection + attention. Warp h computes
// wh = obs @ Bheads[:,h*32:+32] via MMA (frag-resident), scores from
// fragments, head-out via frag-shuffle B, then z / whf / gf path.
// Static smem ~30 KB.
// =====================================================================
#define XCP 132

__global__ __launch_bounds__(256) void attn_kernel(
    const float* __restrict__ obs_g, const float* __restrict__ adj_g,
    const float* __restrict__ g1_ah, const float* __restrict__ gf_ah,
    const float* __restrict__ gf_aout)
{
    int b = blockIdx.x;
    int t = threadIdx.x;
    int lane = t & 31, w = t >> 5;
    int r = lane >> 2, cq = lane & 3;

    __shared__ float buf1[NA][XCP];      // obs (phase 1), then xc1
    __shared__ float xcf[NA][XCP];
    __shared__ float att_w[8][NA][17];
    __shared__ float adj[NA][NA];
    __shared__ float f1s[NA], f2s[NA];
    __shared__ float att2s[NA][17];
    __shared__ float whf[NA][34];

    // ---- phase 0: load obs (tf32-rounded) + adj ----
    {
        const float4* src = reinterpret_cast<const float4*>(obs_g + (size_t)b * 2048);
        #pragma unroll
        for (int l = 0; l < 2; l++) {
            int idx4 = t + l * 256;              // 0..511
            int row = idx4 >> 5, c4 = (idx4 & 31) * 4;
            float4 v = src[idx4];
            buf1[row][c4]     = tf32f(v.x);
            buf1[row][c4 + 1] = tf32f(v.y);
            buf1[row][c4 + 2] = tf32f(v.z);
            buf1[row][c4 + 3] = tf32f(v.w);
        }
    }
    adj[t >> 4][t & 15] = adj_g[(size_t)b * 256 + t];
    __syncthreads();

    // ---- phase 1: wh fragment = obs @ Bheads_h  (16x32, K=128) ----
    int h = w;
    float acc1[4][4];
    #pragma unroll
    for (int nt = 0; nt < 4; nt++)
        #pragma unroll
        for (int q = 0; q < 4; q++) acc1[nt][q] = 0.f;
    #pragma unroll
    for (int ks = 0; ks < 16; ks++) {
        int kk = ks * 8;
        uint32_t a0 = __float_as_uint(buf1[r][kk + cq]);
        uint32_t a1 = __float_as_uint(buf1[r + 8][kk + cq]);
        uint32_t a2 = __float_as_uint(buf1[r][kk + cq + 4]);
        uint32_t a3 = __float_as_uint(buf1[r + 8][kk + cq + 4]);
        #pragma unroll
        for (int nt = 0; nt < 4; nt++) {
            int cb = h * 32 + nt * 8;
            uint32_t b0 = __float_as_uint(__ldg(&g_Bheads[(kk + cq) * 256 + cb + r]));
            uint32_t b1 = __float_as_uint(__ldg(&g_Bheads[(kk + 4 + cq) * 256 + cb + r]));
            mma_16n8k8(acc1[nt], a0, a1, a2, a3, b0, b1);
        }
    }

    // ---- scores from fragments: f1/f2 per row, quad-reduce + spread ----
    float facc;
    {
        const float* av = (h < 4) ? (g1_ah + h * 64) : (gf_ah + (h - 4) * 64);
        float pf1r = 0.f, pf1r8 = 0.f, pf2r = 0.f, pf2r8 = 0.f;
        #pragma unroll
        for (int nt = 0; nt < 4; nt++) {
            float2 a1v = __ldg(reinterpret_cast<const float2*>(av + nt * 8 + 2 * cq));
            float2 a2v = __ldg(reinterpret_cast<const float2*>(av + 32 + nt * 8 + 2 * cq));
            pf1r  = fmaf(acc1[nt][0], a1v.x, fmaf(acc1[nt][1], a1v.y, pf1r));
            pf1r8 = fmaf(acc1[nt][2], a1v.x, fmaf(acc1[nt][3], a1v.y, pf1r8));
            pf2r  = fmaf(acc1[nt][0], a2v.x, fmaf(acc1[nt][1], a2v.y, pf2r));
            pf2r8 = fmaf(acc1[nt][2], a2v.x, fmaf(acc1[nt][3], a2v.y, pf2r8));
        }
        #pragma unroll
        for (int mk = 1; mk <= 2; mk <<= 1) {
            pf1r  += __shfl_xor_sync(FULLM, pf1r,  mk);
            pf1r8 += __shfl_xor_sync(FULLM, pf1r8, mk);
            pf2r  += __shfl_xor_sync(FULLM, pf2r,  mk);
            pf2r8 += __shfl_xor_sync(FULLM, pf2r8, mk);
        }
        int j = lane & 15, half = lane >> 4;
        int src = (j & 7) * 4;
        float s1 = __shfl_sync(FULLM, pf1r,  src);
        float s2 = __shfl_sync(FULLM, pf1r8, src);
        float s3 = __shfl_sync(FULLM, pf2r,  src);
        float s4 = __shfl_sync(FULLM, pf2r8, src);
        facc = half ? ((j < 8) ? s3 : s4) : ((j < 8) ? s1 : s2);
    }
    __syncthreads();   // obs reads done; buf1 becomes xc1 below

    // ---- softmax (lanes j hold column att[.][j]) ----
    {
        int j = lane & 15;
        float f2j = __shfl_sync(FULLM, facc, 16 + j);
        float attc[NA];
        float m = -INFINITY;
        #pragma unroll
        for (int i = 0; i < NA; i++) {
            float f1i = __shfl_sync(FULLM, facc, i);
            float e = f1i + f2j;
            e = e > 0.f ? e : ALPHA * e;
            e = (adj[i][j] > 0.f) ? e : NEGV;
            attc[i] = e; m = fmaxf(m, e);
        }
        float s = 0.f;
        #pragma unroll
        for (int i = 0; i < NA; i++) { float x = expf(attc[i] - m); attc[i] = x; s += x; }
        float inv = 1.f / s;
        if (lane < 16) {
            #pragma unroll
            for (int i = 0; i < NA; i++) att_w[h][i][j] = tf32f(attc[i] * inv);
        }
        __syncwarp();
    }

    // ---- head-out: out = att @ wh ; B-frags shuffled from acc1 ----
    {
        float acc2[4][4];
        #pragma unroll
        for (int nt = 0; nt < 4; nt++)
            #pragma unroll
            for (int q = 0; q < 4; q++) acc2[nt][q] = 0.f;
        int src0 = cq * 4 + (r >> 1);
        int src1 = (cq + 4) * 4 + (r >> 1);
        bool odd = (r & 1);
        #pragma unroll
        for (int ks2 = 0; ks2 < 2; ks2++) {
            int kk2 = ks2 * 8;
            uint32_t a0 = __float_as_uint(att_w[h][r][kk2 + cq]);
            uint32_t a1 = __float_as_uint(att_w[h][r + 8][kk2 + cq]);
            uint32_t a2 = __float_as_uint(att_w[h][r][kk2 + cq + 4]);
            uint32_t a3 = __float_as_uint(att_w[h][r + 8][kk2 + cq + 4]);
            #pragma unroll
            for (int nt = 0; nt < 4; nt++) {
                float lo = acc1[nt][ks2 * 2];
                float hi = acc1[nt][ks2 * 2 + 1];
                float v0l = __shfl_sync(FULLM, lo, src0);
                float v0h = __shfl_sync(FULLM, hi, src0);
                float v1l = __shfl_sync(FULLM, lo, src1);
                float v1h = __shfl_sync(FULLM, hi, src1);
                uint32_t b0 = f2tf32(odd ? v0h : v0l);
                uint32_t b1 = f2tf32(odd ? v1h : v1l);
                mma_16n8k8(acc2[nt], a0, a1, a2, a3, b0, b1);
            }
        }
        // epilogue: elu, tf32, store into xc1 (=buf1) or xcf
        float* base = (h < 4) ? &buf1[0][h * 32] : &xcf[0][(h - 4) * 32];
        #pragma unroll
        for (int nt = 0; nt < 4; nt++) {
            int col = nt * 8 + 2 * cq;
            *reinterpret_cast<float2*>(base + r * XCP + col) =
                make_float2(tf32f(elu1(acc2[nt][0])), tf32f(elu1(acc2[nt][1])));
            *reinterpret_cast<float2*>(base + (r + 8) * XCP + col) =
                make_float2(tf32f(elu1(acc2[nt][2])), tf32f(elu1(acc2[nt][3])));
        }
    }
    __syncthreads();

    // ---- g1-out scores: f = xc1 @ wa ----
    #pragma unroll
    for (int rr = 0; rr < 4; rr++) {
        int d = w * 4 + rr;
        int i = d & 15, half = d >> 4;
        const float* wav = g_wa + half * 128;
        float acc = 0.f;
        #pragma unroll
        for (int k = lane; k < 128; k += 32) acc = fmaf(buf1[i][k], wav[k], acc);
        #pragma unroll
        for (int o = 16; o; o >>= 1) acc += __shfl_down_sync(FULLM, acc, o);
        if (lane == 0) { if (half) f2s[i] = acc; else f1s[i] = acc; }
    }
    __syncthreads();
    if (t < NA) {
        int j = t;
        float ev[NA]; float m = -INFINITY;
        #pragma unroll
        for (int i = 0; i < NA; i++) {
            float e = f1s[i] + f2s[j];
            e = e > 0.f ? e : ALPHA * e;
            e = (adj[i][j] > 0.f) ? e : NEGV;
            ev[i] = e; m = fmaxf(m, e);
        }
        float s = 0.f;
        #pragma unroll
        for (int i = 0; i < NA; i++) { float x = expf(ev[i] - m); ev[i] = x; s += x; }
        float inv = 1.f / s;
        #pragma unroll
        for (int i = 0; i < NA; i++) att2s[i][j] = tf32f(ev[i] * inv);
    }
    __syncthreads();

    // ---- z = att2 @ xc1 (warp w -> cols [16w,16w+16)), write tf32 ----
    {
        float acc[2][4];
        #pragma unroll
        for (int nt = 0; nt < 2; nt++)
            #pragma unroll
            for (int q = 0; q < 4; q++) acc[nt][q] = 0.f;
        #pragma unroll
        for (int ks = 0; ks < 2; ks++) {
            int kk = ks * 8;
            uint32_t a0 = __float_as_uint(att2s[r][kk + cq]);
            uint32_t a1 = __float_as_uint(att2s[r + 8][kk + cq]);
            uint32_t a2 = __float_as_uint(att2s[r][kk + cq + 4]);
            uint32_t a3 = __float_as_uint(att2s[r + 8][kk + cq + 4]);
            #pragma unroll
            for (int nt = 0; nt < 2; nt++) {
                int cb = w * 16 + nt * 8;
                uint32_t b0 = __float_as_uint(buf1[kk + cq][cb + r]);
                uint32_t b1 = __float_as_uint(buf1[kk + 4 + cq][cb + r]);
                mma_16n8k8(acc[nt], a0, a1, a2, a3, b0, b1);
            }
        }
        float* zdst = g_z + (size_t)b * 2048;
        #pragma unroll
        for (int nt = 0; nt < 2; nt++) {
            int col = w * 16 + nt * 8 + 2 * cq;
            *reinterpret_cast<float2*>(zdst + r * 128 + col) =
                make_float2(tf32f(acc[nt][0]), tf32f(acc[nt][1]));
            *reinterpret_cast<float2*>(zdst + (r + 8) * 128 + col) =
                make_float2(tf32f(acc[nt][2]), tf32f(acc[nt][3]));
        }
    }

    // ---- whf = xcf @ gf_Wout (warps 0-3) ----
    if (w < 4) {
        int cb = w * 8;
        float acc[4] = {0.f, 0.f, 0.f, 0.f};
        #pragma unroll
        for (int ks = 0; ks < 16; ks++) {
            int kk = ks * 8;
            uint32_t a0 = __float_as_uint(xcf[r][kk + cq]);
            uint32_t a1 = __float_as_uint(xcf[r + 8][kk + cq]);
            uint32_t a2 = __float_as_uint(xcf[r][kk + cq + 4]);
            uint32_t a3 = __float_as_uint(xcf[r + 8][kk + cq + 4]);
            uint32_t b0 = __float_as_uint(g_gfW32[(kk + cq) * 32 + cb + r]);
            uint32_t b1 = __float_as_uint(g_gfW32[(kk + 4 + cq) * 32 + cb + r]);
            mma_16n8k8(acc, a0, a1, a2, a3, b0, b1);
        }
        int col = cb + 2 * cq;
        *reinterpret_cast<float2*>(&whf[r][col]) = make_float2(acc[0], acc[1]);
        *reinterpret_cast<float2*>(&whf[r + 8][col]) = make_float2(acc[2], acc[3]);
    }
    __syncthreads();

    // ---- gf attention finish (single warp) ----
    if (w == 0) {
        int d = lane & 15, half = lane >> 4;
        const float* av = gf_aout + half * 32;
        float fac = 0.f;
        #pragma unroll
        for (int c = 0; c < 32; c++) fac = fmaf(whf[d][c], av[c], fac);
        int j = lane & 15;
        float f2j = __shfl_sync(FULLM, fac, 16 + j);
        float attc[NA];
        float m = -INFINITY;
        #pragma unroll
        for (int i = 0; i < NA; i++) {
            float f1i = __shfl_sync(FULLM, fac, i);
            float e = f1i + f2j;
            e = e > 0.f ? e : ALPHA * e;
            e = (adj[i][j] > 0.f) ? e : NEGV;
            attc[i] = e; m = fmaxf(m, e);
        }
        float s = 0.f;
        #pragma unroll
        for (int i = 0; i < NA; i++) { float x = expf(attc[i] - m); attc[i] = x; s += x; }
        float inv = 1.f / s;
        #pragma unroll
        for (int i = 0; i < NA; i++) attc[i] *= inv;
        int c = lane;
        float o2[NA];
        float mm = -INFINITY;
        #pragma unroll
        for (int i = 0; i < NA; i++) {
            float acc = 0.f;
            #pragma unroll
            for (int n = 0; n < NA; n++) {
                float a_in = __shfl_sync(FULLM, attc[i], n);
                acc = fmaf(a_in, whf[n][c], acc);
            }
            acc = elu1(acc);
            o2[i] = acc; mm = fmaxf(mm, acc);
        }
        float ss = 0.f;
        #pragma unroll
        for (int i = 0; i < NA; i++) ss += expf(o2[i] - mm);
        float lse = mm + logf(ss);
        #pragma unroll
        for (int i = 0; i < NA; i++)
            g_wf[(size_t)b * 512 + i * 32 + c] = fabsf(o2[i] - lse);
    }
}

// =====================================================================
// K2: fused GEMM3 + mix. Block = 64 rows (4 batches) x 512 cols.
// 512 threads, 16 warps (2x8). Dynamic smem 128KB. uint4 loads.
// =====================================================================
#define LDB3 520

extern __shared__ char g3smem[];

__global__ __launch_bounds__(512, 1) void gemm3_mix_kernel(
    const float* __restrict__ A,              // g_z tf32 bits [131072 x 128]
    const float* __restrict__ Wout,           // g_Wout32 tf32 bits [128 x 512]
    const float* __restrict__ agent_qs, const float* __restrict__ states,
    const float* __restrict__ wn_w, const float* __restrict__ wn_b,
    const float* __restrict__ hb_b,
    const float* __restrict__ v1_w, const float* __restrict__ v1_b,
    const float* __restrict__ v2_w, const float* __restrict__ v2_b,
    float* __restrict__ out)
{
    uint32_t* As = reinterpret_cast<uint32_t*>(g3smem);
    uint32_t* Bs = As + 64 * LDA;
    float*    Ds = reinterpret_cast<float*>(g3smem);

    __shared__ float qs_s[4][NA];
    __shared__ float st_s[4][STATE];
    __shared__ float yv_s[4][NA];
    __shared__ float disv[4][NA];
    __shared__ float vpart[4][32];

    int t = threadIdx.x;
    int lane = t & 31, w = t >> 5;
    int wm = w & 1, wn = w >> 1;
    int r = lane >> 2, cq = lane & 3;
    int bm = blockIdx.y * 64;
    int b0 = blockIdx.y * 4;

    if (t < 64) qs_s[t >> 4][t & 15] = agent_qs[(size_t)(b0 + (t >> 4)) * NA + (t & 15)];
    #pragma unroll
    for (int l = 0; l < 2; l++) {
        int idx = t + l * 512;
        st_s[idx >> 8][idx & 255] = states[(size_t)b0 * 256 + idx];
    }

    float acc[2][8][4];
    #pragma unroll
    for (int mi = 0; mi < 2; mi++)
        #pragma unroll
        for (int ni = 0; ni < 8; ni++)
            #pragma unroll
            for (int j = 0; j < 4; j++) acc[mi][ni][j] = 0.f;

    for (int k0 = 0; k0 < 128; k0 += 32) {
        {
            int row = t >> 3, q = t & 7;
            uint4 v = *reinterpret_cast<const uint4*>(A + (size_t)(bm + row) * 128 + k0 + q * 4);
            uint32_t* p = &As[row * LDA + q * 4];
            p[0] = v.x; p[1] = v.y; p[2] = v.z; p[3] = v.w;
        }
        #pragma unroll
        for (int l = 0; l < 8; l++) {
            int idx = t + l * 512;
            int row = idx >> 7, q = idx & 127;
            uint4 v = *reinterpret_cast<const uint4*>(Wout + (size_t)(k0 + row) * 512 + q * 4);
            uint32_t* p = &Bs[row * LDB3 + q * 4];
            p[0] = v.x; p[1] = v.y; p[2] = v.z; p[3] = v.w;
        }
        __syncthreads();
        #pragma unroll
        for (int kk = 0; kk < 32; kk += 8) {
            uint32_t a[2][4];
            #pragma unroll
            for (int mi = 0; mi < 2; mi++) {
                int rb = wm * 32 + mi * 16;
                a[mi][0] = As[(rb + r) * LDA + kk + cq];
                a[mi][1] = As[(rb + r + 8) * LDA + kk + cq];
                a[mi][2] = As[(rb + r) * LDA + kk + cq + 4];
                a[mi][3] = As[(rb + r + 8) * LDA + kk + cq + 4];
            }
            #pragma unroll
            for (int ni = 0; ni < 8; ni++) {
                int cb = wn * 64 + ni * 8;
                uint32_t b0r = Bs[(kk + cq) * LDB3 + cb + r];
                uint32_t b1r = Bs[(kk + 4 + cq) * LDB3 + cb + r];
                #pragma unroll
                for (int mi = 0; mi < 2; mi++)
                    mma_16n8k8(acc[mi][ni], a[mi][0], a[mi][1], a[mi][2], a[mi][3], b0r, b1r);
            }
        }
        __syncthreads();
    }

    #pragma unroll
    for (int mi = 0; mi < 2; mi++) {
        int row0 = wm * 32 + mi * 16 + r;
        #pragma unroll
        for (int ni = 0; ni < 8; ni++) {
            int col = wn * 64 + ni * 8 + 2 * cq;
            *reinterpret_cast<float2*>(&Ds[row0 * 512 + col]) =
                make_float2(elu1(acc[mi][ni][0]), elu1(acc[mi][ni][1]));
            *reinterpret_cast<float2*>(&Ds[(row0 + 8) * 512 + col]) =
                make_float2(elu1(acc[mi][ni][2]), elu1(acc[mi][ni][3]));
        }
    }
    __syncthreads();

    #pragma unroll
    for (int p = 0; p < 4; p++) {
        int tt = t + p * 512;
        int bl = tt >> 9, c = tt & 511;
        float* col = Ds + (bl * 16) * 512 + c;
        float v[NA]; float m = -INFINITY;
        #pragma unroll
        for (int i = 0; i < NA; i++) { v[i] = col[i * 512]; m = fmaxf(m, v[i]); }
        float s = 0.f;
        #pragma unroll
        for (int i = 0; i < NA; i++) s += expf(v[i] - m);
        float lse = m + logf(s);
        #pragma unroll
        for (int i = 0; i < NA; i++) col[i * 512] = fabsf(v[i] - lse);
    }
    __syncthreads();

    {
        int e = lane, i = w;
        #pragma unroll
        for (int bl = 0; bl < 4; bl++) {
            int b = b0 + bl;
            float p = g_ball[(size_t)b * 512 + i * 32 + e] + hb_b[i * 32 + e];
            const float* row = Ds + (bl * 16 + i) * 512;
            #pragma unroll
            for (int n = 0; n < NA; n++)
                p = fmaf(qs_s[bl][n], row[n * 32 + e], p);
            p = elu1(p);
            float prod = p * g_wf[(size_t)b * 512 + i * 32 + e];
            #pragma unroll
            for (int o = 16; o; o >>= 1) prod += __shfl_down_sync(FULLM, prod, o);
            if (lane == 0) yv_s[bl][i] = prod;
        }
    }

    {
        int bl = w >> 2, qt = w & 3;
        #pragma unroll
        for (int rr = 0; rr < 4; rr++) {
            int n = qt * 4 + rr;
            float acc2 = 0.f;
            #pragma unroll
            for (int s_ = lane; s_ < 256; s_ += 32)
                acc2 = fmaf(st_s[bl][s_], wn_w[n * 256 + s_], acc2);
            #pragma unroll
            for (int o = 16; o; o >>= 1) acc2 += __shfl_down_sync(FULLM, acc2, o);
            if (lane == 0) disv[bl][n] = fabsf(acc2 + wn_b[n]);
        }
        #pragma unroll
        for (int rr = 0; rr < 8; rr++) {
            int n = qt * 8 + rr;
            float acc2 = 0.f;
            #pragma unroll
            for (int s_ = lane; s_ < 256; s_ += 32)
                acc2 = fmaf(st_s[bl][s_], v1_w[n * 256 + s_], acc2);
            #pragma unroll
            for (int o = 16; o; o >>= 1) acc2 += __shfl_down_sync(FULLM, acc2, o);
            if (lane == 0) vpart[bl][n] = fmaxf(acc2 + v1_b[n], 0.f);
        }
    }
    __syncthreads();

    if (t < 4) {
        int bl = t;
        float v = v2_b[0];
        #pragma unroll
        for (int h2 = 0; h2 < 32; h2++) v = fmaf(vpart[bl][h2], v2_w[h2], v);
        float q = v;
        #pragma unroll
        for (int n = 0; n < NA; n++) q = fmaf(yv_s[bl][n], disv[bl][n], q);
        out[b0 + bl] = q;
    }
}

// =====================================================================
extern "C" void kernel_launch(void* const* d_in, const int* in_sizes, int n_in,
                              void* d_out, int out_size)
{
    const float* agent_qs = (const float*)d_in[0];
    const float* states   = (const float*)d_in[1];
    const float* obs_ls   = (const float*)d_in[2];
    const float* adj_ls   = (const float*)d_in[3];
    const float* wn_w     = (const float*)d_in[4];
    const float* wn_b     = (const float*)d_in[5];
    const float* g1_Wh    = (const float*)d_in[6];
    const float* g1_ah    = (const float*)d_in[7];
    const float* g1_Wout  = (const float*)d_in[8];
    const float* g1_aout  = (const float*)d_in[9];
    const float* gf_Wh    = (const float*)d_in[10];
    const float* gf_ah    = (const float*)d_in[11];
    const float* gf_Wout  = (const float*)d_in[12];
    const float* gf_aout  = (const float*)d_in[13];
    const float* hb_W     = (const float*)d_in[14];
    const float* hb_b     = (const float*)d_in[15];
    const float* v1_w     = (const float*)d_in[16];
    const float* v1_b     = (const float*)d_in[17];
    const float* v2_w     = (const float*)d_in[18];
    const float* v2_b     = (const float*)d_in[19];
    float* out = (float*)d_out;

    float *p_z, *p_ball, *p_BhbT, *p_Wout32;
    cudaGetSymbolAddress((void**)&p_z,      g_z);
    cudaGetSymbolAddress((void**)&p_ball,   g_ball);
    cudaGetSymbolAddress((void**)&p_BhbT,   g_BhbT);
    cudaGetSymbolAddress((void**)&p_Wout32, g_Wout32);

    const int G3_SMEM = 64 * 512 * 4;     // 128 KB dynamic
    cudaFuncSetAttribute(gemm3_mix_kernel,
                         cudaFuncAttributeMaxDynamicSharedMemorySize, G3_SMEM);

    pack_kernel<<<64, 256>>>(g1_Wh, gf_Wh, g1_Wout, g1_aout, gf_Wout, hb_W);

    // b_all = states(8192x256) @ hb_W^T(256x512)
    gemm_tf32<<<dim3(4, 64), 256>>>(states, p_BhbT, p_ball, BTOT, 256, 512);

    // fused head-projection + attention (gemm1 eliminated)
    attn_kernel<<<BTOT, 256>>>(obs_ls, adj_ls, g1_ah, gf_ah, gf_aout);

    // fused: D = Z @ Wout -> elu -> logsoftmax -> abs -> mix -> q
    gemm3_mix_kernel<<<dim3(1, 2048), 512, G3_SMEM>>>(
        p_z, p_Wout32, agent_qs, states, wn_w, wn_b, hb_b,
        v1_w, v1_b, v2_w, v2_b, out);
}

// round 11
// speedup vs baseline: 3.0450x; 1.0343x over previous
#include <cuda_runtime.h>
#include <math.h>
#include <stdint.h>

#define NA 16
#define OBSF 128
#define STATE 256
#define EMBED 32
#define NHID 32
#define BTOT 8192
#define ALPHA 0.2f
#define NEGV -9.0e15f
#define FULLM 0xffffffffu

// ---------------- scratch (device globals) ----------------
__device__ float g_z[(size_t)BTOT * NA * 128];       // 64 MB   att2@xcat1 (tf32 bits)
__device__ float g_ball[(size_t)BTOT * 512];         // 16 MB   b_all pre-bias
__device__ float g_wf[(size_t)BTOT * 512];           // 16 MB   |logsoftmax(gf out)|
__device__ float g_Bheads[128 * 256];                // packed head weights (tf32 bits)
__device__ float g_BhbT[256 * 512];                  // hb_W transposed (tf32 bits)
__device__ float g_Wout32[128 * 512];                // g1_Wout (tf32 bits)
__device__ float g_gfW32[128 * 32];                  // gf_Wout (tf32 bits)
__device__ float g_wa[256];                          // wa1 (128) | wa2 (128), fp32

__device__ __forceinline__ uint32_t f2tf32(float f) {
    uint32_t u; asm("cvt.rna.tf32.f32 %0, %1;" : "=r"(u) : "f"(f)); return u;
}
__device__ __forceinline__ float tf32f(float f) { return __uint_as_float(f2tf32(f)); }

__device__ __forceinline__ void mma_16n8k8(float* c,
    uint32_t a0, uint32_t a1, uint32_t a2, uint32_t a3,
    uint32_t b0, uint32_t b1)
{
    asm volatile(
        "mma.sync.aligned.m16n8k8.row.col.f32.tf32.tf32.f32 "
        "{%0,%1,%2,%3}, {%4,%5,%6,%7}, {%8,%9}, {%0,%1,%2,%3};"
        : "+f"(c[0]), "+f"(c[1]), "+f"(c[2]), "+f"(c[3])
        : "r"(a0), "r"(a1), "r"(a2), "r"(a3), "r"(b0), "r"(b1));
}

__device__ __forceinline__ float elu1(float v) {
    return v > 0.f ? v : expm1f(v);
}

__device__ __forceinline__ void cp16(uint32_t smem_addr, const void* gptr) {
    asm volatile("cp.async.ca.shared.global [%0], [%1], 16;\n"
                 :: "r"(smem_addr), "l"(gptr));
}
#define CP_COMMIT() asm volatile("cp.async.commit_group;\n" ::: "memory")
template <int N> __device__ __forceinline__ void cp_wait() {
    asm volatile("cp.async.wait_group %0;\n" :: "n"(N) : "memory");
}

// =====================================================================
// K0: pack weights (tf32-converted) + wa vectors
// =====================================================================
__global__ void pack_kernel(const float* __restrict__ g1_Wh, const float* __restrict__ gf_Wh,
                            const float* __restrict__ g1_Wout, const float* __restrict__ g1_aout,
                            const float* __restrict__ gf_Wout, const float* __restrict__ hb_W)
{
    int t = threadIdx.x, bid = blockIdx.x;
    int gid = bid * 256 + t;
    for (int idx = gid; idx < 128 * 256; idx += 64 * 256) {
        int k = idx >> 8, c = idx & 255;
        float v = (c < 128) ? g1_Wh[(c >> 5) * 4096 + k * 32 + (c & 31)]
                            : gf_Wh[((c - 128) >> 5) * 4096 + k * 32 + (c & 31)];
        g_Bheads[idx] = tf32f(v);
    }
    for (int idx = gid; idx < 256 * 512; idx += 64 * 256) {
        int k = idx >> 9, n = idx & 511;
        g_BhbT[idx] = tf32f(hb_W[n * 256 + k]);
    }
    for (int idx = gid; idx < 128 * 512; idx += 64 * 256)
        g_Wout32[idx] = tf32f(g1_Wout[idx]);
    for (int idx = gid; idx < 128 * 32; idx += 64 * 256)
        g_gfW32[idx] = tf32f(gf_Wout[idx]);
    if (bid == 0) {
        int wp = t >> 5, ln = t & 31;
        for (int d = wp; d < 256; d += 8) {
            int k = d & 127, half = d >> 7;
            const float* ap = g1_aout + half * 512;
            const float* wr = g1_Wout + (size_t)k * 512;
            float acc = 0.f;
            for (int c = ln; c < 512; c += 32) acc = fmaf(wr[c], ap[c], acc);
            #pragma unroll
            for (int o = 16; o; o >>= 1) acc += __shfl_down_sync(FULLM, acc, o);
            if (ln == 0) g_wa[half * 128 + k] = acc;
        }
    }
}

// =====================================================================
// TF32 GEMM (used for b_all only): C = A @ B, B PRE-CONVERTED.
// =====================================================================
#define LDA 36
#define LDB 136

__global__ __launch_bounds__(256) void gemm_tf32(
    const float* __restrict__ A, const float* __restrict__ B, float* __restrict__ C,
    int M, int K, int N)
{
    __shared__ uint32_t As[128 * LDA];
    __shared__ uint32_t Bs[32 * LDB];
    int t = threadIdx.x;
    int lane = t & 31, w = t >> 5;
    int wm = w & 3, wn = w >> 2;
    int bm = blockIdx.y * 128, bn = blockIdx.x * 128;
    int r = lane >> 2, cq = lane & 3;

    float acc[2][8][4];
    #pragma unroll
    for (int mi = 0; mi < 2; mi++)
        #pragma unroll
        for (int ni = 0; ni < 8; ni++)
            #pragma unroll
            for (int j = 0; j < 4; j++) acc[mi][ni][j] = 0.f;

    for (int k0 = 0; k0 < K; k0 += 32) {
        #pragma unroll
        for (int l = 0; l < 4; l++) {
            int idx = t + l * 256;
            int row = idx >> 3, q = idx & 7;
            float4 v = *reinterpret_cast<const float4*>(A + (size_t)(bm + row) * K + k0 + q * 4);
            uint32_t* p = &As[row * LDA + q * 4];
            p[0] = f2tf32(v.x); p[1] = f2tf32(v.y); p[2] = f2tf32(v.z); p[3] = f2tf32(v.w);
        }
        #pragma unroll
        for (int l = 0; l < 4; l++) {
            int idx = t + l * 256;
            int row = idx >> 5, q = idx & 31;
            uint4 v = *reinterpret_cast<const uint4*>(B + (size_t)(k0 + row) * N + bn + q * 4);
            uint32_t* p = &Bs[row * LDB + q * 4];
            p[0] = v.x; p[1] = v.y; p[2] = v.z; p[3] = v.w;
        }
        __syncthreads();
        #pragma unroll
        for (int kk = 0; kk < 32; kk += 8) {
            uint32_t a[2][4];
            #pragma unroll
            for (int mi = 0; mi < 2; mi++) {
                int rb = wm * 32 + mi * 16;
                a[mi][0] = As[(rb + r) * LDA + kk + cq];
                a[mi][1] = As[(rb + r + 8) * LDA + kk + cq];
                a[mi][2] = As[(rb + r) * LDA + kk + cq + 4];
                a[mi][3] = As[(rb + r + 8) * LDA + kk + cq + 4];
            }
            #pragma unroll
            for (int ni = 0; ni < 8; ni++) {
                int cb = wn * 64 + ni * 8;
                uint32_t b0 = Bs[(kk + cq) * LDB + cb + r];
                uint32_t b1 = Bs[(kk + 4 + cq) * LDB + cb + r];
                #pragma unroll
                for (int mi = 0; mi < 2; mi++)
                    mma_16n8k8(acc[mi][ni], a[mi][0], a[mi][1], a[mi][2], a[mi][3], b0, b1);
            }
        }
        __syncthreads();
    }
    #pragma unroll
    for (int mi = 0; mi < 2; mi++) {
        int rb = bm + wm * 32 + mi * 16 + r;
        #pragma unroll
        for (int ni = 0; ni < 8; ni++) {
            int cb = bn + wn * 64 + ni * 8 + 2 * cq;
            *reinterpret_cast<float2*>(C + (size_t)rb * N + cb) =
                make_float2(acc[mi][ni][0], acc[mi][ni][1]);
            *reinterpret_cast<float2*>(C + (size_t)(rb + 8) * N + cb) =
                make_float2(acc[mi][ni][2], acc[mi][ni][3]);
        }
    }
}

// =====================================================================
// K1: FUSED head-projection + attention (unchanged from R10).
// =====================================================================
#define XCP 132

__global__ __launch_bounds__(256) void attn_kernel(
    const float* __restrict__ obs_g, const float* __restrict__ adj_g,
    const float* __restrict__ g1_ah, const float* __restrict__ gf_ah,
    const float* __restrict__ gf_aout)
{
    int b = blockIdx.x;
    int t = threadIdx.x;
    int lane = t & 31, w = t >> 5;
    int r = lane >> 2, cq = lane & 3;

    __shared__ float buf1[NA][XCP];      // obs (phase 1), then xc1
    __shared__ float xcf[NA][XCP];
    __shared__ float att_w[8][NA][17];
    __shared__ float adj[NA][NA];
    __shared__ float f1s[NA], f2s[NA];
    __shared__ float att2s[NA][17];
    __shared__ float whf[NA][34];

    {
        const float4* src = reinterpret_cast<const float4*>(obs_g + (size_t)b * 2048);
        #pragma unroll
        for (int l = 0; l < 2; l++) {
            int idx4 = t + l * 256;
            int row = idx4 >> 5, c4 = (idx4 & 31) * 4;
            float4 v = src[idx4];
            buf1[row][c4]     = tf32f(v.x);
            buf1[row][c4 + 1] = tf32f(v.y);
            buf1[row][c4 + 2] = tf32f(v.z);
            buf1[row][c4 + 3] = tf32f(v.w);
        }
    }
    adj[t >> 4][t & 15] = adj_g[(size_t)b * 256 + t];
    __syncthreads();

    int h = w;
    float acc1[4][4];
    #pragma unroll
    for (int nt = 0; nt < 4; nt++)
        #pragma unroll
        for (int q = 0; q < 4; q++) acc1[nt][q] = 0.f;
    #pragma unroll
    for (int ks = 0; ks < 16; ks++) {
        int kk = ks * 8;
        uint32_t a0 = __float_as_uint(buf1[r][kk + cq]);
        uint32_t a1 = __float_as_uint(buf1[r + 8][kk + cq]);
        uint32_t a2 = __float_as_uint(buf1[r][kk + cq + 4]);
        uint32_t a3 = __float_as_uint(buf1[r + 8][kk + cq + 4]);
        #pragma unroll
        for (int nt = 0; nt < 4; nt++) {
            int cb = h * 32 + nt * 8;
            uint32_t b0 = __float_as_uint(__ldg(&g_Bheads[(kk + cq) * 256 + cb + r]));
            uint32_t b1 = __float_as_uint(__ldg(&g_Bheads[(kk + 4 + cq) * 256 + cb + r]));
            mma_16n8k8(acc1[nt], a0, a1, a2, a3, b0, b1);
        }
    }

    float facc;
    {
        const float* av = (h < 4) ? (g1_ah + h * 64) : (gf_ah + (h - 4) * 64);
        float pf1r = 0.f, pf1r8 = 0.f, pf2r = 0.f, pf2r8 = 0.f;
        #pragma unroll
        for (int nt = 0; nt < 4; nt++) {
            float2 a1v = __ldg(reinterpret_cast<const float2*>(av + nt * 8 + 2 * cq));
            float2 a2v = __ldg(reinterpret_cast<const float2*>(av + 32 + nt * 8 + 2 * cq));
            pf1r  = fmaf(acc1[nt][0], a1v.x, fmaf(acc1[nt][1], a1v.y, pf1r));
            pf1r8 = fmaf(acc1[nt][2], a1v.x, fmaf(acc1[nt][3], a1v.y, pf1r8));
            pf2r  = fmaf(acc1[nt][0], a2v.x, fmaf(acc1[nt][1], a2v.y, pf2r));
            pf2r8 = fmaf(acc1[nt][2], a2v.x, fmaf(acc1[nt][3], a2v.y, pf2r8));
        }
        #pragma unroll
        for (int mk = 1; mk <= 2; mk <<= 1) {
            pf1r  += __shfl_xor_sync(FULLM, pf1r,  mk);
            pf1r8 += __shfl_xor_sync(FULLM, pf1r8, mk);
            pf2r  += __shfl_xor_sync(FULLM, pf2r,  mk);
            pf2r8 += __shfl_xor_sync(FULLM, pf2r8, mk);
        }
        int j = lane & 15, half = lane >> 4;
        int src = (j & 7) * 4;
        float s1 = __shfl_sync(FULLM, pf1r,  src);
        float s2 = __shfl_sync(FULLM, pf1r8, src);
        float s3 = __shfl_sync(FULLM, pf2r,  src);
        float s4 = __shfl_sync(FULLM, pf2r8, src);
        facc = half ? ((j < 8) ? s3 : s4) : ((j < 8) ? s1 : s2);
    }
    __syncthreads();

    {
        int j = lane & 15;
        float f2j = __shfl_sync(FULLM, facc, 16 + j);
        float attc[NA];
        float m = -INFINITY;
        #pragma unroll
        for (int i = 0; i < NA; i++) {
            float f1i = __shfl_sync(FULLM, facc, i);
            float e = f1i + f2j;
            e = e > 0.f ? e : ALPHA * e;
            e = (adj[i][j] > 0.f) ? e : NEGV;
            attc[i] = e; m = fmaxf(m, e);
        }
        float s = 0.f;
        #pragma unroll
        for (int i = 0; i < NA; i++) { float x = expf(attc[i] - m); attc[i] = x; s += x; }
        float inv = 1.f / s;
        if (lane < 16) {
            #pragma unroll
            for (int i = 0; i < NA; i++) att_w[h][i][j] = tf32f(attc[i] * inv);
        }
        __syncwarp();
    }

    {
        float acc2[4][4];
        #pragma unroll
        for (int nt = 0; nt < 4; nt++)
            #pragma unroll
            for (int q = 0; q < 4; q++) acc2[nt][q] = 0.f;
        int src0 = cq * 4 + (r >> 1);
        int src1 = (cq + 4) * 4 + (r >> 1);
        bool odd = (r & 1);
        #pragma unroll
        for (int ks2 = 0; ks2 < 2; ks2++) {
            int kk2 = ks2 * 8;
            uint32_t a0 = __float_as_uint(att_w[h][r][kk2 + cq]);
            uint32_t a1 = __float_as_uint(att_w[h][r + 8][kk2 + cq]);
            uint32_t a2 = __float_as_uint(att_w[h][r][kk2 + cq + 4]);
            uint32_t a3 = __float_as_uint(att_w[h][r + 8][kk2 + cq + 4]);
            #pragma unroll
            for (int nt = 0; nt < 4; nt++) {
                float lo = acc1[nt][ks2 * 2];
                float hi = acc1[nt][ks2 * 2 + 1];
                float v0l = __shfl_sync(FULLM, lo, src0);
                float v0h = __shfl_sync(FULLM, hi, src0);
                float v1l = __shfl_sync(FULLM, lo, src1);
                float v1h = __shfl_sync(FULLM, hi, src1);
                uint32_t b0 = f2tf32(odd ? v0h : v0l);
                uint32_t b1 = f2tf32(odd ? v1h : v1l);
                mma_16n8k8(acc2[nt], a0, a1, a2, a3, b0, b1);
            }
        }
        float* base = (h < 4) ? &buf1[0][h * 32] : &xcf[0][(h - 4) * 32];
        #pragma unroll
        for (int nt = 0; nt < 4; nt++) {
            int col = nt * 8 + 2 * cq;
            *reinterpret_cast<float2*>(base + r * XCP + col) =
                make_float2(tf32f(elu1(acc2[nt][0])), tf32f(elu1(acc2[nt][1])));
            *reinterpret_cast<float2*>(base + (r + 8) * XCP + col) =
                make_float2(tf32f(elu1(acc2[nt][2])), tf32f(elu1(acc2[nt][3])));
        }
    }
    __syncthreads();

    #pragma unroll
    for (int rr = 0; rr < 4; rr++) {
        int d = w * 4 + rr;
        int i = d & 15, half = d >> 4;
        const float* wav = g_wa + half * 128;
        float acc = 0.f;
        #pragma unroll
        for (int k = lane; k < 128; k += 32) acc = fmaf(buf1[i][k], wav[k], acc);
        #pragma unroll
        for (int o = 16; o; o >>= 1) acc += __shfl_down_sync(FULLM, acc, o);
        if (lane == 0) { if (half) f2s[i] = acc; else f1s[i] = acc; }
    }
    __syncthreads();
    if (t < NA) {
        int j = t;
        float ev[NA]; float m = -INFINITY;
        #pragma unroll
        for (int i = 0; i < NA; i++) {
            float e = f1s[i] + f2s[j];
            e = e > 0.f ? e : ALPHA * e;
            e = (adj[i][j] > 0.f) ? e : NEGV;
            ev[i] = e; m = fmaxf(m, e);
        }
        float s = 0.f;
        #pragma unroll
        for (int i = 0; i < NA; i++) { float x = expf(ev[i] - m); ev[i] = x; s += x; }
        float inv = 1.f / s;
        #pragma unroll
        for (int i = 0; i < NA; i++) att2s[i][j] = tf32f(ev[i] * inv);
    }
    __syncthreads();

    {
        float acc[2][4];
        #pragma unroll
        for (int nt = 0; nt < 2; nt++)
            #pragma unroll
            for (int q = 0; q < 4; q++) acc[nt][q] = 0.f;
        #pragma unroll
        for (int ks = 0; ks < 2; ks++) {
            int kk = ks * 8;
            uint32_t a0 = __float_as_uint(att2s[r][kk + cq]);
            uint32_t a1 = __float_as_uint(att2s[r + 8][kk + cq]);
            uint32_t a2 = __float_as_uint(att2s[r][kk + cq + 4]);
            uint32_t a3 = __float_as_uint(att2s[r + 8][kk + cq + 4]);
            #pragma unroll
            for (int nt = 0; nt < 2; nt++) {
                int cb = w * 16 + nt * 8;
                uint32_t b0 = __float_as_uint(buf1[kk + cq][cb + r]);
                uint32_t b1 = __float_as_uint(buf1[kk + 4 + cq][cb + r]);
                mma_16n8k8(acc[nt], a0, a1, a2, a3, b0, b1);
            }
        }
        float* zdst = g_z + (size_t)b * 2048;
        #pragma unroll
        for (int nt = 0; nt < 2; nt++) {
            int col = w * 16 + nt * 8 + 2 * cq;
            *reinterpret_cast<float2*>(zdst + r * 128 + col) =
                make_float2(tf32f(acc[nt][0]), tf32f(acc[nt][1]));
            *reinterpret_cast<float2*>(zdst + (r + 8) * 128 + col) =
                make_float2(tf32f(acc[nt][2]), tf32f(acc[nt][3]));
        }
    }

    if (w < 4) {
        int cb = w * 8;
        float acc[4] = {0.f, 0.f, 0.f, 0.f};
        #pragma unroll
        for (int ks = 0; ks < 16; ks++) {
            int kk = ks * 8;
            uint32_t a0 = __float_as_uint(xcf[r][kk + cq]);
            uint32_t a1 = __float_as_uint(xcf[r + 8][kk + cq]);
            uint32_t a2 = __float_as_uint(xcf[r][kk + cq + 4]);
            uint32_t a3 = __float_as_uint(xcf[r + 8][kk + cq + 4]);
            uint32_t b0 = __float_as_uint(g_gfW32[(kk + cq) * 32 + cb + r]);
            uint32_t b1 = __float_as_uint(g_gfW32[(kk + 4 + cq) * 32 + cb + r]);
            mma_16n8k8(acc, a0, a1, a2, a3, b0, b1);
        }
        int col = cb + 2 * cq;
        *reinterpret_cast<float2*>(&whf[r][col]) = make_float2(acc[0], acc[1]);
        *reinterpret_cast<float2*>(&whf[r + 8][col]) = make_float2(acc[2], acc[3]);
    }
    __syncthreads();

    if (w == 0) {
        int d = lane & 15, half = lane >> 4;
        const float* av = gf_aout + half * 32;
        float fac = 0.f;
        #pragma unroll
        for (int c = 0; c < 32; c++) fac = fmaf(whf[d][c], av[c], fac);
        int j = lane & 15;
        float f2j = __shfl_sync(FULLM, fac, 16 + j);
        float attc[NA];
        float m = -INFINITY;
        #pragma unroll
        for (int i = 0; i < NA; i++) {
            float f1i = __shfl_sync(FULLM, fac, i);
            float e = f1i + f2j;
            e = e > 0.f ? e : ALPHA * e;
            e = (adj[i][j] > 0.f) ? e : NEGV;
            attc[i] = e; m = fmaxf(m, e);
        }
        float s = 0.f;
        #pragma unroll
        for (int i = 0; i < NA; i++) { float x = expf(attc[i] - m); attc[i] = x; s += x; }
        float inv = 1.f / s;
        #pragma unroll
        for (int i = 0; i < NA; i++) attc[i] *= inv;
        int c = lane;
        float o2[NA];
        float mm = -INFINITY;
        #pragma unroll
        for (int i = 0; i < NA; i++) {
            float acc = 0.f;
            #pragma unroll
            for (int n = 0; n < NA; n++) {
                float a_in = __shfl_sync(FULLM, attc[i], n);
                acc = fmaf(a_in, whf[n][c], acc);
            }
            acc = elu1(acc);
            o2[i] = acc; mm = fmaxf(mm, acc);
        }
        float ss = 0.f;
        #pragma unroll
        for (int i = 0; i < NA; i++) ss += expf(o2[i] - mm);
        float lse = mm + logf(ss);
        #pragma unroll
        for (int i = 0; i < NA; i++)
            g_wf[(size_t)b * 512 + i * 32 + c] = fabsf(o2[i] - lse);
    }
}

// =====================================================================
// K2: fused GEMM3 + mix with cp.async DOUBLE-BUFFERED mainloop.
// Block = 64 rows (4 batches) x 512 cols, 512 threads.
// Smem: 2 stages x (As 64x36 + Bs 32x520) = 151,552 B; Ds overlays.
// =====================================================================
#define LDB3 520
#define ASTG (64 * LDA)                 // u32 per A stage
#define BSTG (32 * LDB3)                // u32 per B stage

extern __shared__ char g3smem[];

__global__ __launch_bounds__(512, 1) void gemm3_mix_kernel(
    const float* __restrict__ A,              // g_z tf32 bits [131072 x 128]
    const float* __restrict__ Wout,           // g_Wout32 tf32 bits [128 x 512]
    const float* __restrict__ agent_qs, const float* __restrict__ states,
    const float* __restrict__ wn_w, const float* __restrict__ wn_b,
    const float* __restrict__ hb_b,
    const float* __restrict__ v1_w, const float* __restrict__ v1_b,
    const float* __restrict__ v2_w, const float* __restrict__ v2_b,
    float* __restrict__ out)
{
    uint32_t* Sm = reinterpret_cast<uint32_t*>(g3smem);
    float*    Ds = reinterpret_cast<float*>(g3smem);    // 64x512, overlays stages
    uint32_t smem_u32 = (uint32_t)__cvta_generic_to_shared(g3smem);

    __shared__ float qs_s[4][NA];
    __shared__ float st_s[4][STATE];
    __shared__ float yv_s[4][NA];
    __shared__ float disv[4][NA];
    __shared__ float vpart[4][32];

    int t = threadIdx.x;
    int lane = t & 31, w = t >> 5;
    int wm = w & 1, wn = w >> 1;
    int r = lane >> 2, cq = lane & 3;
    int bm = blockIdx.y * 64;
    int b0 = blockIdx.y * 4;

    if (t < 64) qs_s[t >> 4][t & 15] = agent_qs[(size_t)(b0 + (t >> 4)) * NA + (t & 15)];
    #pragma unroll
    for (int l = 0; l < 2; l++) {
        int idx = t + l * 512;
        st_s[idx >> 8][idx & 255] = states[(size_t)b0 * 256 + idx];
    }

    // ---- cp.async stage loader: one A uint4 + eight B uint4 per thread ----
    int arow = t >> 3, aq = t & 7;
    const float* agsrc = A + (size_t)(bm + arow) * 128 + aq * 4;
    uint32_t adst_off = (uint32_t)(arow * LDA + aq * 4) * 4;

    #define LOAD_STAGE(s, k0)                                                   \
        do {                                                                    \
            uint32_t abase = smem_u32 + (uint32_t)((s) * ASTG) * 4;             \
            cp16(abase + adst_off, agsrc + (k0));                               \
            uint32_t bbase = smem_u32 + (uint32_t)(2 * ASTG + (s) * BSTG) * 4;  \
            _Pragma("unroll")                                                   \
            for (int l = 0; l < 8; l++) {                                       \
                int idx = t + l * 512;                                          \
                int brow = idx >> 7, bq = idx & 127;                            \
                cp16(bbase + (uint32_t)(brow * LDB3 + bq * 4) * 4,              \
                     Wout + (size_t)((k0) + brow) * 512 + bq * 4);              \
            }                                                                   \
            CP_COMMIT();                                                        \
        } while (0)

    float acc[2][8][4];
    #pragma unroll
    for (int mi = 0; mi < 2; mi++)
        #pragma unroll
        for (int ni = 0; ni < 8; ni++)
            #pragma unroll
            for (int j = 0; j < 4; j++) acc[mi][ni][j] = 0.f;

    LOAD_STAGE(0, 0);
    LOAD_STAGE(1, 32);

    #pragma unroll
    for (int it = 0; it < 4; it++) {
        int s = it & 1;
        if (it < 3) cp_wait<1>(); else cp_wait<0>();
        __syncthreads();
        const uint32_t* As = Sm + s * ASTG;
        const uint32_t* Bs = Sm + 2 * ASTG + s * BSTG;
        #pragma unroll
        for (int kk = 0; kk < 32; kk += 8) {
            uint32_t a[2][4];
            #pragma unroll
            for (int mi = 0; mi < 2; mi++) {
                int rb = wm * 32 + mi * 16;
                a[mi][0] = As[(rb + r) * LDA + kk + cq];
                a[mi][1] = As[(rb + r + 8) * LDA + kk + cq];
                a[mi][2] = As[(rb + r) * LDA + kk + cq + 4];
                a[mi][3] = As[(rb + r + 8) * LDA + kk + cq + 4];
            }
            #pragma unroll
            for (int ni = 0; ni < 8; ni++) {
                int cb = wn * 64 + ni * 8;
                uint32_t b0r = Bs[(kk + cq) * LDB3 + cb + r];
                uint32_t b1r = Bs[(kk + 4 + cq) * LDB3 + cb + r];
                #pragma unroll
                for (int mi = 0; mi < 2; mi++)
                    mma_16n8k8(acc[mi][ni], a[mi][0], a[mi][1], a[mi][2], a[mi][3], b0r, b1r);
            }
        }
        __syncthreads();
        if (it + 2 < 4) LOAD_STAGE(s, (it + 2) * 32);
    }

    // ---- epilogue: elu -> Ds (safe: all compute done, synced above) ----
    #pragma unroll
    for (int mi = 0; mi < 2; mi++) {
        int row0 = wm * 32 + mi * 16 + r;
        #pragma unroll
        for (int ni = 0; ni < 8; ni++) {
            int col = wn * 64 + ni * 8 + 2 * cq;
            *reinterpret_cast<float2*>(&Ds[row0 * 512 + col]) =
                make_float2(elu1(acc[mi][ni][0]), elu1(acc[mi][ni][1]));
            *reinterpret_cast<float2*>(&Ds[(row0 + 8) * 512 + col]) =
                make_float2(elu1(acc[mi][ni][2]), elu1(acc[mi][ni][3]));
        }
    }
    __syncthreads();

    #pragma unroll
    for (int p = 0; p < 4; p++) {
        int tt = t + p * 512;
        int bl = tt >> 9, c = tt & 511;
        float* col = Ds + (bl * 16) * 512 + c;
        float v[NA]; float m = -INFINITY;
        #pragma unroll
        for (int i = 0; i < NA; i++) { v[i] = col[i * 512]; m = fmaxf(m, v[i]); }
        float s = 0.f;
        #pragma unroll
        for (int i = 0; i < NA; i++) s += expf(v[i] - m);
        float lse = m + logf(s);
        #pragma unroll
        for (int i = 0; i < NA; i++) col[i * 512] = fabsf(v[i] - lse);
    }
    __syncthreads();

    {
        int e = lane, i = w;
        #pragma unroll
        for (int bl = 0; bl < 4; bl++) {
            int b = b0 + bl;
            float p = g_ball[(size_t)b * 512 + i * 32 + e] + hb_b[i * 32 + e];
            const float* row = Ds + (bl * 16 + i) * 512;
            #pragma unroll
            for (int n = 0; n < NA; n++)
                p = fmaf(qs_s[bl][n], row[n * 32 + e], p);
            p = elu1(p);
            float prod = p * g_wf[(size_t)b * 512 + i * 32 + e];
            #pragma unroll
            for (int o = 16; o; o >>= 1) prod += __shfl_down_sync(FULLM, prod, o);
            if (lane == 0) yv_s[bl][i] = prod;
        }
    }

    {
        int bl = w >> 2, qt = w & 3;
        #pragma unroll
        for (int rr = 0; rr < 4; rr++) {
            int n = qt * 4 + rr;
            float acc2 = 0.f;
            #pragma unroll
            for (int s_ = lane; s_ < 256; s_ += 32)
                acc2 = fmaf(st_s[bl][s_], wn_w[n * 256 + s_], acc2);
            #pragma unroll
            for (int o = 16; o; o >>= 1) acc2 += __shfl_down_sync(FULLM, acc2, o);
            if (lane == 0) disv[bl][n] = fabsf(acc2 + wn_b[n]);
        }
        #pragma unroll
        for (int rr = 0; rr < 8; rr++) {
            int n = qt * 8 + rr;
            float acc2 = 0.f;
            #pragma unroll
            for (int s_ = lane; s_ < 256; s_ += 32)
                acc2 = fmaf(st_s[bl][s_], v1_w[n * 256 + s_], acc2);
            #pragma unroll
            for (int o = 16; o; o >>= 1) acc2 += __shfl_down_sync(FULLM, acc2, o);
            if (lane == 0) vpart[bl][n] = fmaxf(acc2 + v1_b[n], 0.f);
        }
    }
    __syncthreads();

    if (t < 4) {
        int bl = t;
        float v = v2_b[0];
        #pragma unroll
        for (int h2 = 0; h2 < 32; h2++) v = fmaf(vpart[bl][h2], v2_w[h2], v);
        float q = v;
        #pragma unroll
        for (int n = 0; n < NA; n++) q = fmaf(yv_s[bl][n], disv[bl][n], q);
        out[b0 + bl] = q;
    }
}

// =====================================================================
extern "C" void kernel_launch(void* const* d_in, const int* in_sizes, int n_in,
                              void* d_out, int out_size)
{
    const float* agent_qs = (const float*)d_in[0];
    const float* states   = (const float*)d_in[1];
    const float* obs_ls   = (const float*)d_in[2];
    const float* adj_ls   = (const float*)d_in[3];
    const float* wn_w     = (const float*)d_in[4];
    const float* wn_b     = (const float*)d_in[5];
    const float* g1_Wh    = (const float*)d_in[6];
    const float* g1_ah    = (const float*)d_in[7];
    const float* g1_Wout  = (const float*)d_in[8];
    const float* g1_aout  = (const float*)d_in[9];
    const float* gf_Wh    = (const float*)d_in[10];
    const float* gf_ah    = (const float*)d_in[11];
    const float* gf_Wout  = (const float*)d_in[12];
    const float* gf_aout  = (const float*)d_in[13];
    const float* hb_W     = (const float*)d_in[14];
    const float* hb_b     = (const float*)d_in[15];
    const float* v1_w     = (const float*)d_in[16];
    const float* v1_b     = (const float*)d_in[17];
    const float* v2_w     = (const float*)d_in[18];
    const float* v2_b     = (const float*)d_in[19];
    float* out = (float*)d_out;

    float *p_z, *p_ball, *p_BhbT, *p_Wout32;
    cudaGetSymbolAddress((void**)&p_z,      g_z);
    cudaGetSymbolAddress((void**)&p_ball,   g_ball);
    cudaGetSymbolAddress((void**)&p_BhbT,   g_BhbT);
    cudaGetSymbolAddress((void**)&p_Wout32, g_Wout32);

    const int G3_SMEM = (2 * ASTG + 2 * BSTG) * 4;   // 151,552 B
    cudaFuncSetAttribute(gemm3_mix_kernel,
                         cudaFuncAttributeMaxDynamicSharedMemorySize, G3_SMEM);

    pack_kernel<<<64, 256>>>(g1_Wh, gf_Wh, g1_Wout, g1_aout, gf_Wout, hb_W);

    // b_all = states(8192x256) @ hb_W^T(256x512)
    gemm_tf32<<<dim3(4, 64), 256>>>(states, p_BhbT, p_ball, BTOT, 256, 512);

    // fused head-projection + attention
    attn_kernel<<<BTOT, 256>>>(obs_ls, adj_ls, g1_ah, gf_ah, gf_aout);

    // fused: D = Z @ Wout -> elu -> logsoftmax -> abs -> mix -> q
    gemm3_mix_kernel<<<dim3(1, 2048), 512, G3_SMEM>>>(
        p_z, p_Wout32, agent_qs, states, wn_w, wn_b, hb_b,
        v1_w, v1_b, v2_w, v2_b, out);
}

// round 12
// speedup vs baseline: 3.3877x; 1.1126x over previous
#include <cuda_runtime.h>
#include <math.h>
#include <stdint.h>

#define NA 16
#define OBSF 128
#define STATE 256
#define EMBED 32
#define NHID 32
#define BTOT 8192
#define ALPHA 0.2f
#define NEGV -9.0e15f
#define FULLM 0xffffffffu

// ---------------- scratch (device globals) ----------------
__device__ float g_z[(size_t)BTOT * NA * 128];       // 64 MB   att2@xcat1 (tf32 bits)
__device__ float g_ball[(size_t)BTOT * 512];         // 16 MB   b_all pre-bias
__device__ float g_wf[(size_t)BTOT * 512];           // 16 MB   |logsoftmax(gf out)|
__device__ float g_Bheads[128 * 256];                // packed head weights (tf32 bits)
__device__ float g_BhbT[256 * 512];                  // hb_W transposed (tf32 bits)
__device__ float g_Wout32[128 * 512];                // g1_Wout (tf32 bits)
__device__ float g_gfW32[128 * 32];                  // gf_Wout (tf32 bits)
__device__ float g_wa[256];                          // wa1 (128) | wa2 (128), fp32

__device__ __forceinline__ uint32_t f2tf32(float f) {
    uint32_t u; asm("cvt.rna.tf32.f32 %0, %1;" : "=r"(u) : "f"(f)); return u;
}
__device__ __forceinline__ float tf32f(float f) { return __uint_as_float(f2tf32(f)); }

__device__ __forceinline__ void mma_16n8k8(float* c,
    uint32_t a0, uint32_t a1, uint32_t a2, uint32_t a3,
    uint32_t b0, uint32_t b1)
{
    asm volatile(
        "mma.sync.aligned.m16n8k8.row.col.f32.tf32.tf32.f32 "
        "{%0,%1,%2,%3}, {%4,%5,%6,%7}, {%8,%9}, {%0,%1,%2,%3};"
        : "+f"(c[0]), "+f"(c[1]), "+f"(c[2]), "+f"(c[3])
        : "r"(a0), "r"(a1), "r"(a2), "r"(a3), "r"(b0), "r"(b1));
}

// fast elu: exp via MUFU.EX2 (rel err ~2^-22, well under 1e-3 budget)
__device__ __forceinline__ float elu1(float v) {
    return v > 0.f ? v : (__expf(v) - 1.f);
}

__device__ __forceinline__ void cp16(uint32_t smem_addr, const void* gptr) {
    asm volatile("cp.async.ca.shared.global [%0], [%1], 16;\n"
                 :: "r"(smem_addr), "l"(gptr));
}
#define CP_COMMIT() asm volatile("cp.async.commit_group;\n" ::: "memory")
template <int N> __device__ __forceinline__ void cp_wait() {
    asm volatile("cp.async.wait_group %0;\n" :: "n"(N) : "memory");
}

// =====================================================================
// K0: pack weights (tf32-converted) + wa vectors
// =====================================================================
__global__ void pack_kernel(const float* __restrict__ g1_Wh, const float* __restrict__ gf_Wh,
                            const float* __restrict__ g1_Wout, const float* __restrict__ g1_aout,
                            const float* __restrict__ gf_Wout, const float* __restrict__ hb_W)
{
    int t = threadIdx.x, bid = blockIdx.x;
    int gid = bid * 256 + t;
    for (int idx = gid; idx < 128 * 256; idx += 64 * 256) {
        int k = idx >> 8, c = idx & 255;
        float v = (c < 128) ? g1_Wh[(c >> 5) * 4096 + k * 32 + (c & 31)]
                            : gf_Wh[((c - 128) >> 5) * 4096 + k * 32 + (c & 31)];
        g_Bheads[idx] = tf32f(v);
    }
    for (int idx = gid; idx < 256 * 512; idx += 64 * 256) {
        int k = idx >> 9, n = idx & 511;
        g_BhbT[idx] = tf32f(hb_W[n * 256 + k]);
    }
    for (int idx = gid; idx < 128 * 512; idx += 64 * 256)
        g_Wout32[idx] = tf32f(g1_Wout[idx]);
    for (int idx = gid; idx < 128 * 32; idx += 64 * 256)
        g_gfW32[idx] = tf32f(gf_Wout[idx]);
    if (bid == 0) {
        int wp = t >> 5, ln = t & 31;
        for (int d = wp; d < 256; d += 8) {
            int k = d & 127, half = d >> 7;
            const float* ap = g1_aout + half * 512;
            const float* wr = g1_Wout + (size_t)k * 512;
            float acc = 0.f;
            for (int c = ln; c < 512; c += 32) acc = fmaf(wr[c], ap[c], acc);
            #pragma unroll
            for (int o = 16; o; o >>= 1) acc += __shfl_down_sync(FULLM, acc, o);
            if (ln == 0) g_wa[half * 128 + k] = acc;
        }
    }
}

// =====================================================================
// TF32 GEMM (used for b_all only): C = A @ B, B PRE-CONVERTED.
// =====================================================================
#define LDA 36
#define LDB 136

__global__ __launch_bounds__(256) void gemm_tf32(
    const float* __restrict__ A, const float* __restrict__ B, float* __restrict__ C,
    int M, int K, int N)
{
    __shared__ uint32_t As[128 * LDA];
    __shared__ uint32_t Bs[32 * LDB];
    int t = threadIdx.x;
    int lane = t & 31, w = t >> 5;
    int wm = w & 3, wn = w >> 2;
    int bm = blockIdx.y * 128, bn = blockIdx.x * 128;
    int r = lane >> 2, cq = lane & 3;

    float acc[2][8][4];
    #pragma unroll
    for (int mi = 0; mi < 2; mi++)
        #pragma unroll
        for (int ni = 0; ni < 8; ni++)
            #pragma unroll
            for (int j = 0; j < 4; j++) acc[mi][ni][j] = 0.f;

    for (int k0 = 0; k0 < K; k0 += 32) {
        #pragma unroll
        for (int l = 0; l < 4; l++) {
            int idx = t + l * 256;
            int row = idx >> 3, q = idx & 7;
            float4 v = *reinterpret_cast<const float4*>(A + (size_t)(bm + row) * K + k0 + q * 4);
            uint32_t* p = &As[row * LDA + q * 4];
            p[0] = f2tf32(v.x); p[1] = f2tf32(v.y); p[2] = f2tf32(v.z); p[3] = f2tf32(v.w);
        }
        #pragma unroll
        for (int l = 0; l < 4; l++) {
            int idx = t + l * 256;
            int row = idx >> 5, q = idx & 31;
            uint4 v = *reinterpret_cast<const uint4*>(B + (size_t)(k0 + row) * N + bn + q * 4);
            uint32_t* p = &Bs[row * LDB + q * 4];
            p[0] = v.x; p[1] = v.y; p[2] = v.z; p[3] = v.w;
        }
        __syncthreads();
        #pragma unroll
        for (int kk = 0; kk < 32; kk += 8) {
            uint32_t a[2][4];
            #pragma unroll
            for (int mi = 0; mi < 2; mi++) {
                int rb = wm * 32 + mi * 16;
                a[mi][0] = As[(rb + r) * LDA + kk + cq];
                a[mi][1] = As[(rb + r + 8) * LDA + kk + cq];
                a[mi][2] = As[(rb + r) * LDA + kk + cq + 4];
                a[mi][3] = As[(rb + r + 8) * LDA + kk + cq + 4];
            }
            #pragma unroll
            for (int ni = 0; ni < 8; ni++) {
                int cb = wn * 64 + ni * 8;
                uint32_t b0 = Bs[(kk + cq) * LDB + cb + r];
                uint32_t b1 = Bs[(kk + 4 + cq) * LDB + cb + r];
                #pragma unroll
                for (int mi = 0; mi < 2; mi++)
                    mma_16n8k8(acc[mi][ni], a[mi][0], a[mi][1], a[mi][2], a[mi][3], b0, b1);
            }
        }
        __syncthreads();
    }
    #pragma unroll
    for (int mi = 0; mi < 2; mi++) {
        int rb = bm + wm * 32 + mi * 16 + r;
        #pragma unroll
        for (int ni = 0; ni < 8; ni++) {
            int cb = bn + wn * 64 + ni * 8 + 2 * cq;
            *reinterpret_cast<float2*>(C + (size_t)rb * N + cb) =
                make_float2(acc[mi][ni][0], acc[mi][ni][1]);
            *reinterpret_cast<float2*>(C + (size_t)(rb + 8) * N + cb) =
                make_float2(acc[mi][ni][2], acc[mi][ni][3]);
        }
    }
}

// =====================================================================
// K1: FUSED head-projection + attention (R10 structure, fast-math exp).
// =====================================================================
#define XCP 132

__global__ __launch_bounds__(256) void attn_kernel(
    const float* __restrict__ obs_g, const float* __restrict__ adj_g,
    const float* __restrict__ g1_ah, const float* __restrict__ gf_ah,
    const float* __restrict__ gf_aout)
{
    int b = blockIdx.x;
    int t = threadIdx.x;
    int lane = t & 31, w = t >> 5;
    int r = lane >> 2, cq = lane & 3;

    __shared__ float buf1[NA][XCP];      // obs (phase 1), then xc1
    __shared__ float xcf[NA][XCP];
    __shared__ float att_w[8][NA][17];
    __shared__ float adj[NA][NA];
    __shared__ float f1s[NA], f2s[NA];
    __shared__ float att2s[NA][17];
    __shared__ float whf[NA][34];

    {
        const float4* src = reinterpret_cast<const float4*>(obs_g + (size_t)b * 2048);
        #pragma unroll
        for (int l = 0; l < 2; l++) {
            int idx4 = t + l * 256;
            int row = idx4 >> 5, c4 = (idx4 & 31) * 4;
            float4 v = src[idx4];
            buf1[row][c4]     = tf32f(v.x);
            buf1[row][c4 + 1] = tf32f(v.y);
            buf1[row][c4 + 2] = tf32f(v.z);
            buf1[row][c4 + 3] = tf32f(v.w);
        }
    }
    adj[t >> 4][t & 15] = adj_g[(size_t)b * 256 + t];
    __syncthreads();

    int h = w;
    float acc1[4][4];
    #pragma unroll
    for (int nt = 0; nt < 4; nt++)
        #pragma unroll
        for (int q = 0; q < 4; q++) acc1[nt][q] = 0.f;
    #pragma unroll
    for (int ks = 0; ks < 16; ks++) {
        int kk = ks * 8;
        uint32_t a0 = __float_as_uint(buf1[r][kk + cq]);
        uint32_t a1 = __float_as_uint(buf1[r + 8][kk + cq]);
        uint32_t a2 = __float_as_uint(buf1[r][kk + cq + 4]);
        uint32_t a3 = __float_as_uint(buf1[r + 8][kk + cq + 4]);
        #pragma unroll
        for (int nt = 0; nt < 4; nt++) {
            int cb = h * 32 + nt * 8;
            uint32_t b0 = __float_as_uint(__ldg(&g_Bheads[(kk + cq) * 256 + cb + r]));
            uint32_t b1 = __float_as_uint(__ldg(&g_Bheads[(kk + 4 + cq) * 256 + cb + r]));
            mma_16n8k8(acc1[nt], a0, a1, a2, a3, b0, b1);
        }
    }

    float facc;
    {
        const float* av = (h < 4) ? (g1_ah + h * 64) : (gf_ah + (h - 4) * 64);
        float pf1r = 0.f, pf1r8 = 0.f, pf2r = 0.f, pf2r8 = 0.f;
        #pragma unroll
        for (int nt = 0; nt < 4; nt++) {
            float2 a1v = __ldg(reinterpret_cast<const float2*>(av + nt * 8 + 2 * cq));
            float2 a2v = __ldg(reinterpret_cast<const float2*>(av + 32 + nt * 8 + 2 * cq));
            pf1r  = fmaf(acc1[nt][0], a1v.x, fmaf(acc1[nt][1], a1v.y, pf1r));
            pf1r8 = fmaf(acc1[nt][2], a1v.x, fmaf(acc1[nt][3], a1v.y, pf1r8));
            pf2r  = fmaf(acc1[nt][0], a2v.x, fmaf(acc1[nt][1], a2v.y, pf2r));
            pf2r8 = fmaf(acc1[nt][2], a2v.x, fmaf(acc1[nt][3], a2v.y, pf2r8));
        }
        #pragma unroll
        for (int mk = 1; mk <= 2; mk <<= 1) {
            pf1r  += __shfl_xor_sync(FULLM, pf1r,  mk);
            pf1r8 += __shfl_xor_sync(FULLM, pf1r8, mk);
            pf2r  += __shfl_xor_sync(FULLM, pf2r,  mk);
            pf2r8 += __shfl_xor_sync(FULLM, pf2r8, mk);
        }
        int j = lane & 15, half = lane >> 4;
        int src = (j & 7) * 4;
        float s1 = __shfl_sync(FULLM, pf1r,  src);
        float s2 = __shfl_sync(FULLM, pf1r8, src);
        float s3 = __shfl_sync(FULLM, pf2r,  src);
        float s4 = __shfl_sync(FULLM, pf2r8, src);
        facc = half ? ((j < 8) ? s3 : s4) : ((j < 8) ? s1 : s2);
    }
    __syncthreads();

    {
        int j = lane & 15;
        float f2j = __shfl_sync(FULLM, facc, 16 + j);
        float attc[NA];
        float m = -INFINITY;
        #pragma unroll
        for (int i = 0; i < NA; i++) {
            float f1i = __shfl_sync(FULLM, facc, i);
            float e = f1i + f2j;
            e = e > 0.f ? e : ALPHA * e;
            e = (adj[i][j] > 0.f) ? e : NEGV;
            attc[i] = e; m = fmaxf(m, e);
        }
        float s = 0.f;
        #pragma unroll
        for (int i = 0; i < NA; i++) { float x = __expf(attc[i] - m); attc[i] = x; s += x; }
        float inv = 1.f / s;
        if (lane < 16) {
            #pragma unroll
            for (int i = 0; i < NA; i++) att_w[h][i][j] = tf32f(attc[i] * inv);
        }
        __syncwarp();
    }

    {
        float acc2[4][4];
        #pragma unroll
        for (int nt = 0; nt < 4; nt++)
            #pragma unroll
            for (int q = 0; q < 4; q++) acc2[nt][q] = 0.f;
        int src0 = cq * 4 + (r >> 1);
        int src1 = (cq + 4) * 4 + (r >> 1);
        bool odd = (r & 1);
        #pragma unroll
        for (int ks2 = 0; ks2 < 2; ks2++) {
            int kk2 = ks2 * 8;
            uint32_t a0 = __float_as_uint(att_w[h][r][kk2 + cq]);
            uint32_t a1 = __float_as_uint(att_w[h][r + 8][kk2 + cq]);
            uint32_t a2 = __float_as_uint(att_w[h][r][kk2 + cq + 4]);
            uint32_t a3 = __float_as_uint(att_w[h][r + 8][kk2 + cq + 4]);
            #pragma unroll
            for (int nt = 0; nt < 4; nt++) {
                float lo = acc1[nt][ks2 * 2];
                float hi = acc1[nt][ks2 * 2 + 1];
                float v0l = __shfl_sync(FULLM, lo, src0);
                float v0h = __shfl_sync(FULLM, hi, src0);
                float v1l = __shfl_sync(FULLM, lo, src1);
                float v1h = __shfl_sync(FULLM, hi, src1);
                uint32_t b0 = f2tf32(odd ? v0h : v0l);
                uint32_t b1 = f2tf32(odd ? v1h : v1l);
                mma_16n8k8(acc2[nt], a0, a1, a2, a3, b0, b1);
            }
        }
        float* base = (h < 4) ? &buf1[0][h * 32] : &xcf[0][(h - 4) * 32];
        #pragma unroll
        for (int nt = 0; nt < 4; nt++) {
            int col = nt * 8 + 2 * cq;
            *reinterpret_cast<float2*>(base + r * XCP + col) =
                make_float2(tf32f(elu1(acc2[nt][0])), tf32f(elu1(acc2[nt][1])));
            *reinterpret_cast<float2*>(base + (r + 8) * XCP + col) =
                make_float2(tf32f(elu1(acc2[nt][2])), tf32f(elu1(acc2[nt][3])));
        }
    }
    __syncthreads();

    #pragma unroll
    for (int rr = 0; rr < 4; rr++) {
        int d = w * 4 + rr;
        int i = d & 15, half = d >> 4;
        const float* wav = g_wa + half * 128;
        float acc = 0.f;
        #pragma unroll
        for (int k = lane; k < 128; k += 32) acc = fmaf(buf1[i][k], wav[k], acc);
        #pragma unroll
        for (int o = 16; o; o >>= 1) acc += __shfl_down_sync(FULLM, acc, o);
        if (lane == 0) { if (half) f2s[i] = acc; else f1s[i] = acc; }
    }
    __syncthreads();
    if (t < NA) {
        int j = t;
        float ev[NA]; float m = -INFINITY;
        #pragma unroll
        for (int i = 0; i < NA; i++) {
            float e = f1s[i] + f2s[j];
            e = e > 0.f ? e : ALPHA * e;
            e = (adj[i][j] > 0.f) ? e : NEGV;
            ev[i] = e; m = fmaxf(m, e);
        }
        float s = 0.f;
        #pragma unroll
        for (int i = 0; i < NA; i++) { float x = __expf(ev[i] - m); ev[i] = x; s += x; }
        float inv = 1.f / s;
        #pragma unroll
        for (int i = 0; i < NA; i++) att2s[i][j] = tf32f(ev[i] * inv);
    }
    __syncthreads();

    {
        float acc[2][4];
        #pragma unroll
        for (int nt = 0; nt < 2; nt++)
            #pragma unroll
            for (int q = 0; q < 4; q++) acc[nt][q] = 0.f;
        #pragma unroll
        for (int ks = 0; ks < 2; ks++) {
            int kk = ks * 8;
            uint32_t a0 = __float_as_uint(att2s[r][kk + cq]);
            uint32_t a1 = __float_as_uint(att2s[r + 8][kk + cq]);
            uint32_t a2 = __float_as_uint(att2s[r][kk + cq + 4]);
            uint32_t a3 = __float_as_uint(att2s[r + 8][kk + cq + 4]);
            #pragma unroll
            for (int nt = 0; nt < 2; nt++) {
                int cb = w * 16 + nt * 8;
                uint32_t b0 = __float_as_uint(buf1[kk + cq][cb + r]);
                uint32_t b1 = __float_as_uint(buf1[kk + 4 + cq][cb + r]);
                mma_16n8k8(acc[nt], a0, a1, a2, a3, b0, b1);
            }
        }
        float* zdst = g_z + (size_t)b * 2048;
        #pragma unroll
        for (int nt = 0; nt < 2; nt++) {
            int col = w * 16 + nt * 8 + 2 * cq;
            *reinterpret_cast<float2*>(zdst + r * 128 + col) =
                make_float2(tf32f(acc[nt][0]), tf32f(acc[nt][1]));
            *reinterpret_cast<float2*>(zdst + (r + 8) * 128 + col) =
                make_float2(tf32f(acc[nt][2]), tf32f(acc[nt][3]));
        }
    }

    if (w < 4) {
        int cb = w * 8;
        float acc[4] = {0.f, 0.f, 0.f, 0.f};
        #pragma unroll
        for (int ks = 0; ks < 16; ks++) {
            int kk = ks * 8;
            uint32_t a0 = __float_as_uint(xcf[r][kk + cq]);
            uint32_t a1 = __float_as_uint(xcf[r + 8][kk + cq]);
            uint32_t a2 = __float_as_uint(xcf[r][kk + cq + 4]);
            uint32_t a3 = __float_as_uint(xcf[r + 8][kk + cq + 4]);
            uint32_t b0 = __float_as_uint(g_gfW32[(kk + cq) * 32 + cb + r]);
            uint32_t b1 = __float_as_uint(g_gfW32[(kk + 4 + cq) * 32 + cb + r]);
            mma_16n8k8(acc, a0, a1, a2, a3, b0, b1);
        }
        int col = cb + 2 * cq;
        *reinterpret_cast<float2*>(&whf[r][col]) = make_float2(acc[0], acc[1]);
        *reinterpret_cast<float2*>(&whf[r + 8][col]) = make_float2(acc[2], acc[3]);
    }
    __syncthreads();

    if (w == 0) {
        int d = lane & 15, half = lane >> 4;
        const float* av = gf_aout + half * 32;
        float fac = 0.f;
        #pragma unroll
        for (int c = 0; c < 32; c++) fac = fmaf(whf[d][c], av[c], fac);
        int j = lane & 15;
        float f2j = __shfl_sync(FULLM, fac, 16 + j);
        float attc[NA];
        float m = -INFINITY;
        #pragma unroll
        for (int i = 0; i < NA; i++) {
            float f1i = __shfl_sync(FULLM, fac, i);
            float e = f1i + f2j;
            e = e > 0.f ? e : ALPHA * e;
            e = (adj[i][j] > 0.f) ? e : NEGV;
            attc[i] = e; m = fmaxf(m, e);
        }
        float s = 0.f;
        #pragma unroll
        for (int i = 0; i < NA; i++) { float x = __expf(attc[i] - m); attc[i] = x; s += x; }
        float inv = 1.f / s;
        #pragma unroll
        for (int i = 0; i < NA; i++) attc[i] *= inv;
        int c = lane;
        float o2[NA];
        float mm = -INFINITY;
        #pragma unroll
        for (int i = 0; i < NA; i++) {
            float acc = 0.f;
            #pragma unroll
            for (int n = 0; n < NA; n++) {
                float a_in = __shfl_sync(FULLM, attc[i], n);
                acc = fmaf(a_in, whf[n][c], acc);
            }
            acc = elu1(acc);
            o2[i] = acc; mm = fmaxf(mm, acc);
        }
        float ss = 0.f;
        #pragma unroll
        for (int i = 0; i < NA; i++) ss += __expf(o2[i] - mm);
        float lse = mm + __logf(ss);
        #pragma unroll
        for (int i = 0; i < NA; i++)
            g_wf[(size_t)b * 512 + i * 32 + c] = fabsf(o2[i] - lse);
    }
}

// =====================================================================
// K2: fused GEMM3 + mix, cp.async double-buffered, fast-math epilogue.
// =====================================================================
#define LDB3 520
#define ASTG (64 * LDA)
#define BSTG (32 * LDB3)

extern __shared__ char g3smem[];

__global__ __launch_bounds__(512, 1) void gemm3_mix_kernel(
    const float* __restrict__ A,
    const float* __restrict__ Wout,
    const float* __restrict__ agent_qs, const float* __restrict__ states,
    const float* __restrict__ wn_w, const float* __restrict__ wn_b,
    const float* __restrict__ hb_b,
    const float* __restrict__ v1_w, const float* __restrict__ v1_b,
    const float* __restrict__ v2_w, const float* __restrict__ v2_b,
    float* __restrict__ out)
{
    uint32_t* Sm = reinterpret_cast<uint32_t*>(g3smem);
    float*    Ds = reinterpret_cast<float*>(g3smem);
    uint32_t smem_u32 = (uint32_t)__cvta_generic_to_shared(g3smem);

    __shared__ float qs_s[4][NA];
    __shared__ float st_s[4][STATE];
    __shared__ float yv_s[4][NA];
    __shared__ float disv[4][NA];
    __shared__ float vpart[4][32];

    int t = threadIdx.x;
    int lane = t & 31, w = t >> 5;
    int wm = w & 1, wn = w >> 1;
    int r = lane >> 2, cq = lane & 3;
    int bm = blockIdx.y * 64;
    int b0 = blockIdx.y * 4;

    if (t < 64) qs_s[t >> 4][t & 15] = agent_qs[(size_t)(b0 + (t >> 4)) * NA + (t & 15)];
    #pragma unroll
    for (int l = 0; l < 2; l++) {
        int idx = t + l * 512;
        st_s[idx >> 8][idx & 255] = states[(size_t)b0 * 256 + idx];
    }

    int arow = t >> 3, aq = t & 7;
    const float* agsrc = A + (size_t)(bm + arow) * 128 + aq * 4;
    uint32_t adst_off = (uint32_t)(arow * LDA + aq * 4) * 4;

    #define LOAD_STAGE(s, k0)                                                   \
        do {                                                                    \
            uint32_t abase = smem_u32 + (uint32_t)((s) * ASTG) * 4;             \
            cp16(abase + adst_off, agsrc + (k0));                               \
            uint32_t bbase = smem_u32 + (uint32_t)(2 * ASTG + (s) * BSTG) * 4;  \
            _Pragma("unroll")                                                   \
            for (int l = 0; l < 8; l++) {                                       \
                int idx = t + l * 512;                                          \
                int brow = idx >> 7, bq = idx & 127;                            \
                cp16(bbase + (uint32_t)(brow * LDB3 + bq * 4) * 4,              \
                     Wout + (size_t)((k0) + brow) * 512 + bq * 4);              \
            }                                                                   \
            CP_COMMIT();                                                        \
        } while (0)

    float acc[2][8][4];
    #pragma unroll
    for (int mi = 0; mi < 2; mi++)
        #pragma unroll
        for (int ni = 0; ni < 8; ni++)
            #pragma unroll
            for (int j = 0; j < 4; j++) acc[mi][ni][j] = 0.f;

    LOAD_STAGE(0, 0);
    LOAD_STAGE(1, 32);

    #pragma unroll
    for (int it = 0; it < 4; it++) {
        int s = it & 1;
        if (it < 3) cp_wait<1>(); else cp_wait<0>();
        __syncthreads();
        const uint32_t* As = Sm + s * ASTG;
        const uint32_t* Bs = Sm + 2 * ASTG + s * BSTG;
        #pragma unroll
        for (int kk = 0; kk < 32; kk += 8) {
            uint32_t a[2][4];
            #pragma unroll
            for (int mi = 0; mi < 2; mi++) {
                int rb = wm * 32 + mi * 16;
                a[mi][0] = As[(rb + r) * LDA + kk + cq];
                a[mi][1] = As[(rb + r + 8) * LDA + kk + cq];
                a[mi][2] = As[(rb + r) * LDA + kk + cq + 4];
                a[mi][3] = As[(rb + r + 8) * LDA + kk + cq + 4];
            }
            #pragma unroll
            for (int ni = 0; ni < 8; ni++) {
                int cb = wn * 64 + ni * 8;
                uint32_t b0r = Bs[(kk + cq) * LDB3 + cb + r];
                uint32_t b1r = Bs[(kk + 4 + cq) * LDB3 + cb + r];
                #pragma unroll
                for (int mi = 0; mi < 2; mi++)
                    mma_16n8k8(acc[mi][ni], a[mi][0], a[mi][1], a[mi][2], a[mi][3], b0r, b1r);
            }
        }
        __syncthreads();
        if (it + 2 < 4) LOAD_STAGE(s, (it + 2) * 32);
    }

    #pragma unroll
    for (int mi = 0; mi < 2; mi++) {
        int row0 = wm * 32 + mi * 16 + r;
        #pragma unroll
        for (int ni = 0; ni < 8; ni++) {
            int col = wn * 64 + ni * 8 + 2 * cq;
            *reinterpret_cast<float2*>(&Ds[row0 * 512 + col]) =
                make_float2(elu1(acc[mi][ni][0]), elu1(acc[mi][ni][1]));
            *reinterpret_cast<float2*>(&Ds[(row0 + 8) * 512 + col]) =
                make_float2(elu1(acc[mi][ni][2]), elu1(acc[mi][ni][3]));
        }
    }
    __syncthreads();

    #pragma unroll
    for (int p = 0; p < 4; p++) {
        int tt = t + p * 512;
        int bl = tt >> 9, c = tt & 511;
        float* col = Ds + (bl * 16) * 512 + c;
        float v[NA]; float m = -INFINITY;
        #pragma unroll
        for (int i = 0; i < NA; i++) { v[i] = col[i * 512]; m = fmaxf(m, v[i]); }
        float s = 0.f;
        #pragma unroll
        for (int i = 0; i < NA; i++) s += __expf(v[i] - m);
        float lse = m + __logf(s);
        #pragma unroll
        for (int i = 0; i < NA; i++) col[i * 512] = fabsf(v[i] - lse);
    }
    __syncthreads();

    {
        int e = lane, i = w;
        #pragma unroll
        for (int bl = 0; bl < 4; bl++) {
            int b = b0 + bl;
            float p = g_ball[(size_t)b * 512 + i * 32 + e] + hb_b[i * 32 + e];
            const float* row = Ds + (bl * 16 + i) * 512;
            #pragma unroll
            for (int n = 0; n < NA; n++)
                p = fmaf(qs_s[bl][n], row[n * 32 + e], p);
            p = elu1(p);
            float prod = p * g_wf[(size_t)b * 512 + i * 32 + e];
            #pragma unroll
            for (int o = 16; o; o >>= 1) prod += __shfl_down_sync(FULLM, prod, o);
            if (lane == 0) yv_s[bl][i] = prod;
        }
    }

    {
        int bl = w >> 2, qt = w & 3;
        #pragma unroll
        for (int rr = 0; rr < 4; rr++) {
            int n = qt * 4 + rr;
            float acc2 = 0.f;
            #pragma unroll
            for (int s_ = lane; s_ < 256; s_ += 32)
                acc2 = fmaf(st_s[bl][s_], wn_w[n * 256 + s_], acc2);
            #pragma unroll
            for (int o = 16; o; o >>= 1) acc2 += __shfl_down_sync(FULLM, acc2, o);
            if (lane == 0) disv[bl][n] = fabsf(acc2 + wn_b[n]);
        }
        #pragma unroll
        for (int rr = 0; rr < 8; rr++) {
            int n = qt * 8 + rr;
            float acc2 = 0.f;
            #pragma unroll
            for (int s_ = lane; s_ < 256; s_ += 32)
                acc2 = fmaf(st_s[bl][s_], v1_w[n * 256 + s_], acc2);
            #pragma unroll
            for (int o = 16; o; o >>= 1) acc2 += __shfl_down_sync(FULLM, acc2, o);
            if (lane == 0) vpart[bl][n] = fmaxf(acc2 + v1_b[n], 0.f);
        }
    }
    __syncthreads();

    if (t < 4) {
        int bl = t;
        float v = v2_b[0];
        #pragma unroll
        for (int h2 = 0; h2 < 32; h2++) v = fmaf(vpart[bl][h2], v2_w[h2], v);
        float q = v;
        #pragma unroll
        for (int n = 0; n < NA; n++) q = fmaf(yv_s[bl][n], disv[bl][n], q);
        out[b0 + bl] = q;
    }
}

// =====================================================================
extern "C" void kernel_launch(void* const* d_in, const int* in_sizes, int n_in,
                              void* d_out, int out_size)
{
    const float* agent_qs = (const float*)d_in[0];
    const float* states   = (const float*)d_in[1];
    const float* obs_ls   = (const float*)d_in[2];
    const float* adj_ls   = (const float*)d_in[3];
    const float* wn_w     = (const float*)d_in[4];
    const float* wn_b     = (const float*)d_in[5];
    const float* g1_Wh    = (const float*)d_in[6];
    const float* g1_ah    = (const float*)d_in[7];
    const float* g1_Wout  = (const float*)d_in[8];
    const float* g1_aout  = (const float*)d_in[9];
    const float* gf_Wh    = (const float*)d_in[10];
    const float* gf_ah    = (const float*)d_in[11];
    const float* gf_Wout  = (const float*)d_in[12];
    const float* gf_aout  = (const float*)d_in[13];
    const float* hb_W     = (const float*)d_in[14];
    const float* hb_b     = (const float*)d_in[15];
    const float* v1_w     = (const float*)d_in[16];
    const float* v1_b     = (const float*)d_in[17];
    const float* v2_w     = (const float*)d_in[18];
    const float* v2_b     = (const float*)d_in[19];
    float* out = (float*)d_out;

    float *p_z, *p_ball, *p_BhbT, *p_Wout32;
    cudaGetSymbolAddress((void**)&p_z,      g_z);
    cudaGetSymbolAddress((void**)&p_ball,   g_ball);
    cudaGetSymbolAddress((void**)&p_BhbT,   g_BhbT);
    cudaGetSymbolAddress((void**)&p_Wout32, g_Wout32);

    const int G3_SMEM = (2 * ASTG + 2 * BSTG) * 4;   // 151,552 B
    cudaFuncSetAttribute(gemm3_mix_kernel,
                         cudaFuncAttributeMaxDynamicSharedMemorySize, G3_SMEM);

    pack_kernel<<<64, 256>>>(g1_Wh, gf_Wh, g1_Wout, g1_aout, gf_Wout, hb_W);

    // b_all = states(8192x256) @ hb_W^T(256x512)
    gemm_tf32<<<dim3(4, 64), 256>>>(states, p_BhbT, p_ball, BTOT, 256, 512);

    // fused head-projection + attention
    attn_kernel<<<BTOT, 256>>>(obs_ls, adj_ls, g1_ah, gf_ah, gf_aout);

    // fused: D = Z @ Wout -> elu -> logsoftmax -> abs -> mix -> q
    gemm3_mix_kernel<<<dim3(1, 2048), 512, G3_SMEM>>>(
        p_z, p_Wout32, agent_qs, states, wn_w, wn_b, hb_b,
        v1_w, v1_b, v2_w, v2_b, out);
}

// round 13
// speedup vs baseline: 3.6757x; 1.0850x over previous
#include <cuda_runtime.h>
#include <math.h>
#include <stdint.h>

#define NA 16
#define OBSF 128
#define STATE 256
#define EMBED 32
#define NHID 32
#define BTOT 8192
#define ALPHA 0.2f
#define NEGV -9.0e15f
#define FULLM 0xffffffffu

// ---------------- scratch (device globals) ----------------
__device__ float g_z[(size_t)BTOT * NA * 128];       // 64 MB   att2@xcat1 (tf32 bits)
__device__ float g_ball[(size_t)BTOT * 512];         // 16 MB   b_all pre-bias
__device__ float g_wf[(size_t)BTOT * 512];           // 16 MB   |logsoftmax(gf out)|
__device__ float g_hidp[(size_t)BTOT * 2 * 512];     // 32 MB   partial hidden sums
__device__ float g_Bheads[128 * 256];                // packed head weights (tf32 bits)
__device__ float g_BhbT[256 * 512];                  // hb_W transposed (tf32 bits)
__device__ float g_Wout32[128 * 512];                // g1_Wout (tf32 bits)
__device__ float g_gfW32[128 * 32];                  // gf_Wout (tf32 bits)
__device__ float g_wa[256];                          // wa1 (128) | wa2 (128), fp32

__device__ __forceinline__ uint32_t f2tf32(float f) {
    uint32_t u; asm("cvt.rna.tf32.f32 %0, %1;" : "=r"(u) : "f"(f)); return u;
}
__device__ __forceinline__ float tf32f(float f) { return __uint_as_float(f2tf32(f)); }

__device__ __forceinline__ void mma_16n8k8(float* c,
    uint32_t a0, uint32_t a1, uint32_t a2, uint32_t a3,
    uint32_t b0, uint32_t b1)
{
    asm volatile(
        "mma.sync.aligned.m16n8k8.row.col.f32.tf32.tf32.f32 "
        "{%0,%1,%2,%3}, {%4,%5,%6,%7}, {%8,%9}, {%0,%1,%2,%3};"
        : "+f"(c[0]), "+f"(c[1]), "+f"(c[2]), "+f"(c[3])
        : "r"(a0), "r"(a1), "r"(a2), "r"(a3), "r"(b0), "r"(b1));
}

__device__ __forceinline__ float elu1(float v) {
    return v > 0.f ? v : (__expf(v) - 1.f);
}

__device__ __forceinline__ void cp16(uint32_t smem_addr, const void* gptr) {
    asm volatile("cp.async.ca.shared.global [%0], [%1], 16;\n"
                 :: "r"(smem_addr), "l"(gptr));
}
#define CP_COMMIT() asm volatile("cp.async.commit_group;\n" ::: "memory")
template <int N> __device__ __forceinline__ void cp_wait() {
    asm volatile("cp.async.wait_group %0;\n" :: "n"(N) : "memory");
}

// =====================================================================
// K0: pack weights (tf32-converted) + wa vectors
// =====================================================================
__global__ void pack_kernel(const float* __restrict__ g1_Wh, const float* __restrict__ gf_Wh,
                            const float* __restrict__ g1_Wout, const float* __restrict__ g1_aout,
                            const float* __restrict__ gf_Wout, const float* __restrict__ hb_W)
{
    int t = threadIdx.x, bid = blockIdx.x;
    int gid = bid * 256 + t;
    for (int idx = gid; idx < 128 * 256; idx += 64 * 256) {
        int k = idx >> 8, c = idx & 255;
        float v = (c < 128) ? g1_Wh[(c >> 5) * 4096 + k * 32 + (c & 31)]
                            : gf_Wh[((c - 128) >> 5) * 4096 + k * 32 + (c & 31)];
        g_Bheads[idx] = tf32f(v);
    }
    for (int idx = gid; idx < 256 * 512; idx += 64 * 256) {
        int k = idx >> 9, n = idx & 511;
        g_BhbT[idx] = tf32f(hb_W[n * 256 + k]);
    }
    for (int idx = gid; idx < 128 * 512; idx += 64 * 256)
        g_Wout32[idx] = tf32f(g1_Wout[idx]);
    for (int idx = gid; idx < 128 * 32; idx += 64 * 256)
        g_gfW32[idx] = tf32f(gf_Wout[idx]);
    if (bid == 0) {
        int wp = t >> 5, ln = t & 31;
        for (int d = wp; d < 256; d += 8) {
            int k = d & 127, half = d >> 7;
            const float* ap = g1_aout + half * 512;
            const float* wr = g1_Wout + (size_t)k * 512;
            float acc = 0.f;
            for (int c = ln; c < 512; c += 32) acc = fmaf(wr[c], ap[c], acc);
            #pragma unroll
            for (int o = 16; o; o >>= 1) acc += __shfl_down_sync(FULLM, acc, o);
            if (ln == 0) g_wa[half * 128 + k] = acc;
        }
    }
}

// =====================================================================
// TF32 GEMM (used for b_all only): C = A @ B, B PRE-CONVERTED.
// =====================================================================
#define LDA 36
#define LDB 136

__global__ __launch_bounds__(256) void gemm_tf32(
    const float* __restrict__ A, const float* __restrict__ B, float* __restrict__ C,
    int M, int K, int N)
{
    __shared__ uint32_t As[128 * LDA];
    __shared__ uint32_t Bs[32 * LDB];
    int t = threadIdx.x;
    int lane = t & 31, w = t >> 5;
    int wm = w & 3, wn = w >> 2;
    int bm = blockIdx.y * 128, bn = blockIdx.x * 128;
    int r = lane >> 2, cq = lane & 3;

    float acc[2][8][4];
    #pragma unroll
    for (int mi = 0; mi < 2; mi++)
        #pragma unroll
        for (int ni = 0; ni < 8; ni++)
            #pragma unroll
            for (int j = 0; j < 4; j++) acc[mi][ni][j] = 0.f;

    for (int k0 = 0; k0 < K; k0 += 32) {
        #pragma unroll
        for (int l = 0; l < 4; l++) {
            int idx = t + l * 256;
            int row = idx >> 3, q = idx & 7;
            float4 v = *reinterpret_cast<const float4*>(A + (size_t)(bm + row) * K + k0 + q * 4);
            uint32_t* p = &As[row * LDA + q * 4];
            p[0] = f2tf32(v.x); p[1] = f2tf32(v.y); p[2] = f2tf32(v.z); p[3] = f2tf32(v.w);
        }
        #pragma unroll
        for (int l = 0; l < 4; l++) {
            int idx = t + l * 256;
            int row = idx >> 5, q = idx & 31;
            uint4 v = *reinterpret_cast<const uint4*>(B + (size_t)(k0 + row) * N + bn + q * 4);
            uint32_t* p = &Bs[row * LDB + q * 4];
            p[0] = v.x; p[1] = v.y; p[2] = v.z; p[3] = v.w;
        }
        __syncthreads();
        #pragma unroll
        for (int kk = 0; kk < 32; kk += 8) {
            uint32_t a[2][4];
            #pragma unroll
            for (int mi = 0; mi < 2; mi++) {
                int rb = wm * 32 + mi * 16;
                a[mi][0] = As[(rb + r) * LDA + kk + cq];
                a[mi][1] = As[(rb + r + 8) * LDA + kk + cq];
                a[mi][2] = As[(rb + r) * LDA + kk + cq + 4];
                a[mi][3] = As[(rb + r + 8) * LDA + kk + cq + 4];
            }
            #pragma unroll
            for (int ni = 0; ni < 8; ni++) {
                int cb = wn * 64 + ni * 8;
                uint32_t b0 = Bs[(kk + cq) * LDB + cb + r];
                uint32_t b1 = Bs[(kk + 4 + cq) * LDB + cb + r];
                #pragma unroll
                for (int mi = 0; mi < 2; mi++)
                    mma_16n8k8(acc[mi][ni], a[mi][0], a[mi][1], a[mi][2], a[mi][3], b0, b1);
            }
        }
        __syncthreads();
    }
    #pragma unroll
    for (int mi = 0; mi < 2; mi++) {
        int rb = bm + wm * 32 + mi * 16 + r;
        #pragma unroll
        for (int ni = 0; ni < 8; ni++) {
            int cb = bn + wn * 64 + ni * 8 + 2 * cq;
            *reinterpret_cast<float2*>(C + (size_t)rb * N + cb) =
                make_float2(acc[mi][ni][0], acc[mi][ni][1]);
            *reinterpret_cast<float2*>(C + (size_t)(rb + 8) * N + cb) =
                make_float2(acc[mi][ni][2], acc[mi][ni][3]);
        }
    }
}

// =====================================================================
// K1: FUSED head-projection + attention (unchanged from R12).
// =====================================================================
#define XCP 132

__global__ __launch_bounds__(256) void attn_kernel(
    const float* __restrict__ obs_g, const float* __restrict__ adj_g,
    const float* __restrict__ g1_ah, const float* __restrict__ gf_ah,
    const float* __restrict__ gf_aout)
{
    int b = blockIdx.x;
    int t = threadIdx.x;
    int lane = t & 31, w = t >> 5;
    int r = lane >> 2, cq = lane & 3;

    __shared__ float buf1[NA][XCP];
    __shared__ float xcf[NA][XCP];
    __shared__ float att_w[8][NA][17];
    __shared__ float adj[NA][NA];
    __shared__ float f1s[NA], f2s[NA];
    __shared__ float att2s[NA][17];
    __shared__ float whf[NA][34];

    {
        const float4* src = reinterpret_cast<const float4*>(obs_g + (size_t)b * 2048);
        #pragma unroll
        for (int l = 0; l < 2; l++) {
            int idx4 = t + l * 256;
            int row = idx4 >> 5, c4 = (idx4 & 31) * 4;
            float4 v = src[idx4];
            buf1[row][c4]     = tf32f(v.x);
            buf1[row][c4 + 1] = tf32f(v.y);
            buf1[row][c4 + 2] = tf32f(v.z);
            buf1[row][c4 + 3] = tf32f(v.w);
        }
    }
    adj[t >> 4][t & 15] = adj_g[(size_t)b * 256 + t];
    __syncthreads();

    int h = w;
    float acc1[4][4];
    #pragma unroll
    for (int nt = 0; nt < 4; nt++)
        #pragma unroll
        for (int q = 0; q < 4; q++) acc1[nt][q] = 0.f;
    #pragma unroll
    for (int ks = 0; ks < 16; ks++) {
        int kk = ks * 8;
        uint32_t a0 = __float_as_uint(buf1[r][kk + cq]);
        uint32_t a1 = __float_as_uint(buf1[r + 8][kk + cq]);
        uint32_t a2 = __float_as_uint(buf1[r][kk + cq + 4]);
        uint32_t a3 = __float_as_uint(buf1[r + 8][kk + cq + 4]);
        #pragma unroll
        for (int nt = 0; nt < 4; nt++) {
            int cb = h * 32 + nt * 8;
            uint32_t b0 = __float_as_uint(__ldg(&g_Bheads[(kk + cq) * 256 + cb + r]));
            uint32_t b1 = __float_as_uint(__ldg(&g_Bheads[(kk + 4 + cq) * 256 + cb + r]));
            mma_16n8k8(acc1[nt], a0, a1, a2, a3, b0, b1);
        }
    }

    float facc;
    {
        const float* av = (h < 4) ? (g1_ah + h * 64) : (gf_ah + (h - 4) * 64);
        float pf1r = 0.f, pf1r8 = 0.f, pf2r = 0.f, pf2r8 = 0.f;
        #pragma unroll
        for (int nt = 0; nt < 4; nt++) {
            float2 a1v = __ldg(reinterpret_cast<const float2*>(av + nt * 8 + 2 * cq));
            float2 a2v = __ldg(reinterpret_cast<const float2*>(av + 32 + nt * 8 + 2 * cq));
            pf1r  = fmaf(acc1[nt][0], a1v.x, fmaf(acc1[nt][1], a1v.y, pf1r));
            pf1r8 = fmaf(acc1[nt][2], a1v.x, fmaf(acc1[nt][3], a1v.y, pf1r8));
            pf2r  = fmaf(acc1[nt][0], a2v.x, fmaf(acc1[nt][1], a2v.y, pf2r));
            pf2r8 = fmaf(acc1[nt][2], a2v.x, fmaf(acc1[nt][3], a2v.y, pf2r8));
        }
        #pragma unroll
        for (int mk = 1; mk <= 2; mk <<= 1) {
            pf1r  += __shfl_xor_sync(FULLM, pf1r,  mk);
            pf1r8 += __shfl_xor_sync(FULLM, pf1r8, mk);
            pf2r  += __shfl_xor_sync(FULLM, pf2r,  mk);
            pf2r8 += __shfl_xor_sync(FULLM, pf2r8, mk);
        }
        int j = lane & 15, half = lane >> 4;
        int src = (j & 7) * 4;
        float s1 = __shfl_sync(FULLM, pf1r,  src);
        float s2 = __shfl_sync(FULLM, pf1r8, src);
        float s3 = __shfl_sync(FULLM, pf2r,  src);
        float s4 = __shfl_sync(FULLM, pf2r8, src);
        facc = half ? ((j < 8) ? s3 : s4) : ((j < 8) ? s1 : s2);
    }
    __syncthreads();

    {
        int j = lane & 15;
        float f2j = __shfl_sync(FULLM, facc, 16 + j);
        float attc[NA];
        float m = -INFINITY;
        #pragma unroll
        for (int i = 0; i < NA; i++) {
            float f1i = __shfl_sync(FULLM, facc, i);
            float e = f1i + f2j;
            e = e > 0.f ? e : ALPHA * e;
            e = (adj[i][j] > 0.f) ? e : NEGV;
            attc[i] = e; m = fmaxf(m, e);
        }
        float s = 0.f;
        #pragma unroll
        for (int i = 0; i < NA; i++) { float x = __expf(attc[i] - m); attc[i] = x; s += x; }
        float inv = 1.f / s;
        if (lane < 16) {
            #pragma unroll
            for (int i = 0; i < NA; i++) att_w[h][i][j] = tf32f(attc[i] * inv);
        }
        __syncwarp();
    }

    {
        float acc2[4][4];
        #pragma unroll
        for (int nt = 0; nt < 4; nt++)
            #pragma unroll
            for (int q = 0; q < 4; q++) acc2[nt][q] = 0.f;
        int src0 = cq * 4 + (r >> 1);
        int src1 = (cq + 4) * 4 + (r >> 1);
        bool odd = (r & 1);
        #pragma unroll
        for (int ks2 = 0; ks2 < 2; ks2++) {
            int kk2 = ks2 * 8;
            uint32_t a0 = __float_as_uint(att_w[h][r][kk2 + cq]);
            uint32_t a1 = __float_as_uint(att_w[h][r + 8][kk2 + cq]);
            uint32_t a2 = __float_as_uint(att_w[h][r][kk2 + cq + 4]);
            uint32_t a3 = __float_as_uint(att_w[h][r + 8][kk2 + cq + 4]);
            #pragma unroll
            for (int nt = 0; nt < 4; nt++) {
                float lo = acc1[nt][ks2 * 2];
                float hi = acc1[nt][ks2 * 2 + 1];
                float v0l = __shfl_sync(FULLM, lo, src0);
                float v0h = __shfl_sync(FULLM, hi, src0);
                float v1l = __shfl_sync(FULLM, lo, src1);
                float v1h = __shfl_sync(FULLM, hi, src1);
                uint32_t b0 = f2tf32(odd ? v0h : v0l);
                uint32_t b1 = f2tf32(odd ? v1h : v1l);
                mma_16n8k8(acc2[nt], a0, a1, a2, a3, b0, b1);
            }
        }
        float* base = (h < 4) ? &buf1[0][h * 32] : &xcf[0][(h - 4) * 32];
        #pragma unroll
        for (int nt = 0; nt < 4; nt++) {
            int col = nt * 8 + 2 * cq;
            *reinterpret_cast<float2*>(base + r * XCP + col) =
                make_float2(tf32f(elu1(acc2[nt][0])), tf32f(elu1(acc2[nt][1])));
            *reinterpret_cast<float2*>(base + (r + 8) * XCP + col) =
                make_float2(tf32f(elu1(acc2[nt][2])), tf32f(elu1(acc2[nt][3])));
        }
    }
    __syncthreads();

    #pragma unroll
    for (int rr = 0; rr < 4; rr++) {
        int d = w * 4 + rr;
        int i = d & 15, half = d >> 4;
        const float* wav = g_wa + half * 128;
        float acc = 0.f;
        #pragma unroll
        for (int k = lane; k < 128; k += 32) acc = fmaf(buf1[i][k], wav[k], acc);
        #pragma unroll
        for (int o = 16; o; o >>= 1) acc += __shfl_down_sync(FULLM, acc, o);
        if (lane == 0) { if (half) f2s[i] = acc; else f1s[i] = acc; }
    }
    __syncthreads();
    if (t < NA) {
        int j = t;
        float ev[NA]; float m = -INFINITY;
        #pragma unroll
        for (int i = 0; i < NA; i++) {
            float e = f1s[i] + f2s[j];
            e = e > 0.f ? e : ALPHA * e;
            e = (adj[i][j] > 0.f) ? e : NEGV;
            ev[i] = e; m = fmaxf(m, e);
        }
        float s = 0.f;
        #pragma unroll
        for (int i = 0; i < NA; i++) { float x = __expf(ev[i] - m); ev[i] = x; s += x; }
        float inv = 1.f / s;
        #pragma unroll
        for (int i = 0; i < NA; i++) att2s[i][j] = tf32f(ev[i] * inv);
    }
    __syncthreads();

    {
        float acc[2][4];
        #pragma unroll
        for (int nt = 0; nt < 2; nt++)
            #pragma unroll
            for (int q = 0; q < 4; q++) acc[nt][q] = 0.f;
        #pragma unroll
        for (int ks = 0; ks < 2; ks++) {
            int kk = ks * 8;
            uint32_t a0 = __float_as_uint(att2s[r][kk + cq]);
            uint32_t a1 = __float_as_uint(att2s[r + 8][kk + cq]);
            uint32_t a2 = __float_as_uint(att2s[r][kk + cq + 4]);
            uint32_t a3 = __float_as_uint(att2s[r + 8][kk + cq + 4]);
            #pragma unroll
            for (int nt = 0; nt < 2; nt++) {
                int cb = w * 16 + nt * 8;
                uint32_t b0 = __float_as_uint(buf1[kk + cq][cb + r]);
                uint32_t b1 = __float_as_uint(buf1[kk + 4 + cq][cb + r]);
                mma_16n8k8(acc[nt], a0, a1, a2, a3, b0, b1);
            }
        }
        float* zdst = g_z + (size_t)b * 2048;
        #pragma unroll
        for (int nt = 0; nt < 2; nt++) {
            int col = w * 16 + nt * 8 + 2 * cq;
            *reinterpret_cast<float2*>(zdst + r * 128 + col) =
                make_float2(tf32f(acc[nt][0]), tf32f(acc[nt][1]));
            *reinterpret_cast<float2*>(zdst + (r + 8) * 128 + col) =
                make_float2(tf32f(acc[nt][2]), tf32f(acc[nt][3]));
        }
    }

    if (w < 4) {
        int cb = w * 8;
        float acc[4] = {0.f, 0.f, 0.f, 0.f};
        #pragma unroll
        for (int ks = 0; ks < 16; ks++) {
            int kk = ks * 8;
            uint32_t a0 = __float_as_uint(xcf[r][kk + cq]);
            uint32_t a1 = __float_as_uint(xcf[r + 8][kk + cq]);
            uint32_t a2 = __float_as_uint(xcf[r][kk + cq + 4]);
            uint32_t a3 = __float_as_uint(xcf[r + 8][kk + cq + 4]);
            uint32_t b0 = __float_as_uint(g_gfW32[(kk + cq) * 32 + cb + r]);
            uint32_t b1 = __float_as_uint(g_gfW32[(kk + 4 + cq) * 32 + cb + r]);
            mma_16n8k8(acc, a0, a1, a2, a3, b0, b1);
        }
        int col = cb + 2 * cq;
        *reinterpret_cast<float2*>(&whf[r][col]) = make_float2(acc[0], acc[1]);
        *reinterpret_cast<float2*>(&whf[r + 8][col]) = make_float2(acc[2], acc[3]);
    }
    __syncthreads();

    if (w == 0) {
        int d = lane & 15, half = lane >> 4;
        const float* av = gf_aout + half * 32;
        float fac = 0.f;
        #pragma unroll
        for (int c = 0; c < 32; c++) fac = fmaf(whf[d][c], av[c], fac);
        int j = lane & 15;
        float f2j = __shfl_sync(FULLM, fac, 16 + j);
        float attc[NA];
        float m = -INFINITY;
        #pragma unroll
        for (int i = 0; i < NA; i++) {
            float f1i = __shfl_sync(FULLM, fac, i);
            float e = f1i + f2j;
            e = e > 0.f ? e : ALPHA * e;
            e = (adj[i][j] > 0.f) ? e : NEGV;
            attc[i] = e; m = fmaxf(m, e);
        }
        float s = 0.f;
        #pragma unroll
        for (int i = 0; i < NA; i++) { float x = __expf(attc[i] - m); attc[i] = x; s += x; }
        float inv = 1.f / s;
        #pragma unroll
        for (int i = 0; i < NA; i++) attc[i] *= inv;
        int c = lane;
        float o2[NA];
        float mm = -INFINITY;
        #pragma unroll
        for (int i = 0; i < NA; i++) {
            float acc = 0.f;
            #pragma unroll
            for (int n = 0; n < NA; n++) {
                float a_in = __shfl_sync(FULLM, attc[i], n);
                acc = fmaf(a_in, whf[n][c], acc);
            }
            acc = elu1(acc);
            o2[i] = acc; mm = fmaxf(mm, acc);
        }
        float ss = 0.f;
        #pragma unroll
        for (int i = 0; i < NA; i++) ss += __expf(o2[i] - mm);
        float lse = mm + __logf(ss);
        #pragma unroll
        for (int i = 0; i < NA; i++)
            g_wf[(size_t)b * 512 + i * 32 + c] = fabsf(o2[i] - lse);
    }
}

// =====================================================================
// K2: GEMM3 half-N CTAs: 64 rows x 256 cols, 256 threads, 2 CTA/SM.
// Epilogue: elu -> column logsoftmax -> abs -> PARTIAL qs-contraction.
// =====================================================================
#define LDB3H 264
#define ASTG  (64 * LDA)            // 2304 u32
#define BSTGH (32 * LDB3H)          // 8448 u32

extern __shared__ char g3smem[];

__global__ __launch_bounds__(256, 2) void gemm3_half_kernel(
    const float* __restrict__ A,              // g_z tf32 bits [131072 x 128]
    const float* __restrict__ Wout,           // g_Wout32 tf32 bits [128 x 512]
    const float* __restrict__ agent_qs)
{
    uint32_t* Sm = reinterpret_cast<uint32_t*>(g3smem);
    float*    Ds = reinterpret_cast<float*>(g3smem);    // 64x256 overlay
    uint32_t smem_u32 = (uint32_t)__cvta_generic_to_shared(g3smem);

    __shared__ float qs_s[4][NA];

    int t = threadIdx.x;
    int lane = t & 31, w = t >> 5;              // 8 warps
    int wm = w & 1, wn = w >> 1;                // 2 x 4
    int r = lane >> 2, cq = lane & 3;
    int half = blockIdx.x;                      // N half
    int bm = blockIdx.y * 64;
    int b0 = blockIdx.y * 4;
    int bn = half * 256;

    if (t < 64) qs_s[t >> 4][t & 15] = agent_qs[(size_t)(b0 + (t >> 4)) * NA + (t & 15)];

    int arow = t >> 3, aq = t & 7;              // covers 32 rows per pass; 2 passes
    const float* agsrc = A + (size_t)(bm + arow) * 128 + aq * 4;
    const float* agsrc2 = A + (size_t)(bm + arow + 32) * 128 + aq * 4;
    uint32_t adst1 = (uint32_t)(arow * LDA + aq * 4) * 4;
    uint32_t adst2 = (uint32_t)((arow + 32) * LDA + aq * 4) * 4;

    #define LOAD_STAGE_H(s, k0)                                                 \
        do {                                                                    \
            uint32_t abase = smem_u32 + (uint32_t)((s) * ASTG) * 4;             \
            cp16(abase + adst1, agsrc + (k0));                                  \
            cp16(abase + adst2, agsrc2 + (k0));                                 \
            uint32_t bbase = smem_u32 + (uint32_t)(2 * ASTG + (s) * BSTGH) * 4; \
            _Pragma("unroll")                                                   \
            for (int l = 0; l < 8; l++) {                                       \
                int idx = t + l * 256;                                          \
                int brow = idx >> 6, bq = idx & 63;                             \
                cp16(bbase + (uint32_t)(brow * LDB3H + bq * 4) * 4,             \
                     Wout + (size_t)((k0) + brow) * 512 + bn + bq * 4);         \
            }                                                                   \
            CP_COMMIT();                                                        \
        } while (0)

    float acc[2][8][4];
    #pragma unroll
    for (int mi = 0; mi < 2; mi++)
        #pragma unroll
        for (int ni = 0; ni < 8; ni++)
            #pragma unroll
            for (int j = 0; j < 4; j++) acc[mi][ni][j] = 0.f;

    LOAD_STAGE_H(0, 0);
    LOAD_STAGE_H(1, 32);

    #pragma unroll
    for (int it = 0; it < 4; it++) {
        int s = it & 1;
        if (it < 3) cp_wait<1>(); else cp_wait<0>();
        __syncthreads();
        const uint32_t* As = Sm + s * ASTG;
        const uint32_t* Bs = Sm + 2 * ASTG + s * BSTGH;
        #pragma unroll
        for (int kk = 0; kk < 32; kk += 8) {
            uint32_t a[2][4];
            #pragma unroll
            for (int mi = 0; mi < 2; mi++) {
                int rb = wm * 32 + mi * 16;
                a[mi][0] = As[(rb + r) * LDA + kk + cq];
                a[mi][1] = As[(rb + r + 8) * LDA + kk + cq];
                a[mi][2] = As[(rb + r) * LDA + kk + cq + 4];
                a[mi][3] = As[(rb + r + 8) * LDA + kk + cq + 4];
            }
            #pragma unroll
            for (int ni = 0; ni < 8; ni++) {
                int cb = wn * 64 + ni * 8;
                uint32_t b0r = Bs[(kk + cq) * LDB3H + cb + r];
                uint32_t b1r = Bs[(kk + 4 + cq) * LDB3H + cb + r];
                #pragma unroll
                for (int mi = 0; mi < 2; mi++)
                    mma_16n8k8(acc[mi][ni], a[mi][0], a[mi][1], a[mi][2], a[mi][3], b0r, b1r);
            }
        }
        __syncthreads();
        if (it + 2 < 4) LOAD_STAGE_H(s, (it + 2) * 32);
    }

    // ---- elu -> Ds (64 x 256) ----
    #pragma unroll
    for (int mi = 0; mi < 2; mi++) {
        int row0 = wm * 32 + mi * 16 + r;
        #pragma unroll
        for (int ni = 0; ni < 8; ni++) {
            int col = wn * 64 + ni * 8 + 2 * cq;
            *reinterpret_cast<float2*>(&Ds[row0 * 256 + col]) =
                make_float2(elu1(acc[mi][ni][0]), elu1(acc[mi][ni][1]));
            *reinterpret_cast<float2*>(&Ds[(row0 + 8) * 256 + col]) =
                make_float2(elu1(acc[mi][ni][2]), elu1(acc[mi][ni][3]));
        }
    }
    __syncthreads();

    // ---- per-column logsoftmax over 16 agents + abs (4 batches x 256 cols) ----
    #pragma unroll
    for (int p = 0; p < 4; p++) {
        int tt = t + p * 256;
        int bl = tt >> 8, c = tt & 255;
        float* col = Ds + (bl * 16) * 256 + c;
        float v[NA]; float m = -INFINITY;
        #pragma unroll
        for (int i = 0; i < NA; i++) { v[i] = col[i * 256]; m = fmaxf(m, v[i]); }
        float s = 0.f;
        #pragma unroll
        for (int i = 0; i < NA; i++) s += __expf(v[i] - m);
        float lse = m + __logf(s);
        #pragma unroll
        for (int i = 0; i < NA; i++) col[i * 256] = fabsf(v[i] - lse);
    }
    __syncthreads();

    // ---- partial hidden: hidp[i][e] = sum_{n'=0..7} qs[8*half+n'] * w1[i, n'*32+e] ----
    {
        int e = lane;
        #pragma unroll
        for (int ai = 0; ai < 2; ai++) {
            int i = w + ai * 8;
            #pragma unroll
            for (int bl = 0; bl < 4; bl++) {
                const float* row = Ds + (bl * 16 + i) * 256;
                float p = 0.f;
                #pragma unroll
                for (int np = 0; np < 8; np++)
                    p = fmaf(qs_s[bl][8 * half + np], row[np * 32 + e], p);
                g_hidp[(((size_t)(b0 + bl) * 2 + half) * 16 + i) * 32 + e] = p;
            }
        }
    }
}

// =====================================================================
// K3: final mix: combine partials, elu, y, dis, V, q. 8192 blocks.
// =====================================================================
__global__ __launch_bounds__(256) void mix_final_kernel(
    const float* __restrict__ states,
    const float* __restrict__ wn_w, const float* __restrict__ wn_b,
    const float* __restrict__ hb_b,
    const float* __restrict__ v1_w, const float* __restrict__ v1_b,
    const float* __restrict__ v2_w, const float* __restrict__ v2_b,
    float* __restrict__ out)
{
    int b = blockIdx.x;
    int t = threadIdx.x;
    int lane = t & 31, w = t >> 5;          // 8 warps

    __shared__ float st[STATE];
    __shared__ float yv[NA], disv[NA], vpart[32];

    st[t] = (t < 256) ? states[(size_t)b * 256 + t] : 0.f;
    __syncthreads();

    // hidden + y: warp w -> agents {w, w+8}
    {
        int e = lane;
        #pragma unroll
        for (int ai = 0; ai < 2; ai++) {
            int i = w + ai * 8;
            size_t base0 = (((size_t)b * 2 + 0) * 16 + i) * 32 + e;
            size_t base1 = (((size_t)b * 2 + 1) * 16 + i) * 32 + e;
            float hp = g_hidp[base0] + g_hidp[base1]
                     + g_ball[(size_t)b * 512 + i * 32 + e] + hb_b[i * 32 + e];
            hp = elu1(hp);
            float prod = hp * g_wf[(size_t)b * 512 + i * 32 + e];
            #pragma unroll
            for (int o = 16; o; o >>= 1) prod += __shfl_down_sync(FULLM, prod, o);
            if (lane == 0) yv[i] = prod;
        }
    }

    // dis: warp w -> agents {2w, 2w+1}; V: warp w -> rows {4w..4w+3}
    {
        #pragma unroll
        for (int rr = 0; rr < 2; rr++) {
            int n = w * 2 + rr;
            float acc2 = 0.f;
            #pragma unroll
            for (int s_ = lane; s_ < 256; s_ += 32)
                acc2 = fmaf(st[s_], wn_w[n * 256 + s_], acc2);
            #pragma unroll
            for (int o = 16; o; o >>= 1) acc2 += __shfl_down_sync(FULLM, acc2, o);
            if (lane == 0) disv[n] = fabsf(acc2 + wn_b[n]);
        }
        #pragma unroll
        for (int rr = 0; rr < 4; rr++) {
            int n = w * 4 + rr;
            float acc2 = 0.f;
            #pragma unroll
            for (int s_ = lane; s_ < 256; s_ += 32)
                acc2 = fmaf(st[s_], v1_w[n * 256 + s_], acc2);
            #pragma unroll
            for (int o = 16; o; o >>= 1) acc2 += __shfl_down_sync(FULLM, acc2, o);
            if (lane == 0) vpart[n] = fmaxf(acc2 + v1_b[n], 0.f);
        }
    }
    __syncthreads();

    if (t == 0) {
        float v = v2_b[0];
        #pragma unroll
        for (int h2 = 0; h2 < 32; h2++) v = fmaf(vpart[h2], v2_w[h2], v);
        float q = v;
        #pragma unroll
        for (int n = 0; n < NA; n++) q = fmaf(yv[n], disv[n], q);
        out[b] = q;
    }
}

// =====================================================================
extern "C" void kernel_launch(void* const* d_in, const int* in_sizes, int n_in,
                              void* d_out, int out_size)
{
    const float* agent_qs = (const float*)d_in[0];
    const float* states   = (const float*)d_in[1];
    const float* obs_ls   = (const float*)d_in[2];
    const float* adj_ls   = (const float*)d_in[3];
    const float* wn_w     = (const float*)d_in[4];
    const float* wn_b     = (const float*)d_in[5];
    const float* g1_Wh    = (const float*)d_in[6];
    const float* g1_ah    = (const float*)d_in[7];
    const float* g1_Wout  = (const float*)d_in[8];
    const float* g1_aout  = (const float*)d_in[9];
    const float* gf_Wh    = (const float*)d_in[10];
    const float* gf_ah    = (const float*)d_in[11];
    const float* gf_Wout  = (const float*)d_in[12];
    const float* gf_aout  = (const float*)d_in[13];
    const float* hb_W     = (const float*)d_in[14];
    const float* hb_b     = (const float*)d_in[15];
    const float* v1_w     = (const float*)d_in[16];
    const float* v1_b     = (const float*)d_in[17];
    const float* v2_w     = (const float*)d_in[18];
    const float* v2_b     = (const float*)d_in[19];
    float* out = (float*)d_out;

    float *p_z, *p_ball, *p_BhbT, *p_Wout32;
    cudaGetSymbolAddress((void**)&p_z,      g_z);
    cudaGetSymbolAddress((void**)&p_ball,   g_ball);
    cudaGetSymbolAddress((void**)&p_BhbT,   g_BhbT);
    cudaGetSymbolAddress((void**)&p_Wout32, g_Wout32);

    const int G3H_SMEM = (2 * ASTG + 2 * BSTGH) * 4;   // 86,016 B
    cudaFuncSetAttribute(gemm3_half_kernel,
                         cudaFuncAttributeMaxDynamicSharedMemorySize, G3H_SMEM);

    pack_kernel<<<64, 256>>>(g1_Wh, gf_Wh, g1_Wout, g1_aout, gf_Wout, hb_W);

    // b_all = states(8192x256) @ hb_W^T(256x512)
    gemm_tf32<<<dim3(4, 64), 256>>>(states, p_BhbT, p_ball, BTOT, 256, 512);

    // fused head-projection + attention
    attn_kernel<<<BTOT, 256>>>(obs_ls, adj_ls, g1_ah, gf_ah, gf_aout);

    // D = Z @ Wout in half-N CTAs -> elu/logsoftmax/abs -> partial hidden
    gemm3_half_kernel<<<dim3(2, 2048), 256, G3H_SMEM>>>(p_z, p_Wout32, agent_qs);

    // combine partials + ball -> elu -> y; dis, V, q
    mix_final_kernel<<<BTOT, 256>>>(states, wn_w, wn_b, hb_b,
                                    v1_w, v1_b, v2_w, v2_b, out);
}